// round 2
// baseline (speedup 1.0000x reference)
#include <cuda_runtime.h>
#include <math.h>

#define D_MODEL 2048
#define SEQ     2048
#define BATCH   2
#define NHEADS  16
#define DK      128
#define MROWS   (BATCH*SEQ)   /* 4096 */

// ---------------- scratch (device globals; no allocs allowed) ----------------
__device__ float g_Q[(size_t)MROWS * D_MODEL];
__device__ float g_K[(size_t)MROWS * D_MODEL];
__device__ float g_V[(size_t)MROWS * D_MODEL];
__device__ float g_attn[(size_t)MROWS * D_MODEL];
__device__ float g_cos[SEQ * (DK / 2)];
__device__ float g_sin[SEQ * (DK / 2)];

// ---------------- RoPE tables ----------------
// Replicate the reference's fp32 quantization: theta_i = 10000^(i/64) in fp32,
// phase = s / theta_i rounded to fp32, then exact trig of that fp32 value.
__global__ void rope_table_kernel() {
    int idx = blockIdx.x * blockDim.x + threadIdx.x;
    if (idx >= SEQ * 64) return;
    int s = idx >> 6;
    int i = idx & 63;
    float th = powf(10000.0f, (float)i * (1.0f / 64.0f));
    float ph = (float)s / th;          // fp32 rounding matches reference
    double phd = (double)ph;
    g_cos[idx] = (float)cos(phd);
    g_sin[idx] = (float)sin(phd);
}

// ---------------- RoPE apply (in-place on g_Q, g_K) ----------------
__global__ void rope_apply_kernel() {
    int idx = blockIdx.x * blockDim.x + threadIdx.x;  // over MROWS * 1024 pairs
    if (idx >= MROWS * (D_MODEL / 2)) return;
    int row = idx >> 10;          // b*SEQ + s
    int c2  = idx & 1023;         // h*64 + i  (float2 index within row)
    int i   = c2 & 63;
    int s   = row & (SEQ - 1);    // position
    float c  = g_cos[(s << 6) + i];
    float sn = g_sin[(s << 6) + i];
    size_t off = (size_t)row * (D_MODEL / 2) + c2;
    float2* Q2 = (float2*)g_Q;
    float2* K2 = (float2*)g_K;
    float2 q = Q2[off];
    Q2[off] = make_float2(q.x * c - q.y * sn, q.x * sn + q.y * c);
    float2 k = K2[off];
    K2[off] = make_float2(k.x * c - k.y * sn, k.x * sn + k.y * c);
}

// ---------------- SGEMM NT: C[M,N] = A[M,K] * B[N,K]^T (all row-major fp32) --
// Tile 128x128x16, 256 threads, 8x8 per-thread microtile.
__global__ void __launch_bounds__(256) sgemm_nt(const float* __restrict__ A,
                                                const float* __restrict__ Bm,
                                                float* __restrict__ C,
                                                int M, int N, int K) {
    __shared__ float As[16][128];
    __shared__ float Bs[16][128];
    const int tid = threadIdx.x;
    const int m0 = blockIdx.y * 128;
    const int n0 = blockIdx.x * 128;
    const int ty = tid >> 4;   // 0..15
    const int tx = tid & 15;

    float acc[8][8];
#pragma unroll
    for (int i = 0; i < 8; ++i)
#pragma unroll
        for (int j = 0; j < 8; ++j) acc[i][j] = 0.f;

    for (int k0 = 0; k0 < K; k0 += 16) {
#pragma unroll
        for (int t = 0; t < 2; ++t) {
            int idx = tid + t * 256;      // 0..511 (128 rows x 4 float4)
            int row = idx >> 2;
            int c4  = (idx & 3) << 2;
            float4 va = *(const float4*)(A + (size_t)(m0 + row) * K + k0 + c4);
            As[c4 + 0][row] = va.x;
            As[c4 + 1][row] = va.y;
            As[c4 + 2][row] = va.z;
            As[c4 + 3][row] = va.w;
            float4 vb = *(const float4*)(Bm + (size_t)(n0 + row) * K + k0 + c4);
            Bs[c4 + 0][row] = vb.x;
            Bs[c4 + 1][row] = vb.y;
            Bs[c4 + 2][row] = vb.z;
            Bs[c4 + 3][row] = vb.w;
        }
        __syncthreads();
#pragma unroll
        for (int kk = 0; kk < 16; ++kk) {
            float a[8], b[8];
#pragma unroll
            for (int i = 0; i < 8; ++i) a[i] = As[kk][ty * 8 + i];
#pragma unroll
            for (int j = 0; j < 8; ++j) b[j] = Bs[kk][tx * 8 + j];
#pragma unroll
            for (int i = 0; i < 8; ++i)
#pragma unroll
                for (int j = 0; j < 8; ++j)
                    acc[i][j] = fmaf(a[i], b[j], acc[i][j]);
        }
        __syncthreads();
    }
#pragma unroll
    for (int i = 0; i < 8; ++i) {
        float* cp = C + (size_t)(m0 + ty * 8 + i) * N + n0 + tx * 8;
#pragma unroll
        for (int j = 0; j < 8; j += 4) {
            *(float4*)(cp + j) =
                make_float4(acc[i][j], acc[i][j + 1], acc[i][j + 2], acc[i][j + 3]);
        }
    }
}

// ---------------- causal flash attention, fp32 ----------------
// Block: 64 q rows, 128 threads (2 threads per row, dk split 64/64).
// K/V staged in 32-row smem tiles. Online softmax with branch-on-new-max.
__global__ void __launch_bounds__(128) flash_kernel() {
    __shared__ float4 Ks[32][32];   // 32 rows x 128 floats
    __shared__ float4 Vs[32][32];
    const int tid  = threadIdx.x;
    const int qb   = blockIdx.x;
    const int h    = blockIdx.y;
    const int b    = blockIdx.z;
    const int rloc = tid >> 1;
    const int half = tid & 1;
    const int s    = qb * 64 + rloc;            // query position
    const size_t row = (size_t)b * SEQ + s;
    const int hoff = h * DK + half * 64;

    float q[64], acc[64];
    const float* qp = g_Q + row * D_MODEL + hoff;
#pragma unroll
    for (int d4 = 0; d4 < 16; ++d4) {
        float4 v = *(const float4*)(qp + d4 * 4);
        q[d4 * 4 + 0] = v.x; q[d4 * 4 + 1] = v.y;
        q[d4 * 4 + 2] = v.z; q[d4 * 4 + 3] = v.w;
        acc[d4 * 4 + 0] = 0.f; acc[d4 * 4 + 1] = 0.f;
        acc[d4 * 4 + 2] = 0.f; acc[d4 * 4 + 3] = 0.f;
    }
    float mval = -3.0e38f, l = 0.f;
    const float scale = 0.08838834764831845f;   // 1/sqrt(128)
    const int jend = qb * 64 + 64;

    for (int j0 = 0; j0 < jend; j0 += 32) {
        __syncthreads();
#pragma unroll
        for (int t = 0; t < 8; ++t) {
            int idx = tid + t * 128;            // 0..1023
            int r = idx >> 5;
            int c = idx & 31;
            size_t gbase = ((size_t)b * SEQ + j0 + r) * D_MODEL + h * DK + c * 4;
            Ks[r][c] = *(const float4*)(g_K + gbase);
            Vs[r][c] = *(const float4*)(g_V + gbase);
        }
        __syncthreads();
        const int jcount = min(32, s - j0 + 1); // valid j's this tile for my row
        for (int j = 0; j < 32; ++j) {
            float part = 0.f;
            const float4* kr = &Ks[j][half * 16];
#pragma unroll
            for (int d4 = 0; d4 < 16; ++d4) {
                float4 kk = kr[d4];
                part = fmaf(q[d4 * 4 + 0], kk.x, part);
                part = fmaf(q[d4 * 4 + 1], kk.y, part);
                part = fmaf(q[d4 * 4 + 2], kk.z, part);
                part = fmaf(q[d4 * 4 + 3], kk.w, part);
            }
            float full = part + __shfl_xor_sync(0xffffffffu, part, 1);
            float sc = full * scale;
            if (j < jcount) {
                float p;
                if (sc > mval) {
                    float corr = __expf(mval - sc);
                    l *= corr;
#pragma unroll
                    for (int d = 0; d < 64; ++d) acc[d] *= corr;
                    mval = sc;
                    p = 1.f;
                } else {
                    p = __expf(sc - mval);
                }
                l += p;
                const float4* vr = &Vs[j][half * 16];
#pragma unroll
                for (int d4 = 0; d4 < 16; ++d4) {
                    float4 vv = vr[d4];
                    acc[d4 * 4 + 0] = fmaf(p, vv.x, acc[d4 * 4 + 0]);
                    acc[d4 * 4 + 1] = fmaf(p, vv.y, acc[d4 * 4 + 1]);
                    acc[d4 * 4 + 2] = fmaf(p, vv.z, acc[d4 * 4 + 2]);
                    acc[d4 * 4 + 3] = fmaf(p, vv.w, acc[d4 * 4 + 3]);
                }
            }
        }
    }
    float inv = 1.0f / l;
    float* op = g_attn + row * D_MODEL + hoff;
#pragma unroll
    for (int d4 = 0; d4 < 16; ++d4) {
        *(float4*)(op + d4 * 4) = make_float4(acc[d4 * 4 + 0] * inv,
                                              acc[d4 * 4 + 1] * inv,
                                              acc[d4 * 4 + 2] * inv,
                                              acc[d4 * 4 + 3] * inv);
    }
}

// ---------------- launch ----------------
extern "C" void kernel_launch(void* const* d_in, const int* in_sizes, int n_in,
                              void* d_out, int out_size) {
    const float* x  = (const float*)d_in[0];
    // d_in[1] = token_positions (arange; positions derived from index directly)
    const float* Wq = (const float*)d_in[2];
    const float* Wk = (const float*)d_in[3];
    const float* Wv = (const float*)d_in[4];
    const float* Wo = (const float*)d_in[5];
    float* out = (float*)d_out;

    float *pQ, *pK, *pV, *pA;
    cudaGetSymbolAddress((void**)&pQ, g_Q);
    cudaGetSymbolAddress((void**)&pK, g_K);
    cudaGetSymbolAddress((void**)&pV, g_V);
    cudaGetSymbolAddress((void**)&pA, g_attn);

    rope_table_kernel<<<(SEQ * 64 + 255) / 256, 256>>>();

    dim3 gg(D_MODEL / 128, MROWS / 128);   // (16, 32)
    sgemm_nt<<<gg, 256>>>(x, Wq, pQ, MROWS, D_MODEL, D_MODEL);
    sgemm_nt<<<gg, 256>>>(x, Wk, pK, MROWS, D_MODEL, D_MODEL);
    sgemm_nt<<<gg, 256>>>(x, Wv, pV, MROWS, D_MODEL, D_MODEL);

    rope_apply_kernel<<<(MROWS * (D_MODEL / 2) + 255) / 256, 256>>>();

    flash_kernel<<<dim3(SEQ / 64, NHEADS, BATCH), 128>>>();

    sgemm_nt<<<gg, 256>>>(pA, Wo, out, MROWS, D_MODEL, D_MODEL);
}

// round 4
// speedup vs baseline: 1.9002x; 1.9002x over previous
#include <cuda_runtime.h>
#include <cuda_bf16.h>
#include <mma.h>
#include <cstdint>
#include <math.h>

using namespace nvcuda;

#define D_MODEL 2048
#define SEQ     2048
#define BATCH   2
#define NHEADS  16
#define DK      128
#define MROWS   (BATCH*SEQ)   /* 4096 */

// ---------------- scratch (device globals; no allocs allowed) ----------------
__device__ float g_Q[(size_t)MROWS * D_MODEL];
__device__ float g_K[(size_t)MROWS * D_MODEL];
__device__ float g_V[(size_t)MROWS * D_MODEL];
__device__ float g_attn[(size_t)MROWS * D_MODEL];
__device__ float g_cos[SEQ * (DK / 2)];
__device__ float g_sin[SEQ * (DK / 2)];

// bf16 hi/lo splits
__device__ __nv_bfloat16 g_xh[(size_t)MROWS * D_MODEL];
__device__ __nv_bfloat16 g_xl[(size_t)MROWS * D_MODEL];
__device__ __nv_bfloat16 g_wqh[(size_t)D_MODEL * D_MODEL];
__device__ __nv_bfloat16 g_wql[(size_t)D_MODEL * D_MODEL];
__device__ __nv_bfloat16 g_wkh[(size_t)D_MODEL * D_MODEL];
__device__ __nv_bfloat16 g_wkl[(size_t)D_MODEL * D_MODEL];
__device__ __nv_bfloat16 g_wvh[(size_t)D_MODEL * D_MODEL];
__device__ __nv_bfloat16 g_wvl[(size_t)D_MODEL * D_MODEL];
__device__ __nv_bfloat16 g_woh[(size_t)D_MODEL * D_MODEL];
__device__ __nv_bfloat16 g_wol[(size_t)D_MODEL * D_MODEL];
__device__ __nv_bfloat16 g_ah[(size_t)MROWS * D_MODEL];
__device__ __nv_bfloat16 g_al[(size_t)MROWS * D_MODEL];

// ---------------- generic PTX helpers (base-arch safe) ----------------
__device__ __forceinline__ void cpa16(uint32_t dst, const void* src) {
    asm volatile("cp.async.cg.shared.global [%0], [%1], 16;" :: "r"(dst), "l"(src));
}
#define CPA_COMMIT() asm volatile("cp.async.commit_group;" ::: "memory")
#define CPA_WAIT0()  asm volatile("cp.async.wait_group 0;" ::: "memory")

__device__ __forceinline__ uint32_t su32(const void* p) {
    uint32_t a;
    asm("{ .reg .u64 t; cvta.to.shared.u64 t, %1; cvt.u32.u64 %0, t; }" : "=r"(a) : "l"(p));
    return a;
}

// ---------------- split fp32 -> bf16 hi/lo ----------------
__global__ void split_kernel(const float* __restrict__ src,
                             __nv_bfloat16* __restrict__ hi,
                             __nv_bfloat16* __restrict__ lo, int n4) {
    int i = blockIdx.x * blockDim.x + threadIdx.x;
    if (i >= n4) return;
    float4 v = ((const float4*)src)[i];
    __nv_bfloat16 h0 = __float2bfloat16(v.x);
    __nv_bfloat16 h1 = __float2bfloat16(v.y);
    __nv_bfloat16 h2 = __float2bfloat16(v.z);
    __nv_bfloat16 h3 = __float2bfloat16(v.w);
    __nv_bfloat16 l0 = __float2bfloat16(v.x - __bfloat162float(h0));
    __nv_bfloat16 l1 = __float2bfloat16(v.y - __bfloat162float(h1));
    __nv_bfloat16 l2 = __float2bfloat16(v.z - __bfloat162float(h2));
    __nv_bfloat16 l3 = __float2bfloat16(v.w - __bfloat162float(h3));
    uint2 hp, lp;
    hp.x = (uint32_t)__bfloat16_as_ushort(h0) | ((uint32_t)__bfloat16_as_ushort(h1) << 16);
    hp.y = (uint32_t)__bfloat16_as_ushort(h2) | ((uint32_t)__bfloat16_as_ushort(h3) << 16);
    lp.x = (uint32_t)__bfloat16_as_ushort(l0) | ((uint32_t)__bfloat16_as_ushort(l1) << 16);
    lp.y = (uint32_t)__bfloat16_as_ushort(l2) | ((uint32_t)__bfloat16_as_ushort(l3) << 16);
    ((uint2*)hi)[i] = hp;
    ((uint2*)lo)[i] = lp;
}

// ============================================================================
// Path A: tcgen05 GEMM — compiled only when the 'a'-feature target exists.
// ============================================================================
#define STAGE_BYTES 65536
#define SMEM_TC     (1024 + 2 * STAGE_BYTES)

#if defined(__CUDA_ARCH__) && defined(__CUDA_ARCH_FEAT_SM103_ALL)
#define HAS_TCGEN05 1
#else
#define HAS_TCGEN05 0
#endif

#if HAS_TCGEN05
__device__ __forceinline__ uint32_t elect1() {
    uint32_t p;
    asm volatile("{ .reg .pred p; elect.sync _|p, 0xFFFFFFFF; selp.b32 %0, 1, 0, p; }" : "=r"(p));
    return p;
}
#define TC_ALLOC(sa, n)  asm volatile("tcgen05.alloc.cta_group::1.sync.aligned.shared::cta.b32 [%0], %1;" :: "r"(sa), "r"(n) : "memory")
#define TC_DEALLOC(t, n) asm volatile("tcgen05.dealloc.cta_group::1.sync.aligned.b32 %0, %1;" :: "r"(t), "r"(n))
#define TC_RELINQ()      asm volatile("tcgen05.relinquish_alloc_permit.cta_group::1.sync.aligned;")
#define TC_COMMIT(mb)    asm volatile("tcgen05.commit.cta_group::1.mbarrier::arrive::one.shared::cluster.b64 [%0];" :: "r"(mb) : "memory")
#define TC_FENCE_AFTER() asm volatile("tcgen05.fence::after_thread_sync;" ::: "memory")
#define TC_WAIT_LD()     asm volatile("tcgen05.wait::ld.sync.aligned;" ::: "memory")
#define MB_INIT(mb, c)   asm volatile("mbarrier.init.shared.b64 [%0], %1;" :: "r"(mb), "r"(c) : "memory")
#define FENCE_ASYNC()    asm volatile("fence.proxy.async.shared::cta;" ::: "memory")

__device__ __forceinline__ void mbar_wait(uint32_t mb, uint32_t parity) {
    asm volatile(
        "{\n\t.reg .pred P;\n\t"
        "W%=:\n\t"
        "mbarrier.try_wait.parity.acquire.cta.shared::cta.b64 P, [%0], %1, 0x989680;\n\t"
        "@P bra D%=;\n\t"
        "bra W%=;\n\t"
        "D%=:\n\t}"
        :: "r"(mb), "r"(parity) : "memory");
}
__device__ __forceinline__ void mma_ss(uint32_t d, uint64_t a, uint64_t b,
                                       uint32_t idesc, uint32_t acc) {
    asm volatile(
        "{\n\t.reg .pred p;\n\t"
        "setp.ne.u32 p, %5, 0;\n\t"
        "tcgen05.mma.cta_group::1.kind::f16 [%0], %1, %2, %3, {%4, %4, %4, %4}, p;\n\t}"
        :: "r"(d), "l"(a), "l"(b), "r"(idesc), "r"(0u), "r"(acc) : "memory");
}
#define LDTM_X32(r, a) \
    asm volatile("tcgen05.ld.sync.aligned.32x32b.x32.b32 " \
        "{%0,%1,%2,%3,%4,%5,%6,%7,%8,%9,%10,%11,%12,%13,%14,%15," \
        "%16,%17,%18,%19,%20,%21,%22,%23,%24,%25,%26,%27,%28,%29,%30,%31}, [%32];" \
        : "=r"((r)[0]),"=r"((r)[1]),"=r"((r)[2]),"=r"((r)[3]),"=r"((r)[4]),"=r"((r)[5]), \
          "=r"((r)[6]),"=r"((r)[7]),"=r"((r)[8]),"=r"((r)[9]),"=r"((r)[10]),"=r"((r)[11]), \
          "=r"((r)[12]),"=r"((r)[13]),"=r"((r)[14]),"=r"((r)[15]),"=r"((r)[16]),"=r"((r)[17]), \
          "=r"((r)[18]),"=r"((r)[19]),"=r"((r)[20]),"=r"((r)[21]),"=r"((r)[22]),"=r"((r)[23]), \
          "=r"((r)[24]),"=r"((r)[25]),"=r"((r)[26]),"=r"((r)[27]),"=r"((r)[28]),"=r"((r)[29]), \
          "=r"((r)[30]),"=r"((r)[31]) : "r"(a))

#define SW128(o) ((o) ^ (((o) >> 3) & 0x70))
__device__ __forceinline__ uint64_t mk_desc(uint32_t addr) {
    return ((uint64_t)2 << 61) | ((uint64_t)1 << 46) | ((uint64_t)64 << 32) |
           ((uint64_t)1 << 16) | ((uint64_t)(addr >> 4) & 0x3FFF);
}
#define GEMM_IDESC ((1u << 4) | (1u << 7) | (1u << 10) | (16u << 17) | (8u << 24))

__device__ __forceinline__ void load_chunk_tc(
    uint32_t sdst, const __nv_bfloat16* __restrict__ Ah, const __nv_bfloat16* __restrict__ Al,
    const __nv_bfloat16* __restrict__ Bh, const __nv_bfloat16* __restrict__ Bl,
    int m0, int n0, int k0, int K, int tid) {
#pragma unroll
    for (int t = 0; t < 8; ++t) {
        int u = t * 128 + tid;
        int row = u >> 3;
        int c16 = u & 7;
        uint32_t sw = SW128(row * 128 + c16 * 16);
        size_t aoff = (size_t)(m0 + row) * K + k0 + c16 * 8;
        size_t boff = (size_t)(n0 + row) * K + k0 + c16 * 8;
        cpa16(sdst + sw,         Ah + aoff);
        cpa16(sdst + 16384 + sw, Al + aoff);
        cpa16(sdst + 32768 + sw, Bh + boff);
        cpa16(sdst + 49152 + sw, Bl + boff);
    }
}
#endif // HAS_TCGEN05

__global__ void __launch_bounds__(128) gemm_tcgen(
    const __nv_bfloat16* __restrict__ Ah, const __nv_bfloat16* __restrict__ Al,
    const __nv_bfloat16* __restrict__ Bh, const __nv_bfloat16* __restrict__ Bl,
    float* __restrict__ C, int N, int K) {
#if HAS_TCGEN05
    extern __shared__ char smem[];
    const uint32_t sbase = su32(smem);
    const uint32_t tbase = (sbase + 16 + 1023) & ~1023u;
    const int tid = threadIdx.x;
    const int wid = tid >> 5;
    const int lid = tid & 31;
    const int m0 = blockIdx.y * 128;
    const int n0 = blockIdx.x * 128;
    const int nchunk = K >> 6;

    if (wid == 0) TC_ALLOC(sbase, 128);
    if (tid == 0) MB_INIT(sbase + 8, 1);
    __syncthreads();
    uint32_t tmem;
    asm volatile("ld.shared.b32 %0, [%1];" : "=r"(tmem) : "r"(sbase));

    load_chunk_tc(tbase, Ah, Al, Bh, Bl, m0, n0, 0, K, tid);
    CPA_COMMIT();
    CPA_WAIT0();
    FENCE_ASYNC();
    __syncthreads();

    for (int c = 0; c < nchunk; ++c) {
        const int p = c & 1;
        const uint32_t sb = tbase + p * STAGE_BYTES;
        if (wid == 0 && elect1()) {
            uint64_t dAh = mk_desc(sb);
            uint64_t dAl = mk_desc(sb + 16384);
            uint64_t dBh = mk_desc(sb + 32768);
            uint64_t dBl = mk_desc(sb + 49152);
#pragma unroll
            for (int ks = 0; ks < 4; ++ks) {
                uint32_t first = (c == 0 && ks == 0) ? 0u : 1u;
                mma_ss(tmem, dAh + ks * 2, dBh + ks * 2, GEMM_IDESC, first);
                mma_ss(tmem, dAh + ks * 2, dBl + ks * 2, GEMM_IDESC, 1u);
                mma_ss(tmem, dAl + ks * 2, dBh + ks * 2, GEMM_IDESC, 1u);
            }
            TC_COMMIT(sbase + 8);
        }
        if (c + 1 < nchunk) {
            load_chunk_tc(tbase + (p ^ 1) * STAGE_BYTES, Ah, Al, Bh, Bl,
                          m0, n0, (c + 1) << 6, K, tid);
            CPA_COMMIT();
            CPA_WAIT0();
            FENCE_ASYNC();
        }
        mbar_wait(sbase + 8, (uint32_t)(c & 1));
        __syncthreads();
    }
    TC_FENCE_AFTER();

#pragma unroll
    for (int g = 0; g < 4; ++g) {
        uint32_t r[32];
        LDTM_X32(r, tmem + g * 32);
        TC_WAIT_LD();
        float* cp = C + (size_t)(m0 + wid * 32 + lid) * N + n0 + g * 32;
#pragma unroll
        for (int j = 0; j < 32; j += 4) {
            *(float4*)(cp + j) = make_float4(__uint_as_float(r[j]),
                                             __uint_as_float(r[j + 1]),
                                             __uint_as_float(r[j + 2]),
                                             __uint_as_float(r[j + 3]));
        }
    }
    __syncthreads();
    if (wid == 0) {
        TC_RELINQ();
        TC_DEALLOC(tmem, 128);
    }
#endif // HAS_TCGEN05
}

// ============================================================================
// Path B: wmma bf16 HMMA GEMM — base-arch fallback (runs when tcgen05 can't).
// CTA 128x128, 4 warps of 64x64; split precision AhBh + AhBl + AlBh.
// ============================================================================
#define WPAD       24                    /* padded k-pitch (elems) for k=16 stage */
#define WSTG_EL    (128 * WPAD)          /* elems per matrix per stage */
#define WSTAGE_B   (4 * WSTG_EL * 2)     /* bytes per stage (4 matrices) */
#define SMEM_WMMA  (2 * WSTAGE_B)        /* 49152 */

__device__ __forceinline__ void load_chunk_wmma(
    uint32_t sdst, const __nv_bfloat16* __restrict__ Ah, const __nv_bfloat16* __restrict__ Al,
    const __nv_bfloat16* __restrict__ Bh, const __nv_bfloat16* __restrict__ Bl,
    int m0, int n0, int k0, int K, int tid) {
    const __nv_bfloat16* srcs[4] = {Ah, Al, Bh, Bl};
#pragma unroll
    for (int t = 0; t < 8; ++t) {
        int u = t * 128 + tid;        // 0..1023: 4 matrices x 128 rows x 2 chunks
        int mtx = u >> 8;
        int rem = u & 255;
        int row = rem >> 1;
        int c16 = rem & 1;
        int gr = (mtx < 2 ? m0 : n0) + row;
        uint32_t doff = (uint32_t)mtx * (WSTG_EL * 2) + row * (WPAD * 2) + c16 * 16;
        cpa16(sdst + doff, srcs[mtx] + (size_t)gr * K + k0 + c16 * 8);
    }
}

__global__ void __launch_bounds__(128) gemm_wmma(
    const __nv_bfloat16* __restrict__ Ah, const __nv_bfloat16* __restrict__ Al,
    const __nv_bfloat16* __restrict__ Bh, const __nv_bfloat16* __restrict__ Bl,
    float* __restrict__ C, int N, int K) {
#if !HAS_TCGEN05
    extern __shared__ char smem[];
    const uint32_t sbase = su32(smem);
    const int tid = threadIdx.x;
    const int wid = tid >> 5;
    const int m0 = blockIdx.y * 128;
    const int n0 = blockIdx.x * 128;
    const int wm = (wid & 1) * 64;    // warp sub-tile origin within CTA tile
    const int wn = (wid >> 1) * 64;
    const int nchunk = K >> 4;

    wmma::fragment<wmma::accumulator, 16, 16, 16, float> acc[4][4];
#pragma unroll
    for (int mi = 0; mi < 4; ++mi)
#pragma unroll
        for (int ni = 0; ni < 4; ++ni) wmma::fill_fragment(acc[mi][ni], 0.0f);

    load_chunk_wmma(sbase, Ah, Al, Bh, Bl, m0, n0, 0, K, tid);
    CPA_COMMIT();

    for (int c = 0; c < nchunk; ++c) {
        const int p = c & 1;
        const __nv_bfloat16* s = (const __nv_bfloat16*)(smem + p * WSTAGE_B);
        const __nv_bfloat16* sah = s;
        const __nv_bfloat16* sal = s + WSTG_EL;
        const __nv_bfloat16* sbh = s + 2 * WSTG_EL;
        const __nv_bfloat16* sbl = s + 3 * WSTG_EL;

        CPA_WAIT0();
        __syncthreads();
        if (c + 1 < nchunk) {
            load_chunk_wmma(sbase + (p ^ 1) * WSTAGE_B, Ah, Al, Bh, Bl,
                            m0, n0, (c + 1) << 4, K, tid);
            CPA_COMMIT();
        }

        wmma::fragment<wmma::matrix_b, 16, 16, 16, __nv_bfloat16, wmma::col_major> fbh[4], fbl[4];
#pragma unroll
        for (int ni = 0; ni < 4; ++ni) {
            wmma::load_matrix_sync(fbh[ni], sbh + (wn + ni * 16) * WPAD, WPAD);
            wmma::load_matrix_sync(fbl[ni], sbl + (wn + ni * 16) * WPAD, WPAD);
        }
#pragma unroll
        for (int mi = 0; mi < 4; ++mi) {
            wmma::fragment<wmma::matrix_a, 16, 16, 16, __nv_bfloat16, wmma::row_major> fah, fal;
            wmma::load_matrix_sync(fah, sah + (wm + mi * 16) * WPAD, WPAD);
            wmma::load_matrix_sync(fal, sal + (wm + mi * 16) * WPAD, WPAD);
#pragma unroll
            for (int ni = 0; ni < 4; ++ni) {
                wmma::mma_sync(acc[mi][ni], fah, fbh[ni], acc[mi][ni]);
                wmma::mma_sync(acc[mi][ni], fah, fbl[ni], acc[mi][ni]);
                wmma::mma_sync(acc[mi][ni], fal, fbh[ni], acc[mi][ni]);
            }
        }
        __syncthreads();
    }

#pragma unroll
    for (int mi = 0; mi < 4; ++mi)
#pragma unroll
        for (int ni = 0; ni < 4; ++ni)
            wmma::store_matrix_sync(C + (size_t)(m0 + wm + mi * 16) * N + n0 + wn + ni * 16,
                                    acc[mi][ni], N, wmma::mem_row_major);
#endif // !HAS_TCGEN05
}

// ---------------- RoPE tables ----------------
__global__ void rope_table_kernel() {
    int idx = blockIdx.x * blockDim.x + threadIdx.x;
    if (idx >= SEQ * 64) return;
    int s = idx >> 6;
    int i = idx & 63;
    float th = powf(10000.0f, (float)i * (1.0f / 64.0f));
    float ph = (float)s / th;
    double phd = (double)ph;
    g_cos[idx] = (float)cos(phd);
    g_sin[idx] = (float)sin(phd);
}

// ---------------- RoPE apply (in-place on g_Q, g_K) ----------------
__global__ void rope_apply_kernel() {
    int idx = blockIdx.x * blockDim.x + threadIdx.x;
    if (idx >= MROWS * (D_MODEL / 2)) return;
    int row = idx >> 10;
    int c2  = idx & 1023;
    int i   = c2 & 63;
    int s   = row & (SEQ - 1);
    float c  = g_cos[(s << 6) + i];
    float sn = g_sin[(s << 6) + i];
    size_t off = (size_t)row * (D_MODEL / 2) + c2;
    float2* Q2 = (float2*)g_Q;
    float2* K2 = (float2*)g_K;
    float2 q = Q2[off];
    Q2[off] = make_float2(q.x * c - q.y * sn, q.x * sn + q.y * c);
    float2 k = K2[off];
    K2[off] = make_float2(k.x * c - k.y * sn, k.x * sn + k.y * c);
}

// ---------------- causal flash attention, fp32 ----------------
__global__ void __launch_bounds__(128) flash_kernel() {
    __shared__ float4 Ks[32][32];
    __shared__ float4 Vs[32][32];
    const int tid  = threadIdx.x;
    const int qb   = blockIdx.x;
    const int h    = blockIdx.y;
    const int b    = blockIdx.z;
    const int rloc = tid >> 1;
    const int half = tid & 1;
    const int s    = qb * 64 + rloc;
    const size_t row = (size_t)b * SEQ + s;
    const int hoff = h * DK + half * 64;

    float q[64], acc[64];
    const float* qp = g_Q + row * D_MODEL + hoff;
#pragma unroll
    for (int d4 = 0; d4 < 16; ++d4) {
        float4 v = *(const float4*)(qp + d4 * 4);
        q[d4 * 4 + 0] = v.x; q[d4 * 4 + 1] = v.y;
        q[d4 * 4 + 2] = v.z; q[d4 * 4 + 3] = v.w;
        acc[d4 * 4 + 0] = 0.f; acc[d4 * 4 + 1] = 0.f;
        acc[d4 * 4 + 2] = 0.f; acc[d4 * 4 + 3] = 0.f;
    }
    float mval = -3.0e38f, l = 0.f;
    const float scale = 0.08838834764831845f;
    const int jend = qb * 64 + 64;

    for (int j0 = 0; j0 < jend; j0 += 32) {
        __syncthreads();
#pragma unroll
        for (int t = 0; t < 8; ++t) {
            int idx = tid + t * 128;
            int r = idx >> 5;
            int c = idx & 31;
            size_t gbase = ((size_t)b * SEQ + j0 + r) * D_MODEL + h * DK + c * 4;
            Ks[r][c] = *(const float4*)(g_K + gbase);
            Vs[r][c] = *(const float4*)(g_V + gbase);
        }
        __syncthreads();
        const int jcount = min(32, s - j0 + 1);
        for (int j = 0; j < 32; ++j) {
            float part = 0.f;
            const float4* kr = &Ks[j][half * 16];
#pragma unroll
            for (int d4 = 0; d4 < 16; ++d4) {
                float4 kk = kr[d4];
                part = fmaf(q[d4 * 4 + 0], kk.x, part);
                part = fmaf(q[d4 * 4 + 1], kk.y, part);
                part = fmaf(q[d4 * 4 + 2], kk.z, part);
                part = fmaf(q[d4 * 4 + 3], kk.w, part);
            }
            float full = part + __shfl_xor_sync(0xffffffffu, part, 1);
            float sc = full * scale;
            if (j < jcount) {
                float p;
                if (sc > mval) {
                    float corr = __expf(mval - sc);
                    l *= corr;
#pragma unroll
                    for (int d = 0; d < 64; ++d) acc[d] *= corr;
                    mval = sc;
                    p = 1.f;
                } else {
                    p = __expf(sc - mval);
                }
                l += p;
                const float4* vr = &Vs[j][half * 16];
#pragma unroll
                for (int d4 = 0; d4 < 16; ++d4) {
                    float4 vv = vr[d4];
                    acc[d4 * 4 + 0] = fmaf(p, vv.x, acc[d4 * 4 + 0]);
                    acc[d4 * 4 + 1] = fmaf(p, vv.y, acc[d4 * 4 + 1]);
                    acc[d4 * 4 + 2] = fmaf(p, vv.z, acc[d4 * 4 + 2]);
                    acc[d4 * 4 + 3] = fmaf(p, vv.w, acc[d4 * 4 + 3]);
                }
            }
        }
    }
    float inv = 1.0f / l;
    float* op = g_attn + row * D_MODEL + hoff;
#pragma unroll
    for (int d4 = 0; d4 < 16; ++d4) {
        *(float4*)(op + d4 * 4) = make_float4(acc[d4 * 4 + 0] * inv,
                                              acc[d4 * 4 + 1] * inv,
                                              acc[d4 * 4 + 2] * inv,
                                              acc[d4 * 4 + 3] * inv);
    }
}

// ---------------- launch ----------------
static inline void run_gemm(const __nv_bfloat16* ah, const __nv_bfloat16* al,
                            const __nv_bfloat16* bh, const __nv_bfloat16* bl,
                            float* c) {
    dim3 gg(D_MODEL / 128, MROWS / 128);   // (16, 32)
    gemm_tcgen<<<gg, 128, SMEM_TC>>>(ah, al, bh, bl, c, D_MODEL, D_MODEL);
    gemm_wmma<<<gg, 128, SMEM_WMMA>>>(ah, al, bh, bl, c, D_MODEL, D_MODEL);
}

extern "C" void kernel_launch(void* const* d_in, const int* in_sizes, int n_in,
                              void* d_out, int out_size) {
    const float* x  = (const float*)d_in[0];
    const float* Wq = (const float*)d_in[2];
    const float* Wk = (const float*)d_in[3];
    const float* Wv = (const float*)d_in[4];
    const float* Wo = (const float*)d_in[5];
    float* out = (float*)d_out;

    float *pQ, *pK, *pV, *pA;
    cudaGetSymbolAddress((void**)&pQ, g_Q);
    cudaGetSymbolAddress((void**)&pK, g_K);
    cudaGetSymbolAddress((void**)&pV, g_V);
    cudaGetSymbolAddress((void**)&pA, g_attn);
    __nv_bfloat16 *xh, *xl, *wqh, *wql, *wkh, *wkl, *wvh, *wvl, *woh, *wol, *ah, *al;
    cudaGetSymbolAddress((void**)&xh, g_xh);   cudaGetSymbolAddress((void**)&xl, g_xl);
    cudaGetSymbolAddress((void**)&wqh, g_wqh); cudaGetSymbolAddress((void**)&wql, g_wql);
    cudaGetSymbolAddress((void**)&wkh, g_wkh); cudaGetSymbolAddress((void**)&wkl, g_wkl);
    cudaGetSymbolAddress((void**)&wvh, g_wvh); cudaGetSymbolAddress((void**)&wvl, g_wvl);
    cudaGetSymbolAddress((void**)&woh, g_woh); cudaGetSymbolAddress((void**)&wol, g_wol);
    cudaGetSymbolAddress((void**)&ah, g_ah);   cudaGetSymbolAddress((void**)&al, g_al);

    cudaFuncSetAttribute(gemm_tcgen, cudaFuncAttributeMaxDynamicSharedMemorySize, SMEM_TC);
    cudaFuncSetAttribute(gemm_wmma, cudaFuncAttributeMaxDynamicSharedMemorySize, SMEM_WMMA);

    rope_table_kernel<<<(SEQ * 64 + 255) / 256, 256>>>();

    const int nx4 = MROWS * D_MODEL / 4;
    const int nw4 = D_MODEL * D_MODEL / 4;
    split_kernel<<<(nx4 + 255) / 256, 256>>>(x, xh, xl, nx4);
    split_kernel<<<(nw4 + 255) / 256, 256>>>(Wq, wqh, wql, nw4);
    split_kernel<<<(nw4 + 255) / 256, 256>>>(Wk, wkh, wkl, nw4);
    split_kernel<<<(nw4 + 255) / 256, 256>>>(Wv, wvh, wvl, nw4);
    split_kernel<<<(nw4 + 255) / 256, 256>>>(Wo, woh, wol, nw4);

    run_gemm(xh, xl, wqh, wql, pQ);
    run_gemm(xh, xl, wkh, wkl, pK);
    run_gemm(xh, xl, wvh, wvl, pV);

    rope_apply_kernel<<<(MROWS * (D_MODEL / 2) + 255) / 256, 256>>>();

    flash_kernel<<<dim3(SEQ / 64, NHEADS, BATCH), 128>>>();

    split_kernel<<<(nx4 + 255) / 256, 256>>>(pA, ah, al, nx4);
    run_gemm(ah, al, woh, wol, out);
}

// round 5
// speedup vs baseline: 2.6283x; 1.3832x over previous
#include <cuda_runtime.h>
#include <cuda_bf16.h>
#include <mma.h>
#include <cstdint>
#include <math.h>

using namespace nvcuda;

#define D_MODEL 2048
#define SEQ     2048
#define BATCH   2
#define NHEADS  16
#define DK      128
#define MROWS   (BATCH*SEQ)   /* 4096 */

// ---------------- scratch (device globals; no allocs allowed) ----------------
__device__ float g_Q[(size_t)MROWS * D_MODEL];
__device__ float g_K[(size_t)MROWS * D_MODEL];
__device__ float g_V[(size_t)MROWS * D_MODEL];
__device__ float g_attn[(size_t)MROWS * D_MODEL];
__device__ float g_cos[SEQ * (DK / 2)];
__device__ float g_sin[SEQ * (DK / 2)];

// bf16 hi/lo splits (GEMM operands)
__device__ __nv_bfloat16 g_xh[(size_t)MROWS * D_MODEL];
__device__ __nv_bfloat16 g_xl[(size_t)MROWS * D_MODEL];
__device__ __nv_bfloat16 g_wqh[(size_t)D_MODEL * D_MODEL];
__device__ __nv_bfloat16 g_wql[(size_t)D_MODEL * D_MODEL];
__device__ __nv_bfloat16 g_wkh[(size_t)D_MODEL * D_MODEL];
__device__ __nv_bfloat16 g_wkl[(size_t)D_MODEL * D_MODEL];
__device__ __nv_bfloat16 g_wvh[(size_t)D_MODEL * D_MODEL];
__device__ __nv_bfloat16 g_wvl[(size_t)D_MODEL * D_MODEL];
__device__ __nv_bfloat16 g_woh[(size_t)D_MODEL * D_MODEL];
__device__ __nv_bfloat16 g_wol[(size_t)D_MODEL * D_MODEL];
__device__ __nv_bfloat16 g_ah[(size_t)MROWS * D_MODEL];
__device__ __nv_bfloat16 g_al[(size_t)MROWS * D_MODEL];

// flash operands: rope'd Q/K and V, hi/lo bf16
__device__ __nv_bfloat16 g_qh[(size_t)MROWS * D_MODEL];
__device__ __nv_bfloat16 g_ql[(size_t)MROWS * D_MODEL];
__device__ __nv_bfloat16 g_kh[(size_t)MROWS * D_MODEL];
__device__ __nv_bfloat16 g_kl[(size_t)MROWS * D_MODEL];
__device__ __nv_bfloat16 g_vh[(size_t)MROWS * D_MODEL];
__device__ __nv_bfloat16 g_vl[(size_t)MROWS * D_MODEL];

// ---------------- generic PTX helpers (base-arch safe) ----------------
__device__ __forceinline__ void cpa16(uint32_t dst, const void* src) {
    asm volatile("cp.async.cg.shared.global [%0], [%1], 16;" :: "r"(dst), "l"(src));
}
#define CPA_COMMIT() asm volatile("cp.async.commit_group;" ::: "memory")
#define CPA_WAIT0()  asm volatile("cp.async.wait_group 0;" ::: "memory")

__device__ __forceinline__ uint32_t su32(const void* p) {
    uint32_t a;
    asm("{ .reg .u64 t; cvta.to.shared.u64 t, %1; cvt.u32.u64 %0, t; }" : "=r"(a) : "l"(p));
    return a;
}

#define LDSM4(r0, r1, r2, r3, a) \
    asm volatile("ldmatrix.sync.aligned.m8n8.x4.shared.b16 {%0,%1,%2,%3}, [%4];" \
                 : "=r"(r0), "=r"(r1), "=r"(r2), "=r"(r3) : "r"(a))
#define LDSM4T(r0, r1, r2, r3, a) \
    asm volatile("ldmatrix.sync.aligned.m8n8.x4.trans.shared.b16 {%0,%1,%2,%3}, [%4];" \
                 : "=r"(r0), "=r"(r1), "=r"(r2), "=r"(r3) : "r"(a))
#define MMA16816(d, a0, a1, a2, a3, b0, b1) \
    asm volatile("mma.sync.aligned.m16n8k16.row.col.f32.bf16.bf16.f32 " \
                 "{%0,%1,%2,%3}, {%4,%5,%6,%7}, {%8,%9}, {%0,%1,%2,%3};" \
                 : "+f"((d)[0]), "+f"((d)[1]), "+f"((d)[2]), "+f"((d)[3]) \
                 : "r"(a0), "r"(a1), "r"(a2), "r"(a3), "r"(b0), "r"(b1))

// pack two floats -> bf16x2 reg (lo first)
__device__ __forceinline__ uint32_t packbf(float lo, float hi) {
    uint32_t u;
    asm("cvt.rn.bf16x2.f32 %0, %1, %2;" : "=r"(u) : "f"(hi), "f"(lo));
    return u;
}

// fast exp2 on FMA pipe (arg <= 0), rel err ~1.5e-5
__device__ __forceinline__ float exp2ff(float x) {
    x = fmaxf(x, -126.0f);
    float fl = floorf(x);
    float f = x - fl;
    float p = 1.54035304e-4f;
    p = fmaf(p, f, 1.33335581e-3f);
    p = fmaf(p, f, 9.61812910e-3f);
    p = fmaf(p, f, 5.55041086e-2f);
    p = fmaf(p, f, 2.40226512e-1f);
    p = fmaf(p, f, 6.93147182e-1f);
    p = fmaf(p, f, 1.0f);
    return __uint_as_float((uint32_t)((int)fl + 127) << 23) * p;
}

// ---------------- split fp32 -> bf16 hi/lo ----------------
__global__ void split_kernel(const float* __restrict__ src,
                             __nv_bfloat16* __restrict__ hi,
                             __nv_bfloat16* __restrict__ lo, int n4) {
    int i = blockIdx.x * blockDim.x + threadIdx.x;
    if (i >= n4) return;
    float4 v = ((const float4*)src)[i];
    __nv_bfloat16 h0 = __float2bfloat16(v.x);
    __nv_bfloat16 h1 = __float2bfloat16(v.y);
    __nv_bfloat16 h2 = __float2bfloat16(v.z);
    __nv_bfloat16 h3 = __float2bfloat16(v.w);
    __nv_bfloat16 l0 = __float2bfloat16(v.x - __bfloat162float(h0));
    __nv_bfloat16 l1 = __float2bfloat16(v.y - __bfloat162float(h1));
    __nv_bfloat16 l2 = __float2bfloat16(v.z - __bfloat162float(h2));
    __nv_bfloat16 l3 = __float2bfloat16(v.w - __bfloat162float(h3));
    uint2 hp, lp;
    hp.x = (uint32_t)__bfloat16_as_ushort(h0) | ((uint32_t)__bfloat16_as_ushort(h1) << 16);
    hp.y = (uint32_t)__bfloat16_as_ushort(h2) | ((uint32_t)__bfloat16_as_ushort(h3) << 16);
    lp.x = (uint32_t)__bfloat16_as_ushort(l0) | ((uint32_t)__bfloat16_as_ushort(l1) << 16);
    lp.y = (uint32_t)__bfloat16_as_ushort(l2) | ((uint32_t)__bfloat16_as_ushort(l3) << 16);
    ((uint2*)hi)[i] = hp;
    ((uint2*)lo)[i] = lp;
}

// ============================================================================
// wmma bf16 GEMM (proven path): CTA 128x128, 4 warps, AhBh + AhBl + AlBh.
// ============================================================================
#define WPAD       24
#define WSTG_EL    (128 * WPAD)
#define WSTAGE_B   (4 * WSTG_EL * 2)
#define SMEM_WMMA  (2 * WSTAGE_B)

__device__ __forceinline__ void load_chunk_wmma(
    uint32_t sdst, const __nv_bfloat16* __restrict__ Ah, const __nv_bfloat16* __restrict__ Al,
    const __nv_bfloat16* __restrict__ Bh, const __nv_bfloat16* __restrict__ Bl,
    int m0, int n0, int k0, int K, int tid) {
    const __nv_bfloat16* srcs[4] = {Ah, Al, Bh, Bl};
#pragma unroll
    for (int t = 0; t < 8; ++t) {
        int u = t * 128 + tid;
        int mtx = u >> 8;
        int rem = u & 255;
        int row = rem >> 1;
        int c16 = rem & 1;
        int gr = (mtx < 2 ? m0 : n0) + row;
        uint32_t doff = (uint32_t)mtx * (WSTG_EL * 2) + row * (WPAD * 2) + c16 * 16;
        cpa16(sdst + doff, srcs[mtx] + (size_t)gr * K + k0 + c16 * 8);
    }
}

__global__ void __launch_bounds__(128) gemm_wmma(
    const __nv_bfloat16* __restrict__ Ah, const __nv_bfloat16* __restrict__ Al,
    const __nv_bfloat16* __restrict__ Bh, const __nv_bfloat16* __restrict__ Bl,
    float* __restrict__ C, int N, int K) {
    extern __shared__ char smem[];
    const uint32_t sbase = su32(smem);
    const int tid = threadIdx.x;
    const int wid = tid >> 5;
    const int m0 = blockIdx.y * 128;
    const int n0 = blockIdx.x * 128;
    const int wm = (wid & 1) * 64;
    const int wn = (wid >> 1) * 64;
    const int nchunk = K >> 4;

    wmma::fragment<wmma::accumulator, 16, 16, 16, float> acc[4][4];
#pragma unroll
    for (int mi = 0; mi < 4; ++mi)
#pragma unroll
        for (int ni = 0; ni < 4; ++ni) wmma::fill_fragment(acc[mi][ni], 0.0f);

    load_chunk_wmma(sbase, Ah, Al, Bh, Bl, m0, n0, 0, K, tid);
    CPA_COMMIT();

    for (int c = 0; c < nchunk; ++c) {
        const int p = c & 1;
        const __nv_bfloat16* s = (const __nv_bfloat16*)(smem + p * WSTAGE_B);
        const __nv_bfloat16* sah = s;
        const __nv_bfloat16* sal = s + WSTG_EL;
        const __nv_bfloat16* sbh = s + 2 * WSTG_EL;
        const __nv_bfloat16* sbl = s + 3 * WSTG_EL;

        CPA_WAIT0();
        __syncthreads();
        if (c + 1 < nchunk) {
            load_chunk_wmma(sbase + (p ^ 1) * WSTAGE_B, Ah, Al, Bh, Bl,
                            m0, n0, (c + 1) << 4, K, tid);
            CPA_COMMIT();
        }

        wmma::fragment<wmma::matrix_b, 16, 16, 16, __nv_bfloat16, wmma::col_major> fbh[4], fbl[4];
#pragma unroll
        for (int ni = 0; ni < 4; ++ni) {
            wmma::load_matrix_sync(fbh[ni], sbh + (wn + ni * 16) * WPAD, WPAD);
            wmma::load_matrix_sync(fbl[ni], sbl + (wn + ni * 16) * WPAD, WPAD);
        }
#pragma unroll
        for (int mi = 0; mi < 4; ++mi) {
            wmma::fragment<wmma::matrix_a, 16, 16, 16, __nv_bfloat16, wmma::row_major> fah, fal;
            wmma::load_matrix_sync(fah, sah + (wm + mi * 16) * WPAD, WPAD);
            wmma::load_matrix_sync(fal, sal + (wm + mi * 16) * WPAD, WPAD);
#pragma unroll
            for (int ni = 0; ni < 4; ++ni) {
                wmma::mma_sync(acc[mi][ni], fah, fbh[ni], acc[mi][ni]);
                wmma::mma_sync(acc[mi][ni], fah, fbl[ni], acc[mi][ni]);
                wmma::mma_sync(acc[mi][ni], fal, fbh[ni], acc[mi][ni]);
            }
        }
        __syncthreads();
    }

#pragma unroll
    for (int mi = 0; mi < 4; ++mi)
#pragma unroll
        for (int ni = 0; ni < 4; ++ni)
            wmma::store_matrix_sync(C + (size_t)(m0 + wm + mi * 16) * N + n0 + wn + ni * 16,
                                    acc[mi][ni], N, wmma::mem_row_major);
}

// ---------------- RoPE tables ----------------
__global__ void rope_table_kernel() {
    int idx = blockIdx.x * blockDim.x + threadIdx.x;
    if (idx >= SEQ * 64) return;
    int s = idx >> 6;
    int i = idx & 63;
    float th = powf(10000.0f, (float)i * (1.0f / 64.0f));
    float ph = (float)s / th;
    double phd = (double)ph;
    g_cos[idx] = (float)cos(phd);
    g_sin[idx] = (float)sin(phd);
}

// ---------------- RoPE + split: g_Q/g_K fp32 -> qh/ql, kh/kl bf16 ----------------
__global__ void rope_split_kernel() {
    int idx = blockIdx.x * blockDim.x + threadIdx.x;
    if (idx >= MROWS * (D_MODEL / 2)) return;
    int row = idx >> 10;
    int c2  = idx & 1023;
    int i   = c2 & 63;
    int s   = row & (SEQ - 1);
    float c  = g_cos[(s << 6) + i];
    float sn = g_sin[(s << 6) + i];
    size_t off = (size_t)row * (D_MODEL / 2) + c2;

    float2 q = ((float2*)g_Q)[off];
    float qa = q.x * c - q.y * sn;
    float qb = q.x * sn + q.y * c;
    __nv_bfloat16 qah = __float2bfloat16(qa), qbh = __float2bfloat16(qb);
    ((__nv_bfloat162*)g_qh)[off] = __halves2bfloat162(qah, qbh);
    ((__nv_bfloat162*)g_ql)[off] = __halves2bfloat162(
        __float2bfloat16(qa - __bfloat162float(qah)),
        __float2bfloat16(qb - __bfloat162float(qbh)));

    float2 k = ((float2*)g_K)[off];
    float ka = k.x * c - k.y * sn;
    float kb = k.x * sn + k.y * c;
    __nv_bfloat16 kah = __float2bfloat16(ka), kbh = __float2bfloat16(kb);
    ((__nv_bfloat162*)g_kh)[off] = __halves2bfloat162(kah, kbh);
    ((__nv_bfloat162*)g_kl)[off] = __halves2bfloat162(
        __float2bfloat16(ka - __bfloat162float(kah)),
        __float2bfloat16(kb - __bfloat162float(kbh)));
}

// ============================================================================
// Tensor-core causal flash attention (mma.sync m16n8k16 bf16, split precision)
// CTA: 64 q rows x one (b,h); 4 warps x 16 rows; k-tiles of 64, double-buffered.
// ============================================================================
#define FPITCH 272                       /* bytes per tile row (136 bf16) */
#define FTILE  (64 * FPITCH)             /* 17408 bytes per matrix tile */
#define FQ_OFF 0                         /* qh, ql */
#define FS_OFF (2 * FTILE)               /* stages: kh,kl,vh,vl each FTILE */
#define FSTAGE (4 * FTILE)
#define SMEM_FLASH (2 * FTILE + 2 * FSTAGE)   /* 174080 */

__device__ __forceinline__ void flash_load_kv(uint32_t sdst, int brow0, int hcol,
                                              int tid) {
    const __nv_bfloat16* srcs[4];
    srcs[0] = g_kh; srcs[1] = g_kl; srcs[2] = g_vh; srcs[3] = g_vl;
#pragma unroll
    for (int t = 0; t < 32; ++t) {
        int u = t * 128 + tid;           // 0..4095: 4 tiles x 64 rows x 16 chunks
        int mtx = u >> 10;
        int rem = u & 1023;
        int row = rem >> 4;
        int c16 = rem & 15;
        cpa16(sdst + mtx * FTILE + row * FPITCH + c16 * 16,
              srcs[mtx] + (size_t)(brow0 + row) * D_MODEL + hcol + c16 * 8);
    }
}

__global__ void __launch_bounds__(128) flash_tc() {
    extern __shared__ char smem[];
    const uint32_t sbase = su32(smem);
    const int tid  = threadIdx.x;
    const int wid  = tid >> 5;
    const int lane = tid & 31;
    const int qb   = (int)gridDim.x - 1 - (int)blockIdx.x;  // big tiles first
    const int h    = blockIdx.y;
    const int b    = blockIdx.z;
    const int hcol = h * DK;
    const int brow0q = b * SEQ + qb * 64;
    const int group = lane >> 2;
    const int tig   = lane & 3;
    const int qg0   = qb * 64 + wid * 16 + group;   // this thread's row 0 (row1 = +8)

    const float SCL2 = 0.08838834764831845f * 1.4426950408889634f;

    // ---- load Q tiles (qh, ql) ----
    {
        const __nv_bfloat16* qsrc[2];
        qsrc[0] = g_qh; qsrc[1] = g_ql;
#pragma unroll
        for (int t = 0; t < 16; ++t) {
            int u = t * 128 + tid;       // 0..2047
            int mtx = u >> 10;
            int rem = u & 1023;
            int row = rem >> 4;
            int c16 = rem & 15;
            cpa16(sbase + FQ_OFF + mtx * FTILE + row * FPITCH + c16 * 16,
                  qsrc[mtx] + (size_t)(brow0q + row) * D_MODEL + hcol + c16 * 8);
        }
    }
    flash_load_kv(sbase + FS_OFF, b * SEQ, hcol, tid);
    CPA_COMMIT();
    CPA_WAIT0();
    __syncthreads();

    float oacc[16][4];
#pragma unroll
    for (int f = 0; f < 16; ++f) {
        oacc[f][0] = 0.f; oacc[f][1] = 0.f; oacc[f][2] = 0.f; oacc[f][3] = 0.f;
    }
    float m2[2] = {-1e30f, -1e30f};
    float lsum[2] = {0.f, 0.f};

    const int nt = qb + 1;
    const uint32_t qrow_base = sbase + FQ_OFF + (wid * 16 + (lane & 15)) * FPITCH
                             + (lane >> 4) * 16;

    for (int t = 0; t < nt; ++t) {
        const uint32_t stg = sbase + FS_OFF + (t & 1) * FSTAGE;
        if (t + 1 < nt) {
            flash_load_kv(sbase + FS_OFF + ((t + 1) & 1) * FSTAGE,
                          b * SEQ + (t + 1) * 64, hcol, tid);
            CPA_COMMIT();
        }

        // ---- S = Qh*Kh' + Qh*Kl' + Ql*Kh' ----
        float sacc[8][4];
#pragma unroll
        for (int f = 0; f < 8; ++f) {
            sacc[f][0] = 0.f; sacc[f][1] = 0.f; sacc[f][2] = 0.f; sacc[f][3] = 0.f;
        }
        const uint32_t krow = stg + (lane & 15) * FPITCH + (lane >> 4) * 16;
#pragma unroll
        for (int kc = 0; kc < 8; ++kc) {
            uint32_t qa0, qa1, qa2, qa3, ql0, ql1, ql2, ql3;
            LDSM4(qa0, qa1, qa2, qa3, qrow_base + kc * 32);
            LDSM4(ql0, ql1, ql2, ql3, qrow_base + FTILE + kc * 32);
#pragma unroll
            for (int nf2 = 0; nf2 < 4; ++nf2) {
                uint32_t kh0, kh1, kh2, kh3, kl0, kl1, kl2, kl3;
                uint32_t ka = krow + nf2 * (16 * FPITCH) + kc * 32;
                LDSM4(kh0, kh1, kh2, kh3, ka);
                LDSM4(kl0, kl1, kl2, kl3, ka + FTILE);
                MMA16816(sacc[2 * nf2],     qa0, qa1, qa2, qa3, kh0, kh2);
                MMA16816(sacc[2 * nf2 + 1], qa0, qa1, qa2, qa3, kh1, kh3);
                MMA16816(sacc[2 * nf2],     qa0, qa1, qa2, qa3, kl0, kl2);
                MMA16816(sacc[2 * nf2 + 1], qa0, qa1, qa2, qa3, kl1, kl3);
                MMA16816(sacc[2 * nf2],     ql0, ql1, ql2, ql3, kh0, kh2);
                MMA16816(sacc[2 * nf2 + 1], ql0, ql1, ql2, ql3, kh1, kh3);
            }
        }

        // ---- scale + causal mask (diagonal tile only) ----
#pragma unroll
        for (int f = 0; f < 8; ++f) {
            sacc[f][0] *= SCL2; sacc[f][1] *= SCL2;
            sacc[f][2] *= SCL2; sacc[f][3] *= SCL2;
        }
        if (t == qb) {
            const int j0 = t * 64;
#pragma unroll
            for (int f = 0; f < 8; ++f) {
                int col = j0 + f * 8 + tig * 2;
                if (col > qg0)          sacc[f][0] = -1e30f;
                if (col + 1 > qg0)      sacc[f][1] = -1e30f;
                if (col > qg0 + 8)      sacc[f][2] = -1e30f;
                if (col + 1 > qg0 + 8)  sacc[f][3] = -1e30f;
            }
        }

        // ---- online softmax (rows group, group+8 owned by quad) ----
        float mn0 = -1e30f, mn1 = -1e30f;
#pragma unroll
        for (int f = 0; f < 8; ++f) {
            mn0 = fmaxf(mn0, fmaxf(sacc[f][0], sacc[f][1]));
            mn1 = fmaxf(mn1, fmaxf(sacc[f][2], sacc[f][3]));
        }
        mn0 = fmaxf(mn0, __shfl_xor_sync(0xffffffffu, mn0, 1));
        mn0 = fmaxf(mn0, __shfl_xor_sync(0xffffffffu, mn0, 2));
        mn1 = fmaxf(mn1, __shfl_xor_sync(0xffffffffu, mn1, 1));
        mn1 = fmaxf(mn1, __shfl_xor_sync(0xffffffffu, mn1, 2));
        float mN0 = fmaxf(m2[0], mn0), mN1 = fmaxf(m2[1], mn1);
        float corr0 = exp2ff(m2[0] - mN0), corr1 = exp2ff(m2[1] - mN1);
        m2[0] = mN0; m2[1] = mN1;

        float ls0 = 0.f, ls1 = 0.f;
#pragma unroll
        for (int f = 0; f < 8; ++f) {
            sacc[f][0] = exp2ff(sacc[f][0] - mN0);
            sacc[f][1] = exp2ff(sacc[f][1] - mN0);
            sacc[f][2] = exp2ff(sacc[f][2] - mN1);
            sacc[f][3] = exp2ff(sacc[f][3] - mN1);
            ls0 += sacc[f][0] + sacc[f][1];
            ls1 += sacc[f][2] + sacc[f][3];
        }
        ls0 += __shfl_xor_sync(0xffffffffu, ls0, 1);
        ls0 += __shfl_xor_sync(0xffffffffu, ls0, 2);
        ls1 += __shfl_xor_sync(0xffffffffu, ls1, 1);
        ls1 += __shfl_xor_sync(0xffffffffu, ls1, 2);
        lsum[0] = lsum[0] * corr0 + ls0;
        lsum[1] = lsum[1] * corr1 + ls1;

#pragma unroll
        for (int f = 0; f < 16; ++f) {
            oacc[f][0] *= corr0; oacc[f][1] *= corr0;
            oacc[f][2] *= corr1; oacc[f][3] *= corr1;
        }

        // ---- P -> A frags (hi + residual lo) ----
        uint32_t pah[4][4], pal[4][4];
#pragma unroll
        for (int kc = 0; kc < 4; ++kc) {
            const int f0 = 2 * kc, f1 = 2 * kc + 1;
            pah[kc][0] = packbf(sacc[f0][0], sacc[f0][1]);
            pah[kc][1] = packbf(sacc[f0][2], sacc[f0][3]);
            pah[kc][2] = packbf(sacc[f1][0], sacc[f1][1]);
            pah[kc][3] = packbf(sacc[f1][2], sacc[f1][3]);
#pragma unroll
            for (int e = 0; e < 4; ++e) {
                const int ff = (e < 2) ? f0 : f1;
                const int i0 = (e & 1) * 2;
                float r0 = sacc[ff][i0]     - __bfloat162float(__float2bfloat16(sacc[ff][i0]));
                float r1 = sacc[ff][i0 + 1] - __bfloat162float(__float2bfloat16(sacc[ff][i0 + 1]));
                pal[kc][e] = packbf(r0, r1);
            }
        }

        // ---- O += Ph*Vh + Ph*Vl + Pl*Vh ----
        const uint32_t vrow = stg + 2 * FTILE
                            + ((lane & 7) + ((lane >> 3) & 1) * 8) * FPITCH
                            + ((lane >> 4) & 1) * 16;
#pragma unroll
        for (int kc = 0; kc < 4; ++kc) {
#pragma unroll
            for (int nf2 = 0; nf2 < 8; ++nf2) {
                uint32_t va = vrow + kc * (16 * FPITCH) + nf2 * 32;
                uint32_t v0, v1, v2, v3, u0, u1, u2, u3;
                LDSM4T(v0, v1, v2, v3, va);
                LDSM4T(u0, u1, u2, u3, va + FTILE);
                MMA16816(oacc[2 * nf2],     pah[kc][0], pah[kc][1], pah[kc][2], pah[kc][3], v0, v1);
                MMA16816(oacc[2 * nf2 + 1], pah[kc][0], pah[kc][1], pah[kc][2], pah[kc][3], v2, v3);
                MMA16816(oacc[2 * nf2],     pah[kc][0], pah[kc][1], pah[kc][2], pah[kc][3], u0, u1);
                MMA16816(oacc[2 * nf2 + 1], pah[kc][0], pah[kc][1], pah[kc][2], pah[kc][3], u2, u3);
                MMA16816(oacc[2 * nf2],     pal[kc][0], pal[kc][1], pal[kc][2], pal[kc][3], v0, v1);
                MMA16816(oacc[2 * nf2 + 1], pal[kc][0], pal[kc][1], pal[kc][2], pal[kc][3], v2, v3);
            }
        }

        CPA_WAIT0();
        __syncthreads();
    }

    // ---- epilogue: O / l -> g_attn ----
    const float inv0 = 1.0f / lsum[0];
    const float inv1 = 1.0f / lsum[1];
    float* out0 = g_attn + (size_t)(brow0q + wid * 16 + group) * D_MODEL + hcol;
    float* out1 = out0 + (size_t)8 * D_MODEL;
#pragma unroll
    for (int f = 0; f < 16; ++f) {
        const int col = f * 8 + tig * 2;
        *(float2*)(out0 + col) = make_float2(oacc[f][0] * inv0, oacc[f][1] * inv0);
        *(float2*)(out1 + col) = make_float2(oacc[f][2] * inv1, oacc[f][3] * inv1);
    }
}

// ---------------- launch ----------------
extern "C" void kernel_launch(void* const* d_in, const int* in_sizes, int n_in,
                              void* d_out, int out_size) {
    const float* x  = (const float*)d_in[0];
    const float* Wq = (const float*)d_in[2];
    const float* Wk = (const float*)d_in[3];
    const float* Wv = (const float*)d_in[4];
    const float* Wo = (const float*)d_in[5];
    float* out = (float*)d_out;

    float *pQ, *pK, *pV, *pA;
    cudaGetSymbolAddress((void**)&pQ, g_Q);
    cudaGetSymbolAddress((void**)&pK, g_K);
    cudaGetSymbolAddress((void**)&pV, g_V);
    cudaGetSymbolAddress((void**)&pA, g_attn);
    __nv_bfloat16 *xh, *xl, *wqh, *wql, *wkh, *wkl, *wvh, *wvl, *woh, *wol, *ah, *al, *vh, *vl;
    cudaGetSymbolAddress((void**)&xh, g_xh);   cudaGetSymbolAddress((void**)&xl, g_xl);
    cudaGetSymbolAddress((void**)&wqh, g_wqh); cudaGetSymbolAddress((void**)&wql, g_wql);
    cudaGetSymbolAddress((void**)&wkh, g_wkh); cudaGetSymbolAddress((void**)&wkl, g_wkl);
    cudaGetSymbolAddress((void**)&wvh, g_wvh); cudaGetSymbolAddress((void**)&wvl, g_wvl);
    cudaGetSymbolAddress((void**)&woh, g_woh); cudaGetSymbolAddress((void**)&wol, g_wol);
    cudaGetSymbolAddress((void**)&ah, g_ah);   cudaGetSymbolAddress((void**)&al, g_al);
    cudaGetSymbolAddress((void**)&vh, g_vh);   cudaGetSymbolAddress((void**)&vl, g_vl);

    cudaFuncSetAttribute(gemm_wmma, cudaFuncAttributeMaxDynamicSharedMemorySize, SMEM_WMMA);
    cudaFuncSetAttribute(flash_tc, cudaFuncAttributeMaxDynamicSharedMemorySize, SMEM_FLASH);

    rope_table_kernel<<<(SEQ * 64 + 255) / 256, 256>>>();

    const int nx4 = MROWS * D_MODEL / 4;
    const int nw4 = D_MODEL * D_MODEL / 4;
    split_kernel<<<(nx4 + 255) / 256, 256>>>(x, xh, xl, nx4);
    split_kernel<<<(nw4 + 255) / 256, 256>>>(Wq, wqh, wql, nw4);
    split_kernel<<<(nw4 + 255) / 256, 256>>>(Wk, wkh, wkl, nw4);
    split_kernel<<<(nw4 + 255) / 256, 256>>>(Wv, wvh, wvl, nw4);
    split_kernel<<<(nw4 + 255) / 256, 256>>>(Wo, woh, wol, nw4);

    dim3 gg(D_MODEL / 128, MROWS / 128);   // (16, 32)
    gemm_wmma<<<gg, 128, SMEM_WMMA>>>(xh, xl, wqh, wql, pQ, D_MODEL, D_MODEL);
    gemm_wmma<<<gg, 128, SMEM_WMMA>>>(xh, xl, wkh, wkl, pK, D_MODEL, D_MODEL);
    gemm_wmma<<<gg, 128, SMEM_WMMA>>>(xh, xl, wvh, wvl, pV, D_MODEL, D_MODEL);

    rope_split_kernel<<<(MROWS * (D_MODEL / 2) + 255) / 256, 256>>>();
    split_kernel<<<(nx4 + 255) / 256, 256>>>(pV, vh, vl, nx4);

    flash_tc<<<dim3(SEQ / 64, NHEADS, BATCH), 128, SMEM_FLASH>>>();

    split_kernel<<<(nx4 + 255) / 256, 256>>>(pA, ah, al, nx4);
    gemm_wmma<<<gg, 128, SMEM_WMMA>>>(ah, al, woh, wol, out, D_MODEL, D_MODEL);
}

// round 6
// speedup vs baseline: 2.6838x; 1.0211x over previous
#include <cuda_runtime.h>
#include <cuda_bf16.h>
#include <mma.h>
#include <cstdint>
#include <math.h>

using namespace nvcuda;

#define D_MODEL 2048
#define SEQ     2048
#define BATCH   2
#define NHEADS  16
#define DK      128
#define MROWS   (BATCH*SEQ)   /* 4096 */

// ---------------- scratch (device globals; no allocs allowed) ----------------
__device__ float g_Q[(size_t)MROWS * D_MODEL];
__device__ float g_K[(size_t)MROWS * D_MODEL];
__device__ float g_V[(size_t)MROWS * D_MODEL];
__device__ float g_attn[(size_t)MROWS * D_MODEL];
__device__ float g_cos[SEQ * (DK / 2)];
__device__ float g_sin[SEQ * (DK / 2)];

// bf16 hi/lo splits (GEMM operands)
__device__ __nv_bfloat16 g_xh[(size_t)MROWS * D_MODEL];
__device__ __nv_bfloat16 g_xl[(size_t)MROWS * D_MODEL];
__device__ __nv_bfloat16 g_wqh[(size_t)D_MODEL * D_MODEL];
__device__ __nv_bfloat16 g_wql[(size_t)D_MODEL * D_MODEL];
__device__ __nv_bfloat16 g_wkh[(size_t)D_MODEL * D_MODEL];
__device__ __nv_bfloat16 g_wkl[(size_t)D_MODEL * D_MODEL];
__device__ __nv_bfloat16 g_wvh[(size_t)D_MODEL * D_MODEL];
__device__ __nv_bfloat16 g_wvl[(size_t)D_MODEL * D_MODEL];
__device__ __nv_bfloat16 g_woh[(size_t)D_MODEL * D_MODEL];
__device__ __nv_bfloat16 g_wol[(size_t)D_MODEL * D_MODEL];
__device__ __nv_bfloat16 g_ah[(size_t)MROWS * D_MODEL];
__device__ __nv_bfloat16 g_al[(size_t)MROWS * D_MODEL];

// flash operands: rope'd Q/K and V, hi/lo bf16
__device__ __nv_bfloat16 g_qh[(size_t)MROWS * D_MODEL];
__device__ __nv_bfloat16 g_ql[(size_t)MROWS * D_MODEL];
__device__ __nv_bfloat16 g_kh[(size_t)MROWS * D_MODEL];
__device__ __nv_bfloat16 g_kl[(size_t)MROWS * D_MODEL];
__device__ __nv_bfloat16 g_vh[(size_t)MROWS * D_MODEL];
__device__ __nv_bfloat16 g_vl[(size_t)MROWS * D_MODEL];

// ---------------- generic PTX helpers (base-arch safe) ----------------
__device__ __forceinline__ void cpa16(uint32_t dst, const void* src) {
    asm volatile("cp.async.cg.shared.global [%0], [%1], 16;" :: "r"(dst), "l"(src));
}
#define CPA_COMMIT() asm volatile("cp.async.commit_group;" ::: "memory")
#define CPA_WAIT0()  asm volatile("cp.async.wait_group 0;" ::: "memory")

__device__ __forceinline__ uint32_t su32(const void* p) {
    uint32_t a;
    asm("{ .reg .u64 t; cvta.to.shared.u64 t, %1; cvt.u32.u64 %0, t; }" : "=r"(a) : "l"(p));
    return a;
}

#define LDSM4(r0, r1, r2, r3, a) \
    asm volatile("ldmatrix.sync.aligned.m8n8.x4.shared.b16 {%0,%1,%2,%3}, [%4];" \
                 : "=r"(r0), "=r"(r1), "=r"(r2), "=r"(r3) : "r"(a))
#define LDSM4T(r0, r1, r2, r3, a) \
    asm volatile("ldmatrix.sync.aligned.m8n8.x4.trans.shared.b16 {%0,%1,%2,%3}, [%4];" \
                 : "=r"(r0), "=r"(r1), "=r"(r2), "=r"(r3) : "r"(a))
#define MMA16816(d, a0, a1, a2, a3, b0, b1) \
    asm volatile("mma.sync.aligned.m16n8k16.row.col.f32.bf16.bf16.f32 " \
                 "{%0,%1,%2,%3}, {%4,%5,%6,%7}, {%8,%9}, {%0,%1,%2,%3};" \
                 : "+f"((d)[0]), "+f"((d)[1]), "+f"((d)[2]), "+f"((d)[3]) \
                 : "r"(a0), "r"(a1), "r"(a2), "r"(a3), "r"(b0), "r"(b1))

// pack two floats -> bf16x2 reg (lo first)
__device__ __forceinline__ uint32_t packbf(float lo, float hi) {
    uint32_t u;
    asm("cvt.rn.bf16x2.f32 %0, %1, %2;" : "=r"(u) : "f"(hi), "f"(lo));
    return u;
}

// fast exp2 on FMA pipe (arg <= 0), rel err ~1.5e-5
__device__ __forceinline__ float exp2ff(float x) {
    x = fmaxf(x, -126.0f);
    float fl = floorf(x);
    float f = x - fl;
    float p = 1.54035304e-4f;
    p = fmaf(p, f, 1.33335581e-3f);
    p = fmaf(p, f, 9.61812910e-3f);
    p = fmaf(p, f, 5.55041086e-2f);
    p = fmaf(p, f, 2.40226512e-1f);
    p = fmaf(p, f, 6.93147182e-1f);
    p = fmaf(p, f, 1.0f);
    return __uint_as_float((uint32_t)((int)fl + 127) << 23) * p;
}

// ---------------- split fp32 -> bf16 hi/lo ----------------
__global__ void split_kernel(const float* __restrict__ src,
                             __nv_bfloat16* __restrict__ hi,
                             __nv_bfloat16* __restrict__ lo, int n4) {
    int i = blockIdx.x * blockDim.x + threadIdx.x;
    if (i >= n4) return;
    float4 v = ((const float4*)src)[i];
    __nv_bfloat16 h0 = __float2bfloat16(v.x);
    __nv_bfloat16 h1 = __float2bfloat16(v.y);
    __nv_bfloat16 h2 = __float2bfloat16(v.z);
    __nv_bfloat16 h3 = __float2bfloat16(v.w);
    __nv_bfloat16 l0 = __float2bfloat16(v.x - __bfloat162float(h0));
    __nv_bfloat16 l1 = __float2bfloat16(v.y - __bfloat162float(h1));
    __nv_bfloat16 l2 = __float2bfloat16(v.z - __bfloat162float(h2));
    __nv_bfloat16 l3 = __float2bfloat16(v.w - __bfloat162float(h3));
    uint2 hp, lp;
    hp.x = (uint32_t)__bfloat16_as_ushort(h0) | ((uint32_t)__bfloat16_as_ushort(h1) << 16);
    hp.y = (uint32_t)__bfloat16_as_ushort(h2) | ((uint32_t)__bfloat16_as_ushort(h3) << 16);
    lp.x = (uint32_t)__bfloat16_as_ushort(l0) | ((uint32_t)__bfloat16_as_ushort(l1) << 16);
    lp.y = (uint32_t)__bfloat16_as_ushort(l2) | ((uint32_t)__bfloat16_as_ushort(l3) << 16);
    ((uint2*)hi)[i] = hp;
    ((uint2*)lo)[i] = lp;
}

// ============================================================================
// wmma bf16 GEMM (proven path): CTA 128x128, 4 warps, AhBh + AhBl + AlBh.
// ============================================================================
#define WPAD       24
#define WSTG_EL    (128 * WPAD)
#define WSTAGE_B   (4 * WSTG_EL * 2)
#define SMEM_WMMA  (2 * WSTAGE_B)

__device__ __forceinline__ void load_chunk_wmma(
    uint32_t sdst, const __nv_bfloat16* __restrict__ Ah, const __nv_bfloat16* __restrict__ Al,
    const __nv_bfloat16* __restrict__ Bh, const __nv_bfloat16* __restrict__ Bl,
    int m0, int n0, int k0, int K, int tid) {
    const __nv_bfloat16* srcs[4] = {Ah, Al, Bh, Bl};
#pragma unroll
    for (int t = 0; t < 8; ++t) {
        int u = t * 128 + tid;
        int mtx = u >> 8;
        int rem = u & 255;
        int row = rem >> 1;
        int c16 = rem & 1;
        int gr = (mtx < 2 ? m0 : n0) + row;
        uint32_t doff = (uint32_t)mtx * (WSTG_EL * 2) + row * (WPAD * 2) + c16 * 16;
        cpa16(sdst + doff, srcs[mtx] + (size_t)gr * K + k0 + c16 * 8);
    }
}

__global__ void __launch_bounds__(128) gemm_wmma(
    const __nv_bfloat16* __restrict__ Ah, const __nv_bfloat16* __restrict__ Al,
    const __nv_bfloat16* __restrict__ Bh, const __nv_bfloat16* __restrict__ Bl,
    float* __restrict__ C, int N, int K) {
    extern __shared__ char smem[];
    const uint32_t sbase = su32(smem);
    const int tid = threadIdx.x;
    const int wid = tid >> 5;
    const int m0 = blockIdx.y * 128;
    const int n0 = blockIdx.x * 128;
    const int wm = (wid & 1) * 64;
    const int wn = (wid >> 1) * 64;
    const int nchunk = K >> 4;

    wmma::fragment<wmma::accumulator, 16, 16, 16, float> acc[4][4];
#pragma unroll
    for (int mi = 0; mi < 4; ++mi)
#pragma unroll
        for (int ni = 0; ni < 4; ++ni) wmma::fill_fragment(acc[mi][ni], 0.0f);

    load_chunk_wmma(sbase, Ah, Al, Bh, Bl, m0, n0, 0, K, tid);
    CPA_COMMIT();

    for (int c = 0; c < nchunk; ++c) {
        const int p = c & 1;
        const __nv_bfloat16* s = (const __nv_bfloat16*)(smem + p * WSTAGE_B);
        const __nv_bfloat16* sah = s;
        const __nv_bfloat16* sal = s + WSTG_EL;
        const __nv_bfloat16* sbh = s + 2 * WSTG_EL;
        const __nv_bfloat16* sbl = s + 3 * WSTG_EL;

        CPA_WAIT0();
        __syncthreads();
        if (c + 1 < nchunk) {
            load_chunk_wmma(sbase + (p ^ 1) * WSTAGE_B, Ah, Al, Bh, Bl,
                            m0, n0, (c + 1) << 4, K, tid);
            CPA_COMMIT();
        }

        wmma::fragment<wmma::matrix_b, 16, 16, 16, __nv_bfloat16, wmma::col_major> fbh[4], fbl[4];
#pragma unroll
        for (int ni = 0; ni < 4; ++ni) {
            wmma::load_matrix_sync(fbh[ni], sbh + (wn + ni * 16) * WPAD, WPAD);
            wmma::load_matrix_sync(fbl[ni], sbl + (wn + ni * 16) * WPAD, WPAD);
        }
#pragma unroll
        for (int mi = 0; mi < 4; ++mi) {
            wmma::fragment<wmma::matrix_a, 16, 16, 16, __nv_bfloat16, wmma::row_major> fah, fal;
            wmma::load_matrix_sync(fah, sah + (wm + mi * 16) * WPAD, WPAD);
            wmma::load_matrix_sync(fal, sal + (wm + mi * 16) * WPAD, WPAD);
#pragma unroll
            for (int ni = 0; ni < 4; ++ni) {
                wmma::mma_sync(acc[mi][ni], fah, fbh[ni], acc[mi][ni]);
                wmma::mma_sync(acc[mi][ni], fah, fbl[ni], acc[mi][ni]);
                wmma::mma_sync(acc[mi][ni], fal, fbh[ni], acc[mi][ni]);
            }
        }
        __syncthreads();
    }

#pragma unroll
    for (int mi = 0; mi < 4; ++mi)
#pragma unroll
        for (int ni = 0; ni < 4; ++ni)
            wmma::store_matrix_sync(C + (size_t)(m0 + wm + mi * 16) * N + n0 + wn + ni * 16,
                                    acc[mi][ni], N, wmma::mem_row_major);
}

// ---------------- RoPE tables ----------------
__global__ void rope_table_kernel() {
    int idx = blockIdx.x * blockDim.x + threadIdx.x;
    if (idx >= SEQ * 64) return;
    int s = idx >> 6;
    int i = idx & 63;
    float th = powf(10000.0f, (float)i * (1.0f / 64.0f));
    float ph = (float)s / th;
    double phd = (double)ph;
    g_cos[idx] = (float)cos(phd);
    g_sin[idx] = (float)sin(phd);
}

// ---------------- RoPE + split: g_Q/g_K fp32 -> qh/ql, kh/kl bf16 ----------------
__global__ void rope_split_kernel() {
    int idx = blockIdx.x * blockDim.x + threadIdx.x;
    if (idx >= MROWS * (D_MODEL / 2)) return;
    int row = idx >> 10;
    int c2  = idx & 1023;
    int i   = c2 & 63;
    int s   = row & (SEQ - 1);
    float c  = g_cos[(s << 6) + i];
    float sn = g_sin[(s << 6) + i];
    size_t off = (size_t)row * (D_MODEL / 2) + c2;

    float2 q = ((float2*)g_Q)[off];
    float qa = q.x * c - q.y * sn;
    float qb = q.x * sn + q.y * c;
    __nv_bfloat16 qah = __float2bfloat16(qa), qbh = __float2bfloat16(qb);
    ((__nv_bfloat162*)g_qh)[off] = __halves2bfloat162(qah, qbh);
    ((__nv_bfloat162*)g_ql)[off] = __halves2bfloat162(
        __float2bfloat16(qa - __bfloat162float(qah)),
        __float2bfloat16(qb - __bfloat162float(qbh)));

    float2 k = ((float2*)g_K)[off];
    float ka = k.x * c - k.y * sn;
    float kb = k.x * sn + k.y * c;
    __nv_bfloat16 kah = __float2bfloat16(ka), kbh = __float2bfloat16(kb);
    ((__nv_bfloat162*)g_kh)[off] = __halves2bfloat162(kah, kbh);
    ((__nv_bfloat162*)g_kl)[off] = __halves2bfloat162(
        __float2bfloat16(ka - __bfloat162float(kah)),
        __float2bfloat16(kb - __bfloat162float(kbh)));
}

// ============================================================================
// Tensor-core causal flash attention (mma.sync m16n8k16 bf16, split precision)
// CTA: 128 q rows x one (b,h); 8 warps x 16 rows; kv-tiles of 64, double-buffered.
// ============================================================================
#define FPITCH 272                       /* bytes per tile row (136 bf16) */
#define FQT    (128 * FPITCH)            /* 34816: q tile (128 rows) */
#define FKT    (64 * FPITCH)             /* 17408: kv tile (64 rows) */
#define FS_OFF (2 * FQT)                 /* stages: kh,kl,vh,vl each FKT */
#define FSTAGE (4 * FKT)
#define SMEM_FLASH (2 * FQT + 2 * FSTAGE)   /* 208896 */

__device__ __forceinline__ void flash_load_kv(uint32_t sdst, int brow0, int hcol,
                                              int tid) {
    const __nv_bfloat16* srcs[4];
    srcs[0] = g_kh; srcs[1] = g_kl; srcs[2] = g_vh; srcs[3] = g_vl;
#pragma unroll
    for (int t = 0; t < 16; ++t) {
        int u = t * 256 + tid;           // 0..4095: 4 tiles x 64 rows x 16 chunks
        int mtx = u >> 10;
        int rem = u & 1023;
        int row = rem >> 4;
        int c16 = rem & 15;
        cpa16(sdst + mtx * FKT + row * FPITCH + c16 * 16,
              srcs[mtx] + (size_t)(brow0 + row) * D_MODEL + hcol + c16 * 8);
    }
}

__global__ void __launch_bounds__(256) flash_tc() {
    extern __shared__ char smem[];
    const uint32_t sbase = su32(smem);
    const int tid  = threadIdx.x;
    const int wid  = tid >> 5;
    const int lane = tid & 31;
    const int qb   = (int)gridDim.x - 1 - (int)blockIdx.x;  // big tiles first
    const int h    = blockIdx.y;
    const int b    = blockIdx.z;
    const int hcol = h * DK;
    const int brow0q = b * SEQ + qb * 128;
    const int group = lane >> 2;
    const int tig   = lane & 3;
    const int qg0   = qb * 128 + wid * 16 + group;  // this thread's row 0 (row1 = +8)

    const float SCL2 = 0.08838834764831845f * 1.4426950408889634f;

    // ---- load Q tiles (qh, ql): 2 x 128 rows x 16 chunks = 4096 cp.async ----
    {
        const __nv_bfloat16* qsrc[2];
        qsrc[0] = g_qh; qsrc[1] = g_ql;
#pragma unroll
        for (int t = 0; t < 16; ++t) {
            int u = t * 256 + tid;
            int mtx = u >> 11;
            int rem = u & 2047;
            int row = rem >> 4;
            int c16 = rem & 15;
            cpa16(sbase + mtx * FQT + row * FPITCH + c16 * 16,
                  qsrc[mtx] + (size_t)(brow0q + row) * D_MODEL + hcol + c16 * 8);
        }
    }
    flash_load_kv(sbase + FS_OFF, b * SEQ, hcol, tid);
    CPA_COMMIT();
    CPA_WAIT0();
    __syncthreads();

    float oacc[16][4];
#pragma unroll
    for (int f = 0; f < 16; ++f) {
        oacc[f][0] = 0.f; oacc[f][1] = 0.f; oacc[f][2] = 0.f; oacc[f][3] = 0.f;
    }
    float m2[2] = {-1e30f, -1e30f};
    float lsum[2] = {0.f, 0.f};

    const int nt = 2 * qb + 2;
    const uint32_t qrow_base = sbase + (wid * 16 + (lane & 15)) * FPITCH
                             + (lane >> 4) * 16;

    for (int t = 0; t < nt; ++t) {
        const uint32_t stg = sbase + FS_OFF + (t & 1) * FSTAGE;
        if (t + 1 < nt) {
            flash_load_kv(sbase + FS_OFF + ((t + 1) & 1) * FSTAGE,
                          b * SEQ + (t + 1) * 64, hcol, tid);
            CPA_COMMIT();
        }

        // ---- S = Qh*Kh' + Qh*Kl' + Ql*Kh' ----
        float sacc[8][4];
#pragma unroll
        for (int f = 0; f < 8; ++f) {
            sacc[f][0] = 0.f; sacc[f][1] = 0.f; sacc[f][2] = 0.f; sacc[f][3] = 0.f;
        }
        const uint32_t krow = stg + (lane & 15) * FPITCH + (lane >> 4) * 16;
#pragma unroll
        for (int kc = 0; kc < 8; ++kc) {
            uint32_t qa0, qa1, qa2, qa3, ql0, ql1, ql2, ql3;
            LDSM4(qa0, qa1, qa2, qa3, qrow_base + kc * 32);
            LDSM4(ql0, ql1, ql2, ql3, qrow_base + FQT + kc * 32);
#pragma unroll
            for (int nf2 = 0; nf2 < 4; ++nf2) {
                uint32_t kh0, kh1, kh2, kh3, kl0, kl1, kl2, kl3;
                uint32_t ka = krow + nf2 * (16 * FPITCH) + kc * 32;
                LDSM4(kh0, kh1, kh2, kh3, ka);
                LDSM4(kl0, kl1, kl2, kl3, ka + FKT);
                MMA16816(sacc[2 * nf2],     qa0, qa1, qa2, qa3, kh0, kh2);
                MMA16816(sacc[2 * nf2 + 1], qa0, qa1, qa2, qa3, kh1, kh3);
                MMA16816(sacc[2 * nf2],     qa0, qa1, qa2, qa3, kl0, kl2);
                MMA16816(sacc[2 * nf2 + 1], qa0, qa1, qa2, qa3, kl1, kl3);
                MMA16816(sacc[2 * nf2],     ql0, ql1, ql2, ql3, kh0, kh2);
                MMA16816(sacc[2 * nf2 + 1], ql0, ql1, ql2, ql3, kh1, kh3);
            }
        }

        // ---- scale + causal mask (tiles straddling/past this thread's rows) ----
#pragma unroll
        for (int f = 0; f < 8; ++f) {
            sacc[f][0] *= SCL2; sacc[f][1] *= SCL2;
            sacc[f][2] *= SCL2; sacc[f][3] *= SCL2;
        }
        if (t * 64 + 63 > qg0) {
            const int j0 = t * 64;
#pragma unroll
            for (int f = 0; f < 8; ++f) {
                int col = j0 + f * 8 + tig * 2;
                if (col > qg0)          sacc[f][0] = -1e30f;
                if (col + 1 > qg0)      sacc[f][1] = -1e30f;
                if (col > qg0 + 8)      sacc[f][2] = -1e30f;
                if (col + 1 > qg0 + 8)  sacc[f][3] = -1e30f;
            }
        }

        // ---- online softmax (rows group, group+8 owned by quad) ----
        float mn0 = -1e30f, mn1 = -1e30f;
#pragma unroll
        for (int f = 0; f < 8; ++f) {
            mn0 = fmaxf(mn0, fmaxf(sacc[f][0], sacc[f][1]));
            mn1 = fmaxf(mn1, fmaxf(sacc[f][2], sacc[f][3]));
        }
        mn0 = fmaxf(mn0, __shfl_xor_sync(0xffffffffu, mn0, 1));
        mn0 = fmaxf(mn0, __shfl_xor_sync(0xffffffffu, mn0, 2));
        mn1 = fmaxf(mn1, __shfl_xor_sync(0xffffffffu, mn1, 1));
        mn1 = fmaxf(mn1, __shfl_xor_sync(0xffffffffu, mn1, 2));
        float mN0 = fmaxf(m2[0], mn0), mN1 = fmaxf(m2[1], mn1);
        float corr0 = exp2ff(m2[0] - mN0), corr1 = exp2ff(m2[1] - mN1);
        m2[0] = mN0; m2[1] = mN1;

        float ls0 = 0.f, ls1 = 0.f;
#pragma unroll
        for (int f = 0; f < 8; ++f) {
            sacc[f][0] = exp2ff(sacc[f][0] - mN0);
            sacc[f][1] = exp2ff(sacc[f][1] - mN0);
            sacc[f][2] = exp2ff(sacc[f][2] - mN1);
            sacc[f][3] = exp2ff(sacc[f][3] - mN1);
            ls0 += sacc[f][0] + sacc[f][1];
            ls1 += sacc[f][2] + sacc[f][3];
        }
        ls0 += __shfl_xor_sync(0xffffffffu, ls0, 1);
        ls0 += __shfl_xor_sync(0xffffffffu, ls0, 2);
        ls1 += __shfl_xor_sync(0xffffffffu, ls1, 1);
        ls1 += __shfl_xor_sync(0xffffffffu, ls1, 2);
        lsum[0] = lsum[0] * corr0 + ls0;
        lsum[1] = lsum[1] * corr1 + ls1;

#pragma unroll
        for (int f = 0; f < 16; ++f) {
            oacc[f][0] *= corr0; oacc[f][1] *= corr0;
            oacc[f][2] *= corr1; oacc[f][3] *= corr1;
        }

        // ---- P -> A frags (hi + residual lo) ----
        uint32_t pah[4][4], pal[4][4];
#pragma unroll
        for (int kc = 0; kc < 4; ++kc) {
            const int f0 = 2 * kc, f1 = 2 * kc + 1;
            pah[kc][0] = packbf(sacc[f0][0], sacc[f0][1]);
            pah[kc][1] = packbf(sacc[f0][2], sacc[f0][3]);
            pah[kc][2] = packbf(sacc[f1][0], sacc[f1][1]);
            pah[kc][3] = packbf(sacc[f1][2], sacc[f1][3]);
#pragma unroll
            for (int e = 0; e < 4; ++e) {
                const int ff = (e < 2) ? f0 : f1;
                const int i0 = (e & 1) * 2;
                float r0 = sacc[ff][i0]     - __bfloat162float(__float2bfloat16(sacc[ff][i0]));
                float r1 = sacc[ff][i0 + 1] - __bfloat162float(__float2bfloat16(sacc[ff][i0 + 1]));
                pal[kc][e] = packbf(r0, r1);
            }
        }

        // ---- O += Ph*Vh + Ph*Vl + Pl*Vh ----
        const uint32_t vrow = stg + 2 * FKT
                            + ((lane & 7) + ((lane >> 3) & 1) * 8) * FPITCH
                            + ((lane >> 4) & 1) * 16;
#pragma unroll
        for (int kc = 0; kc < 4; ++kc) {
#pragma unroll
            for (int nf2 = 0; nf2 < 8; ++nf2) {
                uint32_t va = vrow + kc * (16 * FPITCH) + nf2 * 32;
                uint32_t v0, v1, v2, v3, u0, u1, u2, u3;
                LDSM4T(v0, v1, v2, v3, va);
                LDSM4T(u0, u1, u2, u3, va + FKT);
                MMA16816(oacc[2 * nf2],     pah[kc][0], pah[kc][1], pah[kc][2], pah[kc][3], v0, v1);
                MMA16816(oacc[2 * nf2 + 1], pah[kc][0], pah[kc][1], pah[kc][2], pah[kc][3], v2, v3);
                MMA16816(oacc[2 * nf2],     pah[kc][0], pah[kc][1], pah[kc][2], pah[kc][3], u0, u1);
                MMA16816(oacc[2 * nf2 + 1], pah[kc][0], pah[kc][1], pah[kc][2], pah[kc][3], u2, u3);
                MMA16816(oacc[2 * nf2],     pal[kc][0], pal[kc][1], pal[kc][2], pal[kc][3], v0, v1);
                MMA16816(oacc[2 * nf2 + 1], pal[kc][0], pal[kc][1], pal[kc][2], pal[kc][3], v2, v3);
            }
        }

        CPA_WAIT0();
        __syncthreads();
    }

    // ---- epilogue: O / l -> g_attn ----
    const float inv0 = 1.0f / lsum[0];
    const float inv1 = 1.0f / lsum[1];
    float* out0 = g_attn + (size_t)(brow0q + wid * 16 + group) * D_MODEL + hcol;
    float* out1 = out0 + (size_t)8 * D_MODEL;
#pragma unroll
    for (int f = 0; f < 16; ++f) {
        const int col = f * 8 + tig * 2;
        *(float2*)(out0 + col) = make_float2(oacc[f][0] * inv0, oacc[f][1] * inv0);
        *(float2*)(out1 + col) = make_float2(oacc[f][2] * inv1, oacc[f][3] * inv1);
    }
}

// ---------------- launch ----------------
extern "C" void kernel_launch(void* const* d_in, const int* in_sizes, int n_in,
                              void* d_out, int out_size) {
    const float* x  = (const float*)d_in[0];
    const float* Wq = (const float*)d_in[2];
    const float* Wk = (const float*)d_in[3];
    const float* Wv = (const float*)d_in[4];
    const float* Wo = (const float*)d_in[5];
    float* out = (float*)d_out;

    float *pQ, *pK, *pV, *pA;
    cudaGetSymbolAddress((void**)&pQ, g_Q);
    cudaGetSymbolAddress((void**)&pK, g_K);
    cudaGetSymbolAddress((void**)&pV, g_V);
    cudaGetSymbolAddress((void**)&pA, g_attn);
    __nv_bfloat16 *xh, *xl, *wqh, *wql, *wkh, *wkl, *wvh, *wvl, *woh, *wol, *ah, *al, *vh, *vl;
    cudaGetSymbolAddress((void**)&xh, g_xh);   cudaGetSymbolAddress((void**)&xl, g_xl);
    cudaGetSymbolAddress((void**)&wqh, g_wqh); cudaGetSymbolAddress((void**)&wql, g_wql);
    cudaGetSymbolAddress((void**)&wkh, g_wkh); cudaGetSymbolAddress((void**)&wkl, g_wkl);
    cudaGetSymbolAddress((void**)&wvh, g_wvh); cudaGetSymbolAddress((void**)&wvl, g_wvl);
    cudaGetSymbolAddress((void**)&woh, g_woh); cudaGetSymbolAddress((void**)&wol, g_wol);
    cudaGetSymbolAddress((void**)&ah, g_ah);   cudaGetSymbolAddress((void**)&al, g_al);
    cudaGetSymbolAddress((void**)&vh, g_vh);   cudaGetSymbolAddress((void**)&vl, g_vl);

    cudaFuncSetAttribute(gemm_wmma, cudaFuncAttributeMaxDynamicSharedMemorySize, SMEM_WMMA);
    cudaFuncSetAttribute(flash_tc, cudaFuncAttributeMaxDynamicSharedMemorySize, SMEM_FLASH);

    rope_table_kernel<<<(SEQ * 64 + 255) / 256, 256>>>();

    const int nx4 = MROWS * D_MODEL / 4;
    const int nw4 = D_MODEL * D_MODEL / 4;
    split_kernel<<<(nx4 + 255) / 256, 256>>>(x, xh, xl, nx4);
    split_kernel<<<(nw4 + 255) / 256, 256>>>(Wq, wqh, wql, nw4);
    split_kernel<<<(nw4 + 255) / 256, 256>>>(Wk, wkh, wkl, nw4);
    split_kernel<<<(nw4 + 255) / 256, 256>>>(Wv, wvh, wvl, nw4);
    split_kernel<<<(nw4 + 255) / 256, 256>>>(Wo, woh, wol, nw4);

    dim3 gg(D_MODEL / 128, MROWS / 128);   // (16, 32)
    gemm_wmma<<<gg, 128, SMEM_WMMA>>>(xh, xl, wqh, wql, pQ, D_MODEL, D_MODEL);
    gemm_wmma<<<gg, 128, SMEM_WMMA>>>(xh, xl, wkh, wkl, pK, D_MODEL, D_MODEL);
    gemm_wmma<<<gg, 128, SMEM_WMMA>>>(xh, xl, wvh, wvl, pV, D_MODEL, D_MODEL);

    rope_split_kernel<<<(MROWS * (D_MODEL / 2) + 255) / 256, 256>>>();
    split_kernel<<<(nx4 + 255) / 256, 256>>>(pV, vh, vl, nx4);

    flash_tc<<<dim3(SEQ / 128, NHEADS, BATCH), 256, SMEM_FLASH>>>();

    split_kernel<<<(nx4 + 255) / 256, 256>>>(pA, ah, al, nx4);
    gemm_wmma<<<gg, 128, SMEM_WMMA>>>(ah, al, woh, wol, out, D_MODEL, D_MODEL);
}

// round 7
// speedup vs baseline: 2.7995x; 1.0431x over previous
#include <cuda_runtime.h>
#include <cuda_bf16.h>
#include <mma.h>
#include <cstdint>
#include <math.h>

using namespace nvcuda;

#define D_MODEL 2048
#define SEQ     2048
#define BATCH   2
#define NHEADS  16
#define DK      128
#define MROWS   (BATCH*SEQ)   /* 4096 */

// ---------------- scratch (device globals; no allocs allowed) ----------------
__device__ float g_Q[(size_t)MROWS * D_MODEL];
__device__ float g_K[(size_t)MROWS * D_MODEL];
__device__ float g_V[(size_t)MROWS * D_MODEL];
__device__ float g_attn[(size_t)MROWS * D_MODEL];
__device__ float g_cos[SEQ * (DK / 2)];
__device__ float g_sin[SEQ * (DK / 2)];

__device__ __nv_bfloat16 g_xh[(size_t)MROWS * D_MODEL];
__device__ __nv_bfloat16 g_xl[(size_t)MROWS * D_MODEL];
__device__ __nv_bfloat16 g_wqh[(size_t)D_MODEL * D_MODEL];
__device__ __nv_bfloat16 g_wql[(size_t)D_MODEL * D_MODEL];
__device__ __nv_bfloat16 g_wkh[(size_t)D_MODEL * D_MODEL];
__device__ __nv_bfloat16 g_wkl[(size_t)D_MODEL * D_MODEL];
__device__ __nv_bfloat16 g_wvh[(size_t)D_MODEL * D_MODEL];
__device__ __nv_bfloat16 g_wvl[(size_t)D_MODEL * D_MODEL];
__device__ __nv_bfloat16 g_woh[(size_t)D_MODEL * D_MODEL];
__device__ __nv_bfloat16 g_wol[(size_t)D_MODEL * D_MODEL];
__device__ __nv_bfloat16 g_ah[(size_t)MROWS * D_MODEL];
__device__ __nv_bfloat16 g_al[(size_t)MROWS * D_MODEL];

__device__ __nv_bfloat16 g_qh[(size_t)MROWS * D_MODEL];
__device__ __nv_bfloat16 g_ql[(size_t)MROWS * D_MODEL];
__device__ __nv_bfloat16 g_kh[(size_t)MROWS * D_MODEL];
__device__ __nv_bfloat16 g_kl[(size_t)MROWS * D_MODEL];
__device__ __nv_bfloat16 g_vh[(size_t)MROWS * D_MODEL];
__device__ __nv_bfloat16 g_vl[(size_t)MROWS * D_MODEL];

// ---------------- generic PTX helpers ----------------
__device__ __forceinline__ void cpa16(uint32_t dst, const void* src) {
    asm volatile("cp.async.cg.shared.global [%0], [%1], 16;" :: "r"(dst), "l"(src));
}
#define CPA_COMMIT() asm volatile("cp.async.commit_group;" ::: "memory")
#define CPA_WAIT0()  asm volatile("cp.async.wait_group 0;" ::: "memory")
#define CPA_WAIT1()  asm volatile("cp.async.wait_group 1;" ::: "memory")

__device__ __forceinline__ uint32_t su32(const void* p) {
    uint32_t a;
    asm("{ .reg .u64 t; cvta.to.shared.u64 t, %1; cvt.u32.u64 %0, t; }" : "=r"(a) : "l"(p));
    return a;
}

#define LDSM4(r0, r1, r2, r3, a) \
    asm volatile("ldmatrix.sync.aligned.m8n8.x4.shared.b16 {%0,%1,%2,%3}, [%4];" \
                 : "=r"(r0), "=r"(r1), "=r"(r2), "=r"(r3) : "r"(a))
#define LDSM4T(r0, r1, r2, r3, a) \
    asm volatile("ldmatrix.sync.aligned.m8n8.x4.trans.shared.b16 {%0,%1,%2,%3}, [%4];" \
                 : "=r"(r0), "=r"(r1), "=r"(r2), "=r"(r3) : "r"(a))
#define MMA16816(d, a0, a1, a2, a3, b0, b1) \
    asm volatile("mma.sync.aligned.m16n8k16.row.col.f32.bf16.bf16.f32 " \
                 "{%0,%1,%2,%3}, {%4,%5,%6,%7}, {%8,%9}, {%0,%1,%2,%3};" \
                 : "+f"((d)[0]), "+f"((d)[1]), "+f"((d)[2]), "+f"((d)[3]) \
                 : "r"(a0), "r"(a1), "r"(a2), "r"(a3), "r"(b0), "r"(b1))

__device__ __forceinline__ uint32_t packbf(float lo, float hi) {
    uint32_t u;
    asm("cvt.rn.bf16x2.f32 %0, %1, %2;" : "=r"(u) : "f"(hi), "f"(lo));
    return u;
}
__device__ __forceinline__ float bfres(float x) {
    return x - __bfloat162float(__float2bfloat16(x));
}

// fast exp2 on FMA pipe (arg <= 0), rel err ~1.5e-5
__device__ __forceinline__ float exp2ff(float x) {
    x = fmaxf(x, -126.0f);
    float fl = floorf(x);
    float f = x - fl;
    float p = 1.54035304e-4f;
    p = fmaf(p, f, 1.33335581e-3f);
    p = fmaf(p, f, 9.61812910e-3f);
    p = fmaf(p, f, 5.55041086e-2f);
    p = fmaf(p, f, 2.40226512e-1f);
    p = fmaf(p, f, 6.93147182e-1f);
    p = fmaf(p, f, 1.0f);
    return __uint_as_float((uint32_t)((int)fl + 127) << 23) * p;
}

// ---------------- split helper ----------------
__device__ __forceinline__ void split4(const float* __restrict__ src,
                                       __nv_bfloat16* __restrict__ hi,
                                       __nv_bfloat16* __restrict__ lo, int i) {
    float4 v = ((const float4*)src)[i];
    __nv_bfloat16 h0 = __float2bfloat16(v.x);
    __nv_bfloat16 h1 = __float2bfloat16(v.y);
    __nv_bfloat16 h2 = __float2bfloat16(v.z);
    __nv_bfloat16 h3 = __float2bfloat16(v.w);
    __nv_bfloat16 l0 = __float2bfloat16(v.x - __bfloat162float(h0));
    __nv_bfloat16 l1 = __float2bfloat16(v.y - __bfloat162float(h1));
    __nv_bfloat16 l2 = __float2bfloat16(v.z - __bfloat162float(h2));
    __nv_bfloat16 l3 = __float2bfloat16(v.w - __bfloat162float(h3));
    uint2 hp, lp;
    hp.x = (uint32_t)__bfloat16_as_ushort(h0) | ((uint32_t)__bfloat16_as_ushort(h1) << 16);
    hp.y = (uint32_t)__bfloat16_as_ushort(h2) | ((uint32_t)__bfloat16_as_ushort(h3) << 16);
    lp.x = (uint32_t)__bfloat16_as_ushort(l0) | ((uint32_t)__bfloat16_as_ushort(l1) << 16);
    lp.y = (uint32_t)__bfloat16_as_ushort(l2) | ((uint32_t)__bfloat16_as_ushort(l3) << 16);
    ((uint2*)hi)[i] = hp;
    ((uint2*)lo)[i] = lp;
}

__global__ void split_kernel(const float* __restrict__ src,
                             __nv_bfloat16* __restrict__ hi,
                             __nv_bfloat16* __restrict__ lo, int n4) {
    int i = blockIdx.x * blockDim.x + threadIdx.x;
    if (i >= n4) return;
    split4(src, hi, lo, i);
}

// ---------------- fused prep: rope tables + all input/weight splits ----------
// sections: [0,512) tables; [512,8704) x; [8704,+4*4096) Wq,Wk,Wv,Wo
__global__ void prep_kernel(const float* __restrict__ x,
                            const float* __restrict__ Wq, const float* __restrict__ Wk,
                            const float* __restrict__ Wv, const float* __restrict__ Wo) {
    int bid = blockIdx.x;
    int t = threadIdx.x;
    if (bid < 512) {
        int idx = bid * 256 + t;           // SEQ*64 = 131072
        int s = idx >> 6;
        int i = idx & 63;
        float th = powf(10000.0f, (float)i * (1.0f / 64.0f));
        float ph = (float)s / th;          // fp32 rounding matches reference
        double phd = (double)ph;
        g_cos[idx] = (float)cos(phd);
        g_sin[idx] = (float)sin(phd);
    } else if (bid < 8704) {
        split4(x, g_xh, g_xl, (bid - 512) * 256 + t);
    } else {
        int r = bid - 8704;
        int which = r >> 12;
        int i = (r & 4095) * 256 + t;
        if (which == 0)      split4(Wq, g_wqh, g_wql, i);
        else if (which == 1) split4(Wk, g_wkh, g_wkl, i);
        else if (which == 2) split4(Wv, g_wvh, g_wvl, i);
        else                 split4(Wo, g_wvh == g_wvh ? g_woh : g_woh, g_wol, i);
    }
}

// ---------------- fused rope+split(Q,K) and split(V) -------------------------
__global__ void rope_split_v() {
    int bid = blockIdx.x;
    int t = threadIdx.x;
    if (bid < 16384) {
        int idx = bid * 256 + t;          // MROWS*1024
        int row = idx >> 10;
        int c2  = idx & 1023;
        int i   = c2 & 63;
        int s   = row & (SEQ - 1);
        float c  = g_cos[(s << 6) + i];
        float sn = g_sin[(s << 6) + i];
        size_t off = (size_t)row * (D_MODEL / 2) + c2;

        float2 q = ((float2*)g_Q)[off];
        float qa = q.x * c - q.y * sn;
        float qb = q.x * sn + q.y * c;
        __nv_bfloat16 qah = __float2bfloat16(qa), qbh = __float2bfloat16(qb);
        ((__nv_bfloat162*)g_qh)[off] = __halves2bfloat162(qah, qbh);
        ((__nv_bfloat162*)g_ql)[off] = __halves2bfloat162(
            __float2bfloat16(qa - __bfloat162float(qah)),
            __float2bfloat16(qb - __bfloat162float(qbh)));

        float2 k = ((float2*)g_K)[off];
        float ka = k.x * c - k.y * sn;
        float kb = k.x * sn + k.y * c;
        __nv_bfloat16 kah = __float2bfloat16(ka), kbh = __float2bfloat16(kb);
        ((__nv_bfloat162*)g_kh)[off] = __halves2bfloat162(kah, kbh);
        ((__nv_bfloat162*)g_kl)[off] = __halves2bfloat162(
            __float2bfloat16(ka - __bfloat162float(kah)),
            __float2bfloat16(kb - __bfloat162float(kbh)));
    } else {
        split4(g_V, g_vh, g_vl, (bid - 16384) * 256 + t);
    }
}

// ============================================================================
// wmma bf16 GEMM (unchanged, ~93% of legacy-HMMA peak)
// ============================================================================
#define WPAD       24
#define WSTG_EL    (128 * WPAD)
#define WSTAGE_B   (4 * WSTG_EL * 2)
#define SMEM_WMMA  (2 * WSTAGE_B)

__device__ __forceinline__ void load_chunk_wmma(
    uint32_t sdst, const __nv_bfloat16* __restrict__ Ah, const __nv_bfloat16* __restrict__ Al,
    const __nv_bfloat16* __restrict__ Bh, const __nv_bfloat16* __restrict__ Bl,
    int m0, int n0, int k0, int K, int tid) {
    const __nv_bfloat16* srcs[4] = {Ah, Al, Bh, Bl};
#pragma unroll
    for (int t = 0; t < 8; ++t) {
        int u = t * 128 + tid;
        int mtx = u >> 8;
        int rem = u & 255;
        int row = rem >> 1;
        int c16 = rem & 1;
        int gr = (mtx < 2 ? m0 : n0) + row;
        uint32_t doff = (uint32_t)mtx * (WSTG_EL * 2) + row * (WPAD * 2) + c16 * 16;
        cpa16(sdst + doff, srcs[mtx] + (size_t)gr * K + k0 + c16 * 8);
    }
}

__global__ void __launch_bounds__(128) gemm_wmma(
    const __nv_bfloat16* __restrict__ Ah, const __nv_bfloat16* __restrict__ Al,
    const __nv_bfloat16* __restrict__ Bh, const __nv_bfloat16* __restrict__ Bl,
    float* __restrict__ C, int N, int K) {
    extern __shared__ char smem[];
    const uint32_t sbase = su32(smem);
    const int tid = threadIdx.x;
    const int wid = tid >> 5;
    const int m0 = blockIdx.y * 128;
    const int n0 = blockIdx.x * 128;
    const int wm = (wid & 1) * 64;
    const int wn = (wid >> 1) * 64;
    const int nchunk = K >> 4;

    wmma::fragment<wmma::accumulator, 16, 16, 16, float> acc[4][4];
#pragma unroll
    for (int mi = 0; mi < 4; ++mi)
#pragma unroll
        for (int ni = 0; ni < 4; ++ni) wmma::fill_fragment(acc[mi][ni], 0.0f);

    load_chunk_wmma(sbase, Ah, Al, Bh, Bl, m0, n0, 0, K, tid);
    CPA_COMMIT();

    for (int c = 0; c < nchunk; ++c) {
        const int p = c & 1;
        const __nv_bfloat16* s = (const __nv_bfloat16*)(smem + p * WSTAGE_B);
        const __nv_bfloat16* sah = s;
        const __nv_bfloat16* sal = s + WSTG_EL;
        const __nv_bfloat16* sbh = s + 2 * WSTG_EL;
        const __nv_bfloat16* sbl = s + 3 * WSTG_EL;

        CPA_WAIT0();
        __syncthreads();
        if (c + 1 < nchunk) {
            load_chunk_wmma(sbase + (p ^ 1) * WSTAGE_B, Ah, Al, Bh, Bl,
                            m0, n0, (c + 1) << 4, K, tid);
            CPA_COMMIT();
        }

        wmma::fragment<wmma::matrix_b, 16, 16, 16, __nv_bfloat16, wmma::col_major> fbh[4], fbl[4];
#pragma unroll
        for (int ni = 0; ni < 4; ++ni) {
            wmma::load_matrix_sync(fbh[ni], sbh + (wn + ni * 16) * WPAD, WPAD);
            wmma::load_matrix_sync(fbl[ni], sbl + (wn + ni * 16) * WPAD, WPAD);
        }
#pragma unroll
        for (int mi = 0; mi < 4; ++mi) {
            wmma::fragment<wmma::matrix_a, 16, 16, 16, __nv_bfloat16, wmma::row_major> fah, fal;
            wmma::load_matrix_sync(fah, sah + (wm + mi * 16) * WPAD, WPAD);
            wmma::load_matrix_sync(fal, sal + (wm + mi * 16) * WPAD, WPAD);
#pragma unroll
            for (int ni = 0; ni < 4; ++ni) {
                wmma::mma_sync(acc[mi][ni], fah, fbh[ni], acc[mi][ni]);
                wmma::mma_sync(acc[mi][ni], fah, fbl[ni], acc[mi][ni]);
                wmma::mma_sync(acc[mi][ni], fal, fbh[ni], acc[mi][ni]);
            }
        }
        __syncthreads();
    }

#pragma unroll
    for (int mi = 0; mi < 4; ++mi)
#pragma unroll
        for (int ni = 0; ni < 4; ++ni)
            wmma::store_matrix_sync(C + (size_t)(m0 + wm + mi * 16) * N + n0 + wn + ni * 16,
                                    acc[mi][ni], N, wmma::mem_row_major);
}

// ============================================================================
// Flash attention: 64-row CTA, 128 threads, 104.4KB smem -> 2 CTAs/SM.
// Split K/V single buffers, pipelined reload; split-precision mma throughout.
// ============================================================================
#define FPITCH 272
#define FKT    (64 * FPITCH)       /* 17408 per matrix */
#define QOFF   0                   /* qh, ql */
#define KOFF   (2 * FKT)           /* kh, kl */
#define VOFF   (4 * FKT)           /* vh, vl */
#define SMEM_FLASH (6 * FKT)       /* 104448 */

__device__ __forceinline__ void ld_pair(uint32_t sdst, const __nv_bfloat16* __restrict__ h,
                                        const __nv_bfloat16* __restrict__ l,
                                        int brow0, int hcol, int tid) {
#pragma unroll
    for (int t = 0; t < 16; ++t) {
        int u = t * 128 + tid;            // 0..2047: 2 mats x 64 rows x 16 chunks
        int mtx = u >> 10;
        int rem = u & 1023;
        int row = rem >> 4;
        int c16 = rem & 15;
        const __nv_bfloat16* src = mtx ? l : h;
        cpa16(sdst + mtx * FKT + row * FPITCH + c16 * 16,
              src + (size_t)(brow0 + row) * D_MODEL + hcol + c16 * 8);
    }
}

__global__ void __launch_bounds__(128) flash_tc() {
    extern __shared__ char smem[];
    const uint32_t sbase = su32(smem);
    const int tid  = threadIdx.x;
    const int wid  = tid >> 5;
    const int lane = tid & 31;
    const int qb   = (int)gridDim.x - 1 - (int)blockIdx.x;  // big tiles first
    const int h    = blockIdx.y;
    const int b    = blockIdx.z;
    const int hcol = h * DK;
    const int brow0q = b * SEQ + qb * 64;
    const int group = lane >> 2;
    const int tig   = lane & 3;
    const int qg0   = qb * 64 + wid * 16 + group;

    const float SCL2 = 0.08838834764831845f * 1.4426950408889634f;

    ld_pair(sbase + QOFF, g_qh, g_ql, brow0q, hcol, tid);
    ld_pair(sbase + KOFF, g_kh, g_kl, b * SEQ, hcol, tid);
    CPA_COMMIT();                          // group: Q + K0
    ld_pair(sbase + VOFF, g_vh, g_vl, b * SEQ, hcol, tid);
    CPA_COMMIT();                          // group: V0

    float oacc[16][4];
#pragma unroll
    for (int f = 0; f < 16; ++f) {
        oacc[f][0] = 0.f; oacc[f][1] = 0.f; oacc[f][2] = 0.f; oacc[f][3] = 0.f;
    }
    float m2[2] = {-1e30f, -1e30f};        // raw (unscaled) running max
    float lsum[2] = {0.f, 0.f};

    const int nt = qb + 1;
    const uint32_t qrow_base = sbase + QOFF + (wid * 16 + (lane & 15)) * FPITCH
                             + (lane >> 4) * 16;
    const uint32_t krow = sbase + KOFF + (lane & 15) * FPITCH + (lane >> 4) * 16;
    const uint32_t vrow = sbase + VOFF
                        + ((lane & 7) + ((lane >> 3) & 1) * 8) * FPITCH
                        + ((lane >> 4) & 1) * 16;

    for (int t = 0; t < nt; ++t) {
        CPA_WAIT1();                       // K(t) (and Q) landed; V(t) may be in flight
        __syncthreads();

        // ---- S = Qh*Kh' + Qh*Kl' + Ql*Kh' (raw scores) ----
        float sacc[8][4];
#pragma unroll
        for (int f = 0; f < 8; ++f) {
            sacc[f][0] = 0.f; sacc[f][1] = 0.f; sacc[f][2] = 0.f; sacc[f][3] = 0.f;
        }
#pragma unroll
        for (int kc = 0; kc < 8; ++kc) {
            uint32_t qa0, qa1, qa2, qa3, ql0, ql1, ql2, ql3;
            LDSM4(qa0, qa1, qa2, qa3, qrow_base + kc * 32);
            LDSM4(ql0, ql1, ql2, ql3, qrow_base + FKT + kc * 32);
#pragma unroll
            for (int nf2 = 0; nf2 < 4; ++nf2) {
                uint32_t kh0, kh1, kh2, kh3, kl0, kl1, kl2, kl3;
                uint32_t ka = krow + nf2 * (16 * FPITCH) + kc * 32;
                LDSM4(kh0, kh1, kh2, kh3, ka);
                LDSM4(kl0, kl1, kl2, kl3, ka + FKT);
                MMA16816(sacc[2 * nf2],     qa0, qa1, qa2, qa3, kh0, kh2);
                MMA16816(sacc[2 * nf2 + 1], qa0, qa1, qa2, qa3, kh1, kh3);
                MMA16816(sacc[2 * nf2],     qa0, qa1, qa2, qa3, kl0, kl2);
                MMA16816(sacc[2 * nf2 + 1], qa0, qa1, qa2, qa3, kl1, kl3);
                MMA16816(sacc[2 * nf2],     ql0, ql1, ql2, ql3, kh0, kh2);
                MMA16816(sacc[2 * nf2 + 1], ql0, ql1, ql2, ql3, kh1, kh3);
            }
        }
        __syncthreads();                   // all warps done reading K buffer
        if (t + 1 < nt) {                  // reload K for t+1 (hidden behind softmax+PV)
            ld_pair(sbase + KOFF, g_kh, g_kl, b * SEQ + (t + 1) * 64, hcol, tid);
            CPA_COMMIT();
        }

        // ---- causal mask on raw scores (diagonal tile only) ----
        if (t == qb) {
            const int j0 = t * 64;
#pragma unroll
            for (int f = 0; f < 8; ++f) {
                int col = j0 + f * 8 + tig * 2;
                if (col > qg0)          sacc[f][0] = -1e30f;
                if (col + 1 > qg0)      sacc[f][1] = -1e30f;
                if (col > qg0 + 8)      sacc[f][2] = -1e30f;
                if (col + 1 > qg0 + 8)  sacc[f][3] = -1e30f;
            }
        }

        // ---- online softmax (raw max; scale fused into exp args) ----
        float mn0 = -1e30f, mn1 = -1e30f;
#pragma unroll
        for (int f = 0; f < 8; ++f) {
            mn0 = fmaxf(mn0, fmaxf(sacc[f][0], sacc[f][1]));
            mn1 = fmaxf(mn1, fmaxf(sacc[f][2], sacc[f][3]));
        }
        mn0 = fmaxf(mn0, __shfl_xor_sync(0xffffffffu, mn0, 1));
        mn0 = fmaxf(mn0, __shfl_xor_sync(0xffffffffu, mn0, 2));
        mn1 = fmaxf(mn1, __shfl_xor_sync(0xffffffffu, mn1, 1));
        mn1 = fmaxf(mn1, __shfl_xor_sync(0xffffffffu, mn1, 2));
        float mN0 = fmaxf(m2[0], mn0), mN1 = fmaxf(m2[1], mn1);
        float corr0 = exp2ff(SCL2 * (m2[0] - mN0));
        float corr1 = exp2ff(SCL2 * (m2[1] - mN1));
        m2[0] = mN0; m2[1] = mN1;
        const float b0 = mN0 * SCL2, b1 = mN1 * SCL2;

        float ls0 = 0.f, ls1 = 0.f;
#pragma unroll
        for (int f = 0; f < 8; ++f) {
            sacc[f][0] = exp2ff(fmaf(sacc[f][0], SCL2, -b0));
            sacc[f][1] = exp2ff(fmaf(sacc[f][1], SCL2, -b0));
            sacc[f][2] = exp2ff(fmaf(sacc[f][2], SCL2, -b1));
            sacc[f][3] = exp2ff(fmaf(sacc[f][3], SCL2, -b1));
            ls0 += sacc[f][0] + sacc[f][1];
            ls1 += sacc[f][2] + sacc[f][3];
        }
        ls0 += __shfl_xor_sync(0xffffffffu, ls0, 1);
        ls0 += __shfl_xor_sync(0xffffffffu, ls0, 2);
        ls1 += __shfl_xor_sync(0xffffffffu, ls1, 1);
        ls1 += __shfl_xor_sync(0xffffffffu, ls1, 2);
        lsum[0] = lsum[0] * corr0 + ls0;
        lsum[1] = lsum[1] * corr1 + ls1;

#pragma unroll
        for (int f = 0; f < 16; ++f) {
            oacc[f][0] *= corr0; oacc[f][1] *= corr0;
            oacc[f][2] *= corr1; oacc[f][3] *= corr1;
        }

        // ---- wait V(t), then O += Ph*Vh + Ph*Vl + Pl*Vh ----
        if (t + 1 < nt) CPA_WAIT1(); else CPA_WAIT0();
        __syncthreads();

#pragma unroll
        for (int kc = 0; kc < 4; ++kc) {
            const int f0 = 2 * kc, f1 = 2 * kc + 1;
            uint32_t ph0 = packbf(sacc[f0][0], sacc[f0][1]);
            uint32_t ph1 = packbf(sacc[f0][2], sacc[f0][3]);
            uint32_t ph2 = packbf(sacc[f1][0], sacc[f1][1]);
            uint32_t ph3 = packbf(sacc[f1][2], sacc[f1][3]);
            uint32_t pl0 = packbf(bfres(sacc[f0][0]), bfres(sacc[f0][1]));
            uint32_t pl1 = packbf(bfres(sacc[f0][2]), bfres(sacc[f0][3]));
            uint32_t pl2 = packbf(bfres(sacc[f1][0]), bfres(sacc[f1][1]));
            uint32_t pl3 = packbf(bfres(sacc[f1][2]), bfres(sacc[f1][3]));
#pragma unroll
            for (int nf2 = 0; nf2 < 8; ++nf2) {
                uint32_t va = vrow + kc * (16 * FPITCH) + nf2 * 32;
                uint32_t v0, v1, v2, v3, u0, u1, u2, u3;
                LDSM4T(v0, v1, v2, v3, va);
                LDSM4T(u0, u1, u2, u3, va + FKT);
                MMA16816(oacc[2 * nf2],     ph0, ph1, ph2, ph3, v0, v1);
                MMA16816(oacc[2 * nf2 + 1], ph0, ph1, ph2, ph3, v2, v3);
                MMA16816(oacc[2 * nf2],     ph0, ph1, ph2, ph3, u0, u1);
                MMA16816(oacc[2 * nf2 + 1], ph0, ph1, ph2, ph3, u2, u3);
                MMA16816(oacc[2 * nf2],     pl0, pl1, pl2, pl3, v0, v1);
                MMA16816(oacc[2 * nf2 + 1], pl0, pl1, pl2, pl3, v2, v3);
            }
        }
        __syncthreads();                   // all warps done reading V buffer
        if (t + 1 < nt) {                  // reload V for t+1 (hidden behind next S)
            ld_pair(sbase + VOFF, g_vh, g_vl, b * SEQ + (t + 1) * 64, hcol, tid);
            CPA_COMMIT();
        }
    }

    // ---- epilogue ----
    const float inv0 = 1.0f / lsum[0];
    const float inv1 = 1.0f / lsum[1];
    float* out0 = g_attn + (size_t)(brow0q + wid * 16 + group) * D_MODEL + hcol;
    float* out1 = out0 + (size_t)8 * D_MODEL;
#pragma unroll
    for (int f = 0; f < 16; ++f) {
        const int col = f * 8 + tig * 2;
        *(float2*)(out0 + col) = make_float2(oacc[f][0] * inv0, oacc[f][1] * inv0);
        *(float2*)(out1 + col) = make_float2(oacc[f][2] * inv1, oacc[f][3] * inv1);
    }
}

// ---------------- launch (flash is launch index 5 -> ncu-captured) ----------
extern "C" void kernel_launch(void* const* d_in, const int* in_sizes, int n_in,
                              void* d_out, int out_size) {
    const float* x  = (const float*)d_in[0];
    const float* Wq = (const float*)d_in[2];
    const float* Wk = (const float*)d_in[3];
    const float* Wv = (const float*)d_in[4];
    const float* Wo = (const float*)d_in[5];
    float* out = (float*)d_out;

    float *pQ, *pK, *pV, *pA;
    cudaGetSymbolAddress((void**)&pQ, g_Q);
    cudaGetSymbolAddress((void**)&pK, g_K);
    cudaGetSymbolAddress((void**)&pV, g_V);
    cudaGetSymbolAddress((void**)&pA, g_attn);
    __nv_bfloat16 *xh, *xl, *wqh, *wql, *wkh, *wkl, *wvh, *wvl, *woh, *wol, *ah, *al;
    cudaGetSymbolAddress((void**)&xh, g_xh);   cudaGetSymbolAddress((void**)&xl, g_xl);
    cudaGetSymbolAddress((void**)&wqh, g_wqh); cudaGetSymbolAddress((void**)&wql, g_wql);
    cudaGetSymbolAddress((void**)&wkh, g_wkh); cudaGetSymbolAddress((void**)&wkl, g_wkl);
    cudaGetSymbolAddress((void**)&wvh, g_wvh); cudaGetSymbolAddress((void**)&wvl, g_wvl);
    cudaGetSymbolAddress((void**)&woh, g_woh); cudaGetSymbolAddress((void**)&wol, g_wol);
    cudaGetSymbolAddress((void**)&ah, g_ah);   cudaGetSymbolAddress((void**)&al, g_al);

    cudaFuncSetAttribute(gemm_wmma, cudaFuncAttributeMaxDynamicSharedMemorySize, SMEM_WMMA);
    cudaFuncSetAttribute(flash_tc, cudaFuncAttributeMaxDynamicSharedMemorySize, SMEM_FLASH);

    const int nx4 = MROWS * D_MODEL / 4;
    dim3 gg(D_MODEL / 128, MROWS / 128);   // (16, 32)

    prep_kernel<<<8704 + 4 * 4096, 256>>>(x, Wq, Wk, Wv, Wo);                // 0
    gemm_wmma<<<gg, 128, SMEM_WMMA>>>(xh, xl, wqh, wql, pQ, D_MODEL, D_MODEL); // 1
    gemm_wmma<<<gg, 128, SMEM_WMMA>>>(xh, xl, wkh, wkl, pK, D_MODEL, D_MODEL); // 2
    gemm_wmma<<<gg, 128, SMEM_WMMA>>>(xh, xl, wvh, wvl, pV, D_MODEL, D_MODEL); // 3
    rope_split_v<<<16384 + 8192, 256>>>();                                   // 4
    flash_tc<<<dim3(SEQ / 64, NHEADS, BATCH), 128, SMEM_FLASH>>>();          // 5 <- profiled
    split_kernel<<<(nx4 + 255) / 256, 256>>>(pA, ah, al, nx4);               // 6
    gemm_wmma<<<gg, 128, SMEM_WMMA>>>(ah, al, woh, wol, out, D_MODEL, D_MODEL); // 7
}

// round 9
// speedup vs baseline: 3.5139x; 1.2552x over previous
#include <cuda_runtime.h>
#include <cuda_bf16.h>
#include <cstdint>
#include <math.h>

#define D_MODEL 2048
#define SEQ     2048
#define BATCH   2
#define NHEADS  16
#define DK      128
#define MROWS   (BATCH*SEQ)   /* 4096 */

// ---------------- scratch ----------------
__device__ float g_Q[(size_t)MROWS * D_MODEL];
__device__ float g_K[(size_t)MROWS * D_MODEL];
__device__ float g_cos[SEQ * (DK / 2)];
__device__ float g_sin[SEQ * (DK / 2)];

__device__ __nv_bfloat16 g_xh[(size_t)MROWS * D_MODEL];
__device__ __nv_bfloat16 g_xl[(size_t)MROWS * D_MODEL];
__device__ __nv_bfloat16 g_wqh[(size_t)D_MODEL * D_MODEL];
__device__ __nv_bfloat16 g_wql[(size_t)D_MODEL * D_MODEL];
__device__ __nv_bfloat16 g_wkh[(size_t)D_MODEL * D_MODEL];
__device__ __nv_bfloat16 g_wkl[(size_t)D_MODEL * D_MODEL];
__device__ __nv_bfloat16 g_wvh[(size_t)D_MODEL * D_MODEL];
__device__ __nv_bfloat16 g_wvl[(size_t)D_MODEL * D_MODEL];
__device__ __nv_bfloat16 g_woh[(size_t)D_MODEL * D_MODEL];
__device__ __nv_bfloat16 g_wol[(size_t)D_MODEL * D_MODEL];
__device__ __nv_bfloat16 g_ah[(size_t)MROWS * D_MODEL];
__device__ __nv_bfloat16 g_al[(size_t)MROWS * D_MODEL];

__device__ __nv_bfloat16 g_qh[(size_t)MROWS * D_MODEL];
__device__ __nv_bfloat16 g_ql[(size_t)MROWS * D_MODEL];
__device__ __nv_bfloat16 g_kh[(size_t)MROWS * D_MODEL];
__device__ __nv_bfloat16 g_kl[(size_t)MROWS * D_MODEL];
__device__ __nv_bfloat16 g_vh[(size_t)MROWS * D_MODEL];
__device__ __nv_bfloat16 g_vl[(size_t)MROWS * D_MODEL];

// ---------------- PTX helpers ----------------
__device__ __forceinline__ void cpa16(uint32_t dst, const void* src) {
    asm volatile("cp.async.cg.shared.global [%0], [%1], 16;" :: "r"(dst), "l"(src));
}
#define CPA_COMMIT() asm volatile("cp.async.commit_group;" ::: "memory")
#define CPA_WAIT0()  asm volatile("cp.async.wait_group 0;" ::: "memory")
#define CPA_WAIT1()  asm volatile("cp.async.wait_group 1;" ::: "memory")

__device__ __forceinline__ uint32_t su32(const void* p) {
    uint32_t a;
    asm("{ .reg .u64 t; cvta.to.shared.u64 t, %1; cvt.u32.u64 %0, t; }" : "=r"(a) : "l"(p));
    return a;
}

#define LDSM4(r0, r1, r2, r3, a) \
    asm volatile("ldmatrix.sync.aligned.m8n8.x4.shared.b16 {%0,%1,%2,%3}, [%4];" \
                 : "=r"(r0), "=r"(r1), "=r"(r2), "=r"(r3) : "r"(a))
#define LDSM4T(r0, r1, r2, r3, a) \
    asm volatile("ldmatrix.sync.aligned.m8n8.x4.trans.shared.b16 {%0,%1,%2,%3}, [%4];" \
                 : "=r"(r0), "=r"(r1), "=r"(r2), "=r"(r3) : "r"(a))
#define MMA16816(d, a0, a1, a2, a3, b0, b1) \
    asm volatile("mma.sync.aligned.m16n8k16.row.col.f32.bf16.bf16.f32 " \
                 "{%0,%1,%2,%3}, {%4,%5,%6,%7}, {%8,%9}, {%0,%1,%2,%3};" \
                 : "+f"((d)[0]), "+f"((d)[1]), "+f"((d)[2]), "+f"((d)[3]) \
                 : "r"(a0), "r"(a1), "r"(a2), "r"(a3), "r"(b0), "r"(b1))

__device__ __forceinline__ uint32_t packbf(float lo, float hi) {
    uint32_t u;
    asm("cvt.rn.bf16x2.f32 %0, %1, %2;" : "=r"(u) : "f"(hi), "f"(lo));
    return u;
}
__device__ __forceinline__ float bfres(float x) {
    return x - __bfloat162float(__float2bfloat16(x));
}

// fast exp2 on FMA pipe (arg <= 0)
__device__ __forceinline__ float exp2ff(float x) {
    x = fmaxf(x, -126.0f);
    float fl = floorf(x);
    float f = x - fl;
    float p = 1.54035304e-4f;
    p = fmaf(p, f, 1.33335581e-3f);
    p = fmaf(p, f, 9.61812910e-3f);
    p = fmaf(p, f, 5.55041086e-2f);
    p = fmaf(p, f, 2.40226512e-1f);
    p = fmaf(p, f, 6.93147182e-1f);
    p = fmaf(p, f, 1.0f);
    return __uint_as_float((uint32_t)((int)fl + 127) << 23) * p;
}

// ---------------- split helper ----------------
__device__ __forceinline__ void split4(const float* __restrict__ src,
                                       __nv_bfloat16* __restrict__ hi,
                                       __nv_bfloat16* __restrict__ lo, int i) {
    float4 v = ((const float4*)src)[i];
    __nv_bfloat16 h0 = __float2bfloat16(v.x);
    __nv_bfloat16 h1 = __float2bfloat16(v.y);
    __nv_bfloat16 h2 = __float2bfloat16(v.z);
    __nv_bfloat16 h3 = __float2bfloat16(v.w);
    __nv_bfloat16 l0 = __float2bfloat16(v.x - __bfloat162float(h0));
    __nv_bfloat16 l1 = __float2bfloat16(v.y - __bfloat162float(h1));
    __nv_bfloat16 l2 = __float2bfloat16(v.z - __bfloat162float(h2));
    __nv_bfloat16 l3 = __float2bfloat16(v.w - __bfloat162float(h3));
    uint2 hp, lp;
    hp.x = (uint32_t)__bfloat16_as_ushort(h0) | ((uint32_t)__bfloat16_as_ushort(h1) << 16);
    hp.y = (uint32_t)__bfloat16_as_ushort(h2) | ((uint32_t)__bfloat16_as_ushort(h3) << 16);
    lp.x = (uint32_t)__bfloat16_as_ushort(l0) | ((uint32_t)__bfloat16_as_ushort(l1) << 16);
    lp.y = (uint32_t)__bfloat16_as_ushort(l2) | ((uint32_t)__bfloat16_as_ushort(l3) << 16);
    ((uint2*)hi)[i] = hp;
    ((uint2*)lo)[i] = lp;
}

// ---------------- fused prep: rope tables + input/weight splits --------------
__global__ void prep_kernel(const float* __restrict__ x,
                            const float* __restrict__ Wq, const float* __restrict__ Wk,
                            const float* __restrict__ Wv, const float* __restrict__ Wo) {
    int bid = blockIdx.x;
    int t = threadIdx.x;
    if (bid < 512) {
        int idx = bid * 256 + t;
        int s = idx >> 6;
        int i = idx & 63;
        float th = powf(10000.0f, (float)i * (1.0f / 64.0f));
        float ph = (float)s / th;          // fp32 rounding matches reference
        double phd = (double)ph;
        g_cos[idx] = (float)cos(phd);
        g_sin[idx] = (float)sin(phd);
    } else if (bid < 8704) {
        split4(x, g_xh, g_xl, (bid - 512) * 256 + t);
    } else {
        int r = bid - 8704;
        int which = r >> 12;
        int i = (r & 4095) * 256 + t;
        if (which == 0)      split4(Wq, g_wqh, g_wql, i);
        else if (which == 1) split4(Wk, g_wkh, g_wkl, i);
        else if (which == 2) split4(Wv, g_wvh, g_wvl, i);
        else                 split4(Wo, g_woh, g_wol, i);
    }
}

// ---------------- RoPE + split for Q,K only ----------------------------------
__global__ void rope_qk() {
    int idx = blockIdx.x * 256 + threadIdx.x;   // MROWS*1024
    int row = idx >> 10;
    int c2  = idx & 1023;
    int i   = c2 & 63;
    int s   = row & (SEQ - 1);
    float c  = g_cos[(s << 6) + i];
    float sn = g_sin[(s << 6) + i];
    size_t off = (size_t)row * (D_MODEL / 2) + c2;

    float2 q = ((float2*)g_Q)[off];
    float qa = q.x * c - q.y * sn;
    float qb = q.x * sn + q.y * c;
    __nv_bfloat16 qah = __float2bfloat16(qa), qbh = __float2bfloat16(qb);
    ((__nv_bfloat162*)g_qh)[off] = __halves2bfloat162(qah, qbh);
    ((__nv_bfloat162*)g_ql)[off] = __halves2bfloat162(
        __float2bfloat16(qa - __bfloat162float(qah)),
        __float2bfloat16(qb - __bfloat162float(qbh)));

    float2 k = ((float2*)g_K)[off];
    float ka = k.x * c - k.y * sn;
    float kb = k.x * sn + k.y * c;
    __nv_bfloat16 kah = __float2bfloat16(ka), kbh = __float2bfloat16(kb);
    ((__nv_bfloat162*)g_kh)[off] = __halves2bfloat162(kah, kbh);
    ((__nv_bfloat162*)g_kl)[off] = __halves2bfloat162(
        __float2bfloat16(ka - __bfloat162float(kah)),
        __float2bfloat16(kb - __bfloat162float(kbh)));
}

// ============================================================================
// Raw-PTX bf16 GEMM: C[M,N] = A[M,K]*B[N,K]^T, 3-term split precision.
// CTA 128x128, 4 warps (64x64 each), Kc=32, 3-stage cp.async, XOR swizzle.
// mode 0: write fp32 C; mode 1: write hi/lo bf16 (Ch, Cl).
// ============================================================================
#define GKC    32
#define GMAT   8192                 /* 128 rows x 64B per matrix */
#define GSTG   (4 * GMAT)           /* 32768 per stage */
#define GSTAGES 3
#define SMEM_G (GSTAGES * GSTG)     /* 98304 */

// swizzled addr of 16B chunk c (0,16,32,48) in row: row*64 + (c ^ ((row&6)<<3))
__device__ __forceinline__ void g_load(
    uint32_t sdst, const __nv_bfloat16* __restrict__ Ah, const __nv_bfloat16* __restrict__ Al,
    const __nv_bfloat16* __restrict__ Bh, const __nv_bfloat16* __restrict__ Bl,
    int m0, int n0, int k0, int K, int tid) {
    const __nv_bfloat16* srcs[4] = {Ah, Al, Bh, Bl};
#pragma unroll
    for (int t = 0; t < 16; ++t) {
        int u = t * 128 + tid;            // 0..2047: 4 mats x 128 rows x 4 chunks
        int mtx = u >> 9;
        int rem = u & 511;
        int row = rem >> 2;
        int c16 = (rem & 3) << 4;
        int gr = (mtx < 2 ? m0 : n0) + row;
        cpa16(sdst + mtx * GMAT + row * 64 + (c16 ^ ((row & 6) << 3)),
              srcs[mtx] + (size_t)gr * K + k0 + (c16 >> 1));
    }
}

__global__ void __launch_bounds__(128) gemm_tc2(
    const __nv_bfloat16* __restrict__ Ah, const __nv_bfloat16* __restrict__ Al,
    const __nv_bfloat16* __restrict__ Bh, const __nv_bfloat16* __restrict__ Bl,
    float* __restrict__ C, __nv_bfloat16* __restrict__ Ch, __nv_bfloat16* __restrict__ Cl,
    int mode, int N, int K) {
    extern __shared__ char smem[];
    const uint32_t sbase = su32(smem);
    const int tid  = threadIdx.x;
    const int wid  = tid >> 5;
    const int lane = tid & 31;
    const int m0 = blockIdx.y * 128;
    const int n0 = blockIdx.x * 128;
    const int wm = (wid & 1) * 64;
    const int wn = (wid >> 1) * 64;
    const int nchunk = K / GKC;          // 64

    float acc[4][8][4];
#pragma unroll
    for (int mi = 0; mi < 4; ++mi)
#pragma unroll
        for (int n8 = 0; n8 < 8; ++n8) {
            acc[mi][n8][0] = 0.f; acc[mi][n8][1] = 0.f;
            acc[mi][n8][2] = 0.f; acc[mi][n8][3] = 0.f;
        }

    g_load(sbase, Ah, Al, Bh, Bl, m0, n0, 0, K, tid);
    CPA_COMMIT();
    g_load(sbase + GSTG, Ah, Al, Bh, Bl, m0, n0, GKC, K, tid);
    CPA_COMMIT();

    const int r15 = lane & 15;
    const uint32_t xv = (uint32_t)((r15 & 6) << 3);
    const uint32_t chalf = (uint32_t)((lane >> 4) << 4);

#pragma unroll 1
    for (int c = 0; c < nchunk; ++c) {
        CPA_WAIT1();
        __syncthreads();
        if (c + 2 < nchunk) {
            g_load(sbase + ((c + 2) % 3) * GSTG, Ah, Al, Bh, Bl,
                   m0, n0, (c + 2) * GKC, K, tid);
            CPA_COMMIT();
        }
        const uint32_t sa = sbase + (c % 3) * GSTG;
#pragma unroll
        for (int ks = 0; ks < 2; ++ks) {
            const uint32_t cc = (uint32_t)(ks * 32) + chalf;
            uint32_t fa[4][4], fal[4][4], fb[4][4], fbl[4][4];
#pragma unroll
            for (int mi = 0; mi < 4; ++mi) {
                uint32_t row = (uint32_t)(wm + mi * 16 + r15);
                uint32_t ad = sa + row * 64 + (cc ^ xv);
                LDSM4(fa[mi][0], fa[mi][1], fa[mi][2], fa[mi][3], ad);
                LDSM4(fal[mi][0], fal[mi][1], fal[mi][2], fal[mi][3], ad + GMAT);
            }
#pragma unroll
            for (int ni = 0; ni < 4; ++ni) {
                uint32_t row = (uint32_t)(wn + ni * 16 + r15);
                uint32_t bd = sa + 2 * GMAT + row * 64 + (cc ^ xv);
                LDSM4(fb[ni][0], fb[ni][1], fb[ni][2], fb[ni][3], bd);
                LDSM4(fbl[ni][0], fbl[ni][1], fbl[ni][2], fbl[ni][3], bd + GMAT);
            }
#pragma unroll
            for (int mi = 0; mi < 4; ++mi)
#pragma unroll
                for (int n8 = 0; n8 < 8; ++n8) {
                    const int ni = n8 >> 1;
                    const int s = n8 & 1;
                    MMA16816(acc[mi][n8], fa[mi][0], fa[mi][1], fa[mi][2], fa[mi][3],
                             fb[ni][s], fb[ni][s + 2]);
                    MMA16816(acc[mi][n8], fa[mi][0], fa[mi][1], fa[mi][2], fa[mi][3],
                             fbl[ni][s], fbl[ni][s + 2]);
                    MMA16816(acc[mi][n8], fal[mi][0], fal[mi][1], fal[mi][2], fal[mi][3],
                             fb[ni][s], fb[ni][s + 2]);
                }
        }
    }

    // ---- epilogue ----
    const int group = lane >> 2;
    const int tig = lane & 3;
#pragma unroll
    for (int mi = 0; mi < 4; ++mi)
#pragma unroll
        for (int n8 = 0; n8 < 8; ++n8) {
            size_t row0 = (size_t)(m0 + wm + mi * 16 + group) * N;
            size_t row1 = row0 + (size_t)8 * N;
            int col = n0 + wn + n8 * 8 + tig * 2;
            float d0 = acc[mi][n8][0], d1 = acc[mi][n8][1];
            float d2 = acc[mi][n8][2], d3 = acc[mi][n8][3];
            if (mode == 0) {
                *(float2*)(C + row0 + col) = make_float2(d0, d1);
                *(float2*)(C + row1 + col) = make_float2(d2, d3);
            } else {
                __nv_bfloat16 h0 = __float2bfloat16(d0), h1 = __float2bfloat16(d1);
                __nv_bfloat16 h2 = __float2bfloat16(d2), h3 = __float2bfloat16(d3);
                *(__nv_bfloat162*)(Ch + row0 + col) = __halves2bfloat162(h0, h1);
                *(__nv_bfloat162*)(Ch + row1 + col) = __halves2bfloat162(h2, h3);
                *(__nv_bfloat162*)(Cl + row0 + col) = __halves2bfloat162(
                    __float2bfloat16(d0 - __bfloat162float(h0)),
                    __float2bfloat16(d1 - __bfloat162float(h1)));
                *(__nv_bfloat162*)(Cl + row1 + col) = __halves2bfloat162(
                    __float2bfloat16(d2 - __bfloat162float(h2)),
                    __float2bfloat16(d3 - __bfloat162float(h3)));
            }
        }
}

// ============================================================================
// Flash attention (unchanged core; epilogue writes ah/al bf16 hi/lo)
// ============================================================================
#define FPITCH 272
#define FKT    (64 * FPITCH)
#define QOFF   0
#define KOFF   (2 * FKT)
#define VOFF   (4 * FKT)
#define SMEM_FLASH (6 * FKT)       /* 104448 */

__device__ __forceinline__ void ld_pair(uint32_t sdst, const __nv_bfloat16* __restrict__ h,
                                        const __nv_bfloat16* __restrict__ l,
                                        int brow0, int hcol, int tid) {
#pragma unroll
    for (int t = 0; t < 16; ++t) {
        int u = t * 128 + tid;
        int mtx = u >> 10;
        int rem = u & 1023;
        int row = rem >> 4;
        int c16 = rem & 15;
        const __nv_bfloat16* src = mtx ? l : h;
        cpa16(sdst + mtx * FKT + row * FPITCH + c16 * 16,
              src + (size_t)(brow0 + row) * D_MODEL + hcol + c16 * 8);
    }
}

__global__ void __launch_bounds__(128) flash_tc() {
    extern __shared__ char smem[];
    const uint32_t sbase = su32(smem);
    const int tid  = threadIdx.x;
    const int wid  = tid >> 5;
    const int lane = tid & 31;
    const int qb   = (int)gridDim.x - 1 - (int)blockIdx.x;
    const int h    = blockIdx.y;
    const int b    = blockIdx.z;
    const int hcol = h * DK;
    const int brow0q = b * SEQ + qb * 64;
    const int group = lane >> 2;
    const int tig   = lane & 3;
    const int qg0   = qb * 64 + wid * 16 + group;

    const float SCL2 = 0.08838834764831845f * 1.4426950408889634f;

    ld_pair(sbase + QOFF, g_qh, g_ql, brow0q, hcol, tid);
    ld_pair(sbase + KOFF, g_kh, g_kl, b * SEQ, hcol, tid);
    CPA_COMMIT();
    ld_pair(sbase + VOFF, g_vh, g_vl, b * SEQ, hcol, tid);
    CPA_COMMIT();

    float oacc[16][4];
#pragma unroll
    for (int f = 0; f < 16; ++f) {
        oacc[f][0] = 0.f; oacc[f][1] = 0.f; oacc[f][2] = 0.f; oacc[f][3] = 0.f;
    }
    float m2[2] = {-1e30f, -1e30f};
    float lsum[2] = {0.f, 0.f};

    const int nt = qb + 1;
    const uint32_t qrow_base = sbase + QOFF + (wid * 16 + (lane & 15)) * FPITCH
                             + (lane >> 4) * 16;
    const uint32_t krow = sbase + KOFF + (lane & 15) * FPITCH + (lane >> 4) * 16;
    const uint32_t vrow = sbase + VOFF
                        + ((lane & 7) + ((lane >> 3) & 1) * 8) * FPITCH
                        + ((lane >> 4) & 1) * 16;

    for (int t = 0; t < nt; ++t) {
        CPA_WAIT1();
        __syncthreads();

        float sacc[8][4];
#pragma unroll
        for (int f = 0; f < 8; ++f) {
            sacc[f][0] = 0.f; sacc[f][1] = 0.f; sacc[f][2] = 0.f; sacc[f][3] = 0.f;
        }
#pragma unroll
        for (int kc = 0; kc < 8; ++kc) {
            uint32_t qa0, qa1, qa2, qa3, ql0, ql1, ql2, ql3;
            LDSM4(qa0, qa1, qa2, qa3, qrow_base + kc * 32);
            LDSM4(ql0, ql1, ql2, ql3, qrow_base + FKT + kc * 32);
#pragma unroll
            for (int nf2 = 0; nf2 < 4; ++nf2) {
                uint32_t kh0, kh1, kh2, kh3, kl0, kl1, kl2, kl3;
                uint32_t ka = krow + nf2 * (16 * FPITCH) + kc * 32;
                LDSM4(kh0, kh1, kh2, kh3, ka);
                LDSM4(kl0, kl1, kl2, kl3, ka + FKT);
                MMA16816(sacc[2 * nf2],     qa0, qa1, qa2, qa3, kh0, kh2);
                MMA16816(sacc[2 * nf2 + 1], qa0, qa1, qa2, qa3, kh1, kh3);
                MMA16816(sacc[2 * nf2],     qa0, qa1, qa2, qa3, kl0, kl2);
                MMA16816(sacc[2 * nf2 + 1], qa0, qa1, qa2, qa3, kl1, kl3);
                MMA16816(sacc[2 * nf2],     ql0, ql1, ql2, ql3, kh0, kh2);
                MMA16816(sacc[2 * nf2 + 1], ql0, ql1, ql2, ql3, kh1, kh3);
            }
        }
        __syncthreads();
        if (t + 1 < nt) {
            ld_pair(sbase + KOFF, g_kh, g_kl, b * SEQ + (t + 1) * 64, hcol, tid);
            CPA_COMMIT();
        }

        if (t == qb) {
            const int j0 = t * 64;
#pragma unroll
            for (int f = 0; f < 8; ++f) {
                int col = j0 + f * 8 + tig * 2;
                if (col > qg0)          sacc[f][0] = -1e30f;
                if (col + 1 > qg0)      sacc[f][1] = -1e30f;
                if (col > qg0 + 8)      sacc[f][2] = -1e30f;
                if (col + 1 > qg0 + 8)  sacc[f][3] = -1e30f;
            }
        }

        float mn0 = -1e30f, mn1 = -1e30f;
#pragma unroll
        for (int f = 0; f < 8; ++f) {
            mn0 = fmaxf(mn0, fmaxf(sacc[f][0], sacc[f][1]));
            mn1 = fmaxf(mn1, fmaxf(sacc[f][2], sacc[f][3]));
        }
        mn0 = fmaxf(mn0, __shfl_xor_sync(0xffffffffu, mn0, 1));
        mn0 = fmaxf(mn0, __shfl_xor_sync(0xffffffffu, mn0, 2));
        mn1 = fmaxf(mn1, __shfl_xor_sync(0xffffffffu, mn1, 1));
        mn1 = fmaxf(mn1, __shfl_xor_sync(0xffffffffu, mn1, 2));
        float mN0 = fmaxf(m2[0], mn0), mN1 = fmaxf(m2[1], mn1);
        float corr0 = exp2ff(SCL2 * (m2[0] - mN0));
        float corr1 = exp2ff(SCL2 * (m2[1] - mN1));
        m2[0] = mN0; m2[1] = mN1;
        const float b0 = mN0 * SCL2, b1 = mN1 * SCL2;

        float ls0 = 0.f, ls1 = 0.f;
#pragma unroll
        for (int f = 0; f < 8; ++f) {
            sacc[f][0] = exp2ff(fmaf(sacc[f][0], SCL2, -b0));
            sacc[f][1] = exp2ff(fmaf(sacc[f][1], SCL2, -b0));
            sacc[f][2] = exp2ff(fmaf(sacc[f][2], SCL2, -b1));
            sacc[f][3] = exp2ff(fmaf(sacc[f][3], SCL2, -b1));
            ls0 += sacc[f][0] + sacc[f][1];
            ls1 += sacc[f][2] + sacc[f][3];
        }
        ls0 += __shfl_xor_sync(0xffffffffu, ls0, 1);
        ls0 += __shfl_xor_sync(0xffffffffu, ls0, 2);
        ls1 += __shfl_xor_sync(0xffffffffu, ls1, 1);
        ls1 += __shfl_xor_sync(0xffffffffu, ls1, 2);
        lsum[0] = lsum[0] * corr0 + ls0;
        lsum[1] = lsum[1] * corr1 + ls1;

#pragma unroll
        for (int f = 0; f < 16; ++f) {
            oacc[f][0] *= corr0; oacc[f][1] *= corr0;
            oacc[f][2] *= corr1; oacc[f][3] *= corr1;
        }

        if (t + 1 < nt) CPA_WAIT1(); else CPA_WAIT0();
        __syncthreads();

#pragma unroll
        for (int kc = 0; kc < 4; ++kc) {
            const int f0 = 2 * kc, f1 = 2 * kc + 1;
            uint32_t ph0 = packbf(sacc[f0][0], sacc[f0][1]);
            uint32_t ph1 = packbf(sacc[f0][2], sacc[f0][3]);
            uint32_t ph2 = packbf(sacc[f1][0], sacc[f1][1]);
            uint32_t ph3 = packbf(sacc[f1][2], sacc[f1][3]);
            uint32_t pl0 = packbf(bfres(sacc[f0][0]), bfres(sacc[f0][1]));
            uint32_t pl1 = packbf(bfres(sacc[f0][2]), bfres(sacc[f0][3]));
            uint32_t pl2 = packbf(bfres(sacc[f1][0]), bfres(sacc[f1][1]));
            uint32_t pl3 = packbf(bfres(sacc[f1][2]), bfres(sacc[f1][3]));
#pragma unroll
            for (int nf2 = 0; nf2 < 8; ++nf2) {
                uint32_t va = vrow + kc * (16 * FPITCH) + nf2 * 32;
                uint32_t v0, v1, v2, v3, u0, u1, u2, u3;
                LDSM4T(v0, v1, v2, v3, va);
                LDSM4T(u0, u1, u2, u3, va + FKT);
                MMA16816(oacc[2 * nf2],     ph0, ph1, ph2, ph3, v0, v1);
                MMA16816(oacc[2 * nf2 + 1], ph0, ph1, ph2, ph3, v2, v3);
                MMA16816(oacc[2 * nf2],     ph0, ph1, ph2, ph3, u0, u1);
                MMA16816(oacc[2 * nf2 + 1], ph0, ph1, ph2, ph3, u2, u3);
                MMA16816(oacc[2 * nf2],     pl0, pl1, pl2, pl3, v0, v1);
                MMA16816(oacc[2 * nf2 + 1], pl0, pl1, pl2, pl3, v2, v3);
            }
        }
        __syncthreads();
        if (t + 1 < nt) {
            ld_pair(sbase + VOFF, g_vh, g_vl, b * SEQ + (t + 1) * 64, hcol, tid);
            CPA_COMMIT();
        }
    }

    // ---- epilogue: write ah/al bf16 hi/lo directly ----
    const float inv0 = 1.0f / lsum[0];
    const float inv1 = 1.0f / lsum[1];
    size_t r0 = (size_t)(brow0q + wid * 16 + group) * D_MODEL + hcol;
    size_t r1 = r0 + (size_t)8 * D_MODEL;
#pragma unroll
    for (int f = 0; f < 16; ++f) {
        const int col = f * 8 + tig * 2;
        float o0 = oacc[f][0] * inv0, o1 = oacc[f][1] * inv0;
        float o2 = oacc[f][2] * inv1, o3 = oacc[f][3] * inv1;
        __nv_bfloat16 h0 = __float2bfloat16(o0), h1 = __float2bfloat16(o1);
        __nv_bfloat16 h2 = __float2bfloat16(o2), h3 = __float2bfloat16(o3);
        *(__nv_bfloat162*)(g_ah + r0 + col) = __halves2bfloat162(h0, h1);
        *(__nv_bfloat162*)(g_ah + r1 + col) = __halves2bfloat162(h2, h3);
        *(__nv_bfloat162*)(g_al + r0 + col) = __halves2bfloat162(
            __float2bfloat16(o0 - __bfloat162float(h0)),
            __float2bfloat16(o1 - __bfloat162float(h1)));
        *(__nv_bfloat162*)(g_al + r1 + col) = __halves2bfloat162(
            __float2bfloat16(o2 - __bfloat162float(h2)),
            __float2bfloat16(o3 - __bfloat162float(h3)));
    }
}

// ---------------- launch ----------------
extern "C" void kernel_launch(void* const* d_in, const int* in_sizes, int n_in,
                              void* d_out, int out_size) {
    const float* x  = (const float*)d_in[0];
    const float* Wq = (const float*)d_in[2];
    const float* Wk = (const float*)d_in[3];
    const float* Wv = (const float*)d_in[4];
    const float* Wo = (const float*)d_in[5];
    float* out = (float*)d_out;

    float *pQ, *pK;
    cudaGetSymbolAddress((void**)&pQ, g_Q);
    cudaGetSymbolAddress((void**)&pK, g_K);
    __nv_bfloat16 *xh, *xl, *wqh, *wql, *wkh, *wkl, *wvh, *wvl, *woh, *wol, *ah, *al, *vh, *vl;
    cudaGetSymbolAddress((void**)&xh, g_xh);   cudaGetSymbolAddress((void**)&xl, g_xl);
    cudaGetSymbolAddress((void**)&wqh, g_wqh); cudaGetSymbolAddress((void**)&wql, g_wql);
    cudaGetSymbolAddress((void**)&wkh, g_wkh); cudaGetSymbolAddress((void**)&wkl, g_wkl);
    cudaGetSymbolAddress((void**)&wvh, g_wvh); cudaGetSymbolAddress((void**)&wvl, g_wvl);
    cudaGetSymbolAddress((void**)&woh, g_woh); cudaGetSymbolAddress((void**)&wol, g_wol);
    cudaGetSymbolAddress((void**)&ah, g_ah);   cudaGetSymbolAddress((void**)&al, g_al);
    cudaGetSymbolAddress((void**)&vh, g_vh);   cudaGetSymbolAddress((void**)&vl, g_vl);

    cudaFuncSetAttribute(gemm_tc2, cudaFuncAttributeMaxDynamicSharedMemorySize, SMEM_G);
    cudaFuncSetAttribute(flash_tc, cudaFuncAttributeMaxDynamicSharedMemorySize, SMEM_FLASH);

    dim3 gg(D_MODEL / 128, MROWS / 128);   // (16, 32)

    prep_kernel<<<8704 + 4 * 4096, 256>>>(x, Wq, Wk, Wv, Wo);                       // 0
    gemm_tc2<<<gg, 128, SMEM_G>>>(xh, xl, wqh, wql, pQ, nullptr, nullptr, 0,
                                  D_MODEL, D_MODEL);                                // 1
    gemm_tc2<<<gg, 128, SMEM_G>>>(xh, xl, wkh, wkl, pK, nullptr, nullptr, 0,
                                  D_MODEL, D_MODEL);                                // 2
    gemm_tc2<<<gg, 128, SMEM_G>>>(xh, xl, wvh, wvl, nullptr, vh, vl, 1,
                                  D_MODEL, D_MODEL);                                // 3
    rope_qk<<<16384, 256>>>();                                                      // 4
    flash_tc<<<dim3(SEQ / 64, NHEADS, BATCH), 128, SMEM_FLASH>>>();                 // 5
    gemm_tc2<<<gg, 128, SMEM_G>>>(ah, al, woh, wol, out, nullptr, nullptr, 0,
                                  D_MODEL, D_MODEL);                                // 6
}

// round 10
// speedup vs baseline: 3.5190x; 1.0015x over previous
#include <cuda_runtime.h>
#include <cuda_bf16.h>
#include <cstdint>
#include <math.h>

#define D_MODEL 2048
#define SEQ     2048
#define BATCH   2
#define NHEADS  16
#define DK      128
#define MROWS   (BATCH*SEQ)   /* 4096 */

// ---------------- scratch ----------------
__device__ float g_cos[SEQ * (DK / 2)];
__device__ float g_sin[SEQ * (DK / 2)];

__device__ __nv_bfloat16 g_xh[(size_t)MROWS * D_MODEL];
__device__ __nv_bfloat16 g_xl[(size_t)MROWS * D_MODEL];
__device__ __nv_bfloat16 g_wqh[(size_t)D_MODEL * D_MODEL];
__device__ __nv_bfloat16 g_wql[(size_t)D_MODEL * D_MODEL];
__device__ __nv_bfloat16 g_wkh[(size_t)D_MODEL * D_MODEL];
__device__ __nv_bfloat16 g_wkl[(size_t)D_MODEL * D_MODEL];
__device__ __nv_bfloat16 g_wvh[(size_t)D_MODEL * D_MODEL];
__device__ __nv_bfloat16 g_wvl[(size_t)D_MODEL * D_MODEL];
__device__ __nv_bfloat16 g_woh[(size_t)D_MODEL * D_MODEL];
__device__ __nv_bfloat16 g_wol[(size_t)D_MODEL * D_MODEL];
__device__ __nv_bfloat16 g_ah[(size_t)MROWS * D_MODEL];
__device__ __nv_bfloat16 g_al[(size_t)MROWS * D_MODEL];

__device__ __nv_bfloat16 g_qh[(size_t)MROWS * D_MODEL];
__device__ __nv_bfloat16 g_ql[(size_t)MROWS * D_MODEL];
__device__ __nv_bfloat16 g_kh[(size_t)MROWS * D_MODEL];
__device__ __nv_bfloat16 g_kl[(size_t)MROWS * D_MODEL];
__device__ __nv_bfloat16 g_vh[(size_t)MROWS * D_MODEL];
__device__ __nv_bfloat16 g_vl[(size_t)MROWS * D_MODEL];

// ---------------- PTX helpers ----------------
__device__ __forceinline__ void cpa16(uint32_t dst, const void* src) {
    asm volatile("cp.async.cg.shared.global [%0], [%1], 16;" :: "r"(dst), "l"(src));
}
#define CPA_COMMIT() asm volatile("cp.async.commit_group;" ::: "memory")
#define CPA_WAIT0()  asm volatile("cp.async.wait_group 0;" ::: "memory")
#define CPA_WAIT1()  asm volatile("cp.async.wait_group 1;" ::: "memory")

__device__ __forceinline__ uint32_t su32(const void* p) {
    uint32_t a;
    asm("{ .reg .u64 t; cvta.to.shared.u64 t, %1; cvt.u32.u64 %0, t; }" : "=r"(a) : "l"(p));
    return a;
}

#define LDSM4(r0, r1, r2, r3, a) \
    asm volatile("ldmatrix.sync.aligned.m8n8.x4.shared.b16 {%0,%1,%2,%3}, [%4];" \
                 : "=r"(r0), "=r"(r1), "=r"(r2), "=r"(r3) : "r"(a))
#define LDSM4T(r0, r1, r2, r3, a) \
    asm volatile("ldmatrix.sync.aligned.m8n8.x4.trans.shared.b16 {%0,%1,%2,%3}, [%4];" \
                 : "=r"(r0), "=r"(r1), "=r"(r2), "=r"(r3) : "r"(a))
#define MMA16816(d, a0, a1, a2, a3, b0, b1) \
    asm volatile("mma.sync.aligned.m16n8k16.row.col.f32.bf16.bf16.f32 " \
                 "{%0,%1,%2,%3}, {%4,%5,%6,%7}, {%8,%9}, {%0,%1,%2,%3};" \
                 : "+f"((d)[0]), "+f"((d)[1]), "+f"((d)[2]), "+f"((d)[3]) \
                 : "r"(a0), "r"(a1), "r"(a2), "r"(a3), "r"(b0), "r"(b1))

__device__ __forceinline__ uint32_t packbf(float lo, float hi) {
    uint32_t u;
    asm("cvt.rn.bf16x2.f32 %0, %1, %2;" : "=r"(u) : "f"(hi), "f"(lo));
    return u;
}
__device__ __forceinline__ float bfres(float x) {
    return x - __bfloat162float(__float2bfloat16(x));
}

// fast exp2 on FMA pipe (arg <= 0)
__device__ __forceinline__ float exp2ff(float x) {
    x = fmaxf(x, -126.0f);
    float fl = floorf(x);
    float f = x - fl;
    float p = 1.54035304e-4f;
    p = fmaf(p, f, 1.33335581e-3f);
    p = fmaf(p, f, 9.61812910e-3f);
    p = fmaf(p, f, 5.55041086e-2f);
    p = fmaf(p, f, 2.40226512e-1f);
    p = fmaf(p, f, 6.93147182e-1f);
    p = fmaf(p, f, 1.0f);
    return __uint_as_float((uint32_t)((int)fl + 127) << 23) * p;
}

// ---------------- split helper ----------------
__device__ __forceinline__ void split4(const float* __restrict__ src,
                                       __nv_bfloat16* __restrict__ hi,
                                       __nv_bfloat16* __restrict__ lo, int i) {
    float4 v = ((const float4*)src)[i];
    __nv_bfloat16 h0 = __float2bfloat16(v.x);
    __nv_bfloat16 h1 = __float2bfloat16(v.y);
    __nv_bfloat16 h2 = __float2bfloat16(v.z);
    __nv_bfloat16 h3 = __float2bfloat16(v.w);
    __nv_bfloat16 l0 = __float2bfloat16(v.x - __bfloat162float(h0));
    __nv_bfloat16 l1 = __float2bfloat16(v.y - __bfloat162float(h1));
    __nv_bfloat16 l2 = __float2bfloat16(v.z - __bfloat162float(h2));
    __nv_bfloat16 l3 = __float2bfloat16(v.w - __bfloat162float(h3));
    uint2 hp, lp;
    hp.x = (uint32_t)__bfloat16_as_ushort(h0) | ((uint32_t)__bfloat16_as_ushort(h1) << 16);
    hp.y = (uint32_t)__bfloat16_as_ushort(h2) | ((uint32_t)__bfloat16_as_ushort(h3) << 16);
    lp.x = (uint32_t)__bfloat16_as_ushort(l0) | ((uint32_t)__bfloat16_as_ushort(l1) << 16);
    lp.y = (uint32_t)__bfloat16_as_ushort(l2) | ((uint32_t)__bfloat16_as_ushort(l3) << 16);
    ((uint2*)hi)[i] = hp;
    ((uint2*)lo)[i] = lp;
}

// ---------------- fused prep: rope tables + input/weight splits --------------
__global__ void prep_kernel(const float* __restrict__ x,
                            const float* __restrict__ Wq, const float* __restrict__ Wk,
                            const float* __restrict__ Wv, const float* __restrict__ Wo) {
    int bid = blockIdx.x;
    int t = threadIdx.x;
    if (bid < 512) {
        int idx = bid * 256 + t;
        int s = idx >> 6;
        int i = idx & 63;
        float th = powf(10000.0f, (float)i * (1.0f / 64.0f));
        float ph = (float)s / th;          // fp32 rounding matches reference
        double phd = (double)ph;
        g_cos[idx] = (float)cos(phd);
        g_sin[idx] = (float)sin(phd);
    } else if (bid < 8704) {
        split4(x, g_xh, g_xl, (bid - 512) * 256 + t);
    } else {
        int r = bid - 8704;
        int which = r >> 12;
        int i = (r & 4095) * 256 + t;
        if (which == 0)      split4(Wq, g_wqh, g_wql, i);
        else if (which == 1) split4(Wk, g_wkh, g_wkl, i);
        else if (which == 2) split4(Wv, g_wvh, g_wvl, i);
        else                 split4(Wo, g_woh, g_wol, i);
    }
}

// ============================================================================
// Raw-PTX bf16 GEMM: C[M,N] = A[M,K]*B[N,K]^T, 3-term split precision.
// CTA 128x128, 8 warps (64x32 each), Kc=32, 3-stage cp.async, XOR swizzle.
// 256 thr, __launch_bounds__(256,2) -> <=128 regs -> 2 CTAs/SM (16 warps).
// mode 0: fp32 C; mode 1: bf16 hi/lo (Ch,Cl); mode 2: RoPE then bf16 hi/lo.
// ============================================================================
#define GKC    32
#define GMAT   8192                 /* 128 rows x 64B per matrix */
#define GSTG   (4 * GMAT)           /* 32768 per stage */
#define SMEM_G (3 * GSTG)           /* 98304 */

__device__ __forceinline__ void g_load(
    uint32_t sdst, const __nv_bfloat16* __restrict__ Ah, const __nv_bfloat16* __restrict__ Al,
    const __nv_bfloat16* __restrict__ Bh, const __nv_bfloat16* __restrict__ Bl,
    int m0, int n0, int k0, int K, int tid) {
    const __nv_bfloat16* srcs[4] = {Ah, Al, Bh, Bl};
#pragma unroll
    for (int t = 0; t < 8; ++t) {
        int u = t * 256 + tid;            // 0..2047: 4 mats x 128 rows x 4 chunks
        int mtx = u >> 9;
        int rem = u & 511;
        int row = rem >> 2;
        int c16 = (rem & 3) << 4;
        int gr = (mtx < 2 ? m0 : n0) + row;
        cpa16(sdst + mtx * GMAT + row * 64 + (c16 ^ ((row & 6) << 3)),
              srcs[mtx] + (size_t)gr * K + k0 + (c16 >> 1));
    }
}

__global__ void __launch_bounds__(256, 2) gemm_tc2(
    const __nv_bfloat16* __restrict__ Ah, const __nv_bfloat16* __restrict__ Al,
    const __nv_bfloat16* __restrict__ Bh, const __nv_bfloat16* __restrict__ Bl,
    float* __restrict__ C, __nv_bfloat16* __restrict__ Ch, __nv_bfloat16* __restrict__ Cl,
    int mode, int N, int K) {
    extern __shared__ char smem[];
    const uint32_t sbase = su32(smem);
    const int tid  = threadIdx.x;
    const int wid  = tid >> 5;
    const int lane = tid & 31;
    const int m0 = blockIdx.y * 128;
    const int n0 = blockIdx.x * 128;
    const int wm = (wid & 1) * 64;        // 2x4 grid of 64x32 warp tiles
    const int wn = (wid >> 1) * 32;
    const int nchunk = K / GKC;           // 64

    float acc[4][4][4];
#pragma unroll
    for (int mi = 0; mi < 4; ++mi)
#pragma unroll
        for (int n8 = 0; n8 < 4; ++n8) {
            acc[mi][n8][0] = 0.f; acc[mi][n8][1] = 0.f;
            acc[mi][n8][2] = 0.f; acc[mi][n8][3] = 0.f;
        }

    g_load(sbase, Ah, Al, Bh, Bl, m0, n0, 0, K, tid);
    CPA_COMMIT();
    g_load(sbase + GSTG, Ah, Al, Bh, Bl, m0, n0, GKC, K, tid);
    CPA_COMMIT();

    const int r15 = lane & 15;
    const uint32_t xv = (uint32_t)((r15 & 6) << 3);
    const uint32_t chalf = (uint32_t)((lane >> 4) << 4);

#pragma unroll 1
    for (int c = 0; c < nchunk; ++c) {
        CPA_WAIT1();
        __syncthreads();
        if (c + 2 < nchunk) {
            g_load(sbase + ((c + 2) % 3) * GSTG, Ah, Al, Bh, Bl,
                   m0, n0, (c + 2) * GKC, K, tid);
            CPA_COMMIT();
        }
        const uint32_t sa = sbase + (c % 3) * GSTG;
#pragma unroll
        for (int ks = 0; ks < 2; ++ks) {
            const uint32_t cc = (uint32_t)(ks * 32) + chalf;
            // B frags for this warp's 32 cols (2 x 16-row groups), hi+lo
            uint32_t fb[2][4], fbl[2][4];
#pragma unroll
            for (int ni = 0; ni < 2; ++ni) {
                uint32_t row = (uint32_t)(wn + ni * 16 + r15);
                uint32_t bd = sa + 2 * GMAT + row * 64 + (cc ^ xv);
                LDSM4(fb[ni][0], fb[ni][1], fb[ni][2], fb[ni][3], bd);
                LDSM4(fbl[ni][0], fbl[ni][1], fbl[ni][2], fbl[ni][3], bd + GMAT);
            }
            // stream A frags per mi (small live set; LDSM/MMA overlap across mi)
#pragma unroll
            for (int mi = 0; mi < 4; ++mi) {
                uint32_t row = (uint32_t)(wm + mi * 16 + r15);
                uint32_t ad = sa + row * 64 + (cc ^ xv);
                uint32_t fa0, fa1, fa2, fa3, fl0, fl1, fl2, fl3;
                LDSM4(fa0, fa1, fa2, fa3, ad);
                LDSM4(fl0, fl1, fl2, fl3, ad + GMAT);
#pragma unroll
                for (int n8 = 0; n8 < 4; ++n8) {
                    const int ni = n8 >> 1;
                    const int s = n8 & 1;
                    MMA16816(acc[mi][n8], fa0, fa1, fa2, fa3, fb[ni][s], fb[ni][s + 2]);
                    MMA16816(acc[mi][n8], fa0, fa1, fa2, fa3, fbl[ni][s], fbl[ni][s + 2]);
                    MMA16816(acc[mi][n8], fl0, fl1, fl2, fl3, fb[ni][s], fb[ni][s + 2]);
                }
            }
        }
    }

    // ---- epilogue ----
    const int group = lane >> 2;
    const int tig = lane & 3;
#pragma unroll
    for (int mi = 0; mi < 4; ++mi)
#pragma unroll
        for (int n8 = 0; n8 < 4; ++n8) {
            int grow = m0 + wm + mi * 16 + group;
            size_t row0 = (size_t)grow * N;
            size_t row1 = row0 + (size_t)8 * N;
            int col = n0 + wn + n8 * 8 + tig * 2;
            float d0 = acc[mi][n8][0], d1 = acc[mi][n8][1];
            float d2 = acc[mi][n8][2], d3 = acc[mi][n8][3];
            if (mode == 0) {
                *(float2*)(C + row0 + col) = make_float2(d0, d1);
                *(float2*)(C + row1 + col) = make_float2(d2, d3);
            } else {
                if (mode == 2) {   // RoPE on the interleaved pair (d0,d1),(d2,d3)
                    int i = ((wn + n8 * 8) >> 1) + tig;      // pair index in head
                    int s0 = grow & (SEQ - 1);
                    float c0 = g_cos[s0 * 64 + i], sn0 = g_sin[s0 * 64 + i];
                    float c1 = g_cos[(s0 + 8) * 64 + i], sn1 = g_sin[(s0 + 8) * 64 + i];
                    float t0 = d0 * c0 - d1 * sn0, t1 = d0 * sn0 + d1 * c0;
                    float t2 = d2 * c1 - d3 * sn1, t3 = d2 * sn1 + d3 * c1;
                    d0 = t0; d1 = t1; d2 = t2; d3 = t3;
                }
                __nv_bfloat16 h0 = __float2bfloat16(d0), h1 = __float2bfloat16(d1);
                __nv_bfloat16 h2 = __float2bfloat16(d2), h3 = __float2bfloat16(d3);
                *(__nv_bfloat162*)(Ch + row0 + col) = __halves2bfloat162(h0, h1);
                *(__nv_bfloat162*)(Ch + row1 + col) = __halves2bfloat162(h2, h3);
                *(__nv_bfloat162*)(Cl + row0 + col) = __halves2bfloat162(
                    __float2bfloat16(d0 - __bfloat162float(h0)),
                    __float2bfloat16(d1 - __bfloat162float(h1)));
                *(__nv_bfloat162*)(Cl + row1 + col) = __halves2bfloat162(
                    __float2bfloat16(d2 - __bfloat162float(h2)),
                    __float2bfloat16(d3 - __bfloat162float(h3)));
            }
        }
}

// ============================================================================
// Flash attention (unchanged core; epilogue writes ah/al bf16 hi/lo)
// ============================================================================
#define FPITCH 272
#define FKT    (64 * FPITCH)
#define QOFF   0
#define KOFF   (2 * FKT)
#define VOFF   (4 * FKT)
#define SMEM_FLASH (6 * FKT)       /* 104448 */

__device__ __forceinline__ void ld_pair(uint32_t sdst, const __nv_bfloat16* __restrict__ h,
                                        const __nv_bfloat16* __restrict__ l,
                                        int brow0, int hcol, int tid) {
#pragma unroll
    for (int t = 0; t < 16; ++t) {
        int u = t * 128 + tid;
        int mtx = u >> 10;
        int rem = u & 1023;
        int row = rem >> 4;
        int c16 = rem & 15;
        const __nv_bfloat16* src = mtx ? l : h;
        cpa16(sdst + mtx * FKT + row * FPITCH + c16 * 16,
              src + (size_t)(brow0 + row) * D_MODEL + hcol + c16 * 8);
    }
}

__global__ void __launch_bounds__(128) flash_tc() {
    extern __shared__ char smem[];
    const uint32_t sbase = su32(smem);
    const int tid  = threadIdx.x;
    const int wid  = tid >> 5;
    const int lane = tid & 31;
    const int qb   = (int)gridDim.x - 1 - (int)blockIdx.x;
    const int h    = blockIdx.y;
    const int b    = blockIdx.z;
    const int hcol = h * DK;
    const int brow0q = b * SEQ + qb * 64;
    const int group = lane >> 2;
    const int tig   = lane & 3;
    const int qg0   = qb * 64 + wid * 16 + group;

    const float SCL2 = 0.08838834764831845f * 1.4426950408889634f;

    ld_pair(sbase + QOFF, g_qh, g_ql, brow0q, hcol, tid);
    ld_pair(sbase + KOFF, g_kh, g_kl, b * SEQ, hcol, tid);
    CPA_COMMIT();
    ld_pair(sbase + VOFF, g_vh, g_vl, b * SEQ, hcol, tid);
    CPA_COMMIT();

    float oacc[16][4];
#pragma unroll
    for (int f = 0; f < 16; ++f) {
        oacc[f][0] = 0.f; oacc[f][1] = 0.f; oacc[f][2] = 0.f; oacc[f][3] = 0.f;
    }
    float m2[2] = {-1e30f, -1e30f};
    float lsum[2] = {0.f, 0.f};

    const int nt = qb + 1;
    const uint32_t qrow_base = sbase + QOFF + (wid * 16 + (lane & 15)) * FPITCH
                             + (lane >> 4) * 16;
    const uint32_t krow = sbase + KOFF + (lane & 15) * FPITCH + (lane >> 4) * 16;
    const uint32_t vrow = sbase + VOFF
                        + ((lane & 7) + ((lane >> 3) & 1) * 8) * FPITCH
                        + ((lane >> 4) & 1) * 16;

    for (int t = 0; t < nt; ++t) {
        CPA_WAIT1();
        __syncthreads();

        float sacc[8][4];
#pragma unroll
        for (int f = 0; f < 8; ++f) {
            sacc[f][0] = 0.f; sacc[f][1] = 0.f; sacc[f][2] = 0.f; sacc[f][3] = 0.f;
        }
#pragma unroll
        for (int kc = 0; kc < 8; ++kc) {
            uint32_t qa0, qa1, qa2, qa3, ql0, ql1, ql2, ql3;
            LDSM4(qa0, qa1, qa2, qa3, qrow_base + kc * 32);
            LDSM4(ql0, ql1, ql2, ql3, qrow_base + FKT + kc * 32);
#pragma unroll
            for (int nf2 = 0; nf2 < 4; ++nf2) {
                uint32_t kh0, kh1, kh2, kh3, kl0, kl1, kl2, kl3;
                uint32_t ka = krow + nf2 * (16 * FPITCH) + kc * 32;
                LDSM4(kh0, kh1, kh2, kh3, ka);
                LDSM4(kl0, kl1, kl2, kl3, ka + FKT);
                MMA16816(sacc[2 * nf2],     qa0, qa1, qa2, qa3, kh0, kh2);
                MMA16816(sacc[2 * nf2 + 1], qa0, qa1, qa2, qa3, kh1, kh3);
                MMA16816(sacc[2 * nf2],     qa0, qa1, qa2, qa3, kl0, kl2);
                MMA16816(sacc[2 * nf2 + 1], qa0, qa1, qa2, qa3, kl1, kl3);
                MMA16816(sacc[2 * nf2],     ql0, ql1, ql2, ql3, kh0, kh2);
                MMA16816(sacc[2 * nf2 + 1], ql0, ql1, ql2, ql3, kh1, kh3);
            }
        }
        __syncthreads();
        if (t + 1 < nt) {
            ld_pair(sbase + KOFF, g_kh, g_kl, b * SEQ + (t + 1) * 64, hcol, tid);
            CPA_COMMIT();
        }

        if (t == qb) {
            const int j0 = t * 64;
#pragma unroll
            for (int f = 0; f < 8; ++f) {
                int col = j0 + f * 8 + tig * 2;
                if (col > qg0)          sacc[f][0] = -1e30f;
                if (col + 1 > qg0)      sacc[f][1] = -1e30f;
                if (col > qg0 + 8)      sacc[f][2] = -1e30f;
                if (col + 1 > qg0 + 8)  sacc[f][3] = -1e30f;
            }
        }

        float mn0 = -1e30f, mn1 = -1e30f;
#pragma unroll
        for (int f = 0; f < 8; ++f) {
            mn0 = fmaxf(mn0, fmaxf(sacc[f][0], sacc[f][1]));
            mn1 = fmaxf(mn1, fmaxf(sacc[f][2], sacc[f][3]));
        }
        mn0 = fmaxf(mn0, __shfl_xor_sync(0xffffffffu, mn0, 1));
        mn0 = fmaxf(mn0, __shfl_xor_sync(0xffffffffu, mn0, 2));
        mn1 = fmaxf(mn1, __shfl_xor_sync(0xffffffffu, mn1, 1));
        mn1 = fmaxf(mn1, __shfl_xor_sync(0xffffffffu, mn1, 2));
        float mN0 = fmaxf(m2[0], mn0), mN1 = fmaxf(m2[1], mn1);
        float corr0 = exp2ff(SCL2 * (m2[0] - mN0));
        float corr1 = exp2ff(SCL2 * (m2[1] - mN1));
        m2[0] = mN0; m2[1] = mN1;
        const float b0 = mN0 * SCL2, b1 = mN1 * SCL2;

        float ls0 = 0.f, ls1 = 0.f;
#pragma unroll
        for (int f = 0; f < 8; ++f) {
            sacc[f][0] = exp2ff(fmaf(sacc[f][0], SCL2, -b0));
            sacc[f][1] = exp2ff(fmaf(sacc[f][1], SCL2, -b0));
            sacc[f][2] = exp2ff(fmaf(sacc[f][2], SCL2, -b1));
            sacc[f][3] = exp2ff(fmaf(sacc[f][3], SCL2, -b1));
            ls0 += sacc[f][0] + sacc[f][1];
            ls1 += sacc[f][2] + sacc[f][3];
        }
        ls0 += __shfl_xor_sync(0xffffffffu, ls0, 1);
        ls0 += __shfl_xor_sync(0xffffffffu, ls0, 2);
        ls1 += __shfl_xor_sync(0xffffffffu, ls1, 1);
        ls1 += __shfl_xor_sync(0xffffffffu, ls1, 2);
        lsum[0] = lsum[0] * corr0 + ls0;
        lsum[1] = lsum[1] * corr1 + ls1;

#pragma unroll
        for (int f = 0; f < 16; ++f) {
            oacc[f][0] *= corr0; oacc[f][1] *= corr0;
            oacc[f][2] *= corr1; oacc[f][3] *= corr1;
        }

        if (t + 1 < nt) CPA_WAIT1(); else CPA_WAIT0();
        __syncthreads();

#pragma unroll
        for (int kc = 0; kc < 4; ++kc) {
            const int f0 = 2 * kc, f1 = 2 * kc + 1;
            uint32_t ph0 = packbf(sacc[f0][0], sacc[f0][1]);
            uint32_t ph1 = packbf(sacc[f0][2], sacc[f0][3]);
            uint32_t ph2 = packbf(sacc[f1][0], sacc[f1][1]);
            uint32_t ph3 = packbf(sacc[f1][2], sacc[f1][3]);
            uint32_t pl0 = packbf(bfres(sacc[f0][0]), bfres(sacc[f0][1]));
            uint32_t pl1 = packbf(bfres(sacc[f0][2]), bfres(sacc[f0][3]));
            uint32_t pl2 = packbf(bfres(sacc[f1][0]), bfres(sacc[f1][1]));
            uint32_t pl3 = packbf(bfres(sacc[f1][2]), bfres(sacc[f1][3]));
#pragma unroll
            for (int nf2 = 0; nf2 < 8; ++nf2) {
                uint32_t va = vrow + kc * (16 * FPITCH) + nf2 * 32;
                uint32_t v0, v1, v2, v3, u0, u1, u2, u3;
                LDSM4T(v0, v1, v2, v3, va);
                LDSM4T(u0, u1, u2, u3, va + FKT);
                MMA16816(oacc[2 * nf2],     ph0, ph1, ph2, ph3, v0, v1);
                MMA16816(oacc[2 * nf2 + 1], ph0, ph1, ph2, ph3, v2, v3);
                MMA16816(oacc[2 * nf2],     ph0, ph1, ph2, ph3, u0, u1);
                MMA16816(oacc[2 * nf2 + 1], ph0, ph1, ph2, ph3, u2, u3);
                MMA16816(oacc[2 * nf2],     pl0, pl1, pl2, pl3, v0, v1);
                MMA16816(oacc[2 * nf2 + 1], pl0, pl1, pl2, pl3, v2, v3);
            }
        }
        __syncthreads();
        if (t + 1 < nt) {
            ld_pair(sbase + VOFF, g_vh, g_vl, b * SEQ + (t + 1) * 64, hcol, tid);
            CPA_COMMIT();
        }
    }

    const float inv0 = 1.0f / lsum[0];
    const float inv1 = 1.0f / lsum[1];
    size_t r0 = (size_t)(brow0q + wid * 16 + group) * D_MODEL + hcol;
    size_t r1 = r0 + (size_t)8 * D_MODEL;
#pragma unroll
    for (int f = 0; f < 16; ++f) {
        const int col = f * 8 + tig * 2;
        float o0 = oacc[f][0] * inv0, o1 = oacc[f][1] * inv0;
        float o2 = oacc[f][2] * inv1, o3 = oacc[f][3] * inv1;
        __nv_bfloat16 h0 = __float2bfloat16(o0), h1 = __float2bfloat16(o1);
        __nv_bfloat16 h2 = __float2bfloat16(o2), h3 = __float2bfloat16(o3);
        *(__nv_bfloat162*)(g_ah + r0 + col) = __halves2bfloat162(h0, h1);
        *(__nv_bfloat162*)(g_ah + r1 + col) = __halves2bfloat162(h2, h3);
        *(__nv_bfloat162*)(g_al + r0 + col) = __halves2bfloat162(
            __float2bfloat16(o0 - __bfloat162float(h0)),
            __float2bfloat16(o1 - __bfloat162float(h1)));
        *(__nv_bfloat162*)(g_al + r1 + col) = __halves2bfloat162(
            __float2bfloat16(o2 - __bfloat162float(h2)),
            __float2bfloat16(o3 - __bfloat162float(h3)));
    }
}

// ---------------- launch ----------------
extern "C" void kernel_launch(void* const* d_in, const int* in_sizes, int n_in,
                              void* d_out, int out_size) {
    const float* x  = (const float*)d_in[0];
    const float* Wq = (const float*)d_in[2];
    const float* Wk = (const float*)d_in[3];
    const float* Wv = (const float*)d_in[4];
    const float* Wo = (const float*)d_in[5];
    float* out = (float*)d_out;

    __nv_bfloat16 *xh, *xl, *wqh, *wql, *wkh, *wkl, *wvh, *wvl, *woh, *wol, *ah, *al;
    __nv_bfloat16 *qh, *ql, *kh, *kl, *vh, *vl;
    cudaGetSymbolAddress((void**)&xh, g_xh);   cudaGetSymbolAddress((void**)&xl, g_xl);
    cudaGetSymbolAddress((void**)&wqh, g_wqh); cudaGetSymbolAddress((void**)&wql, g_wql);
    cudaGetSymbolAddress((void**)&wkh, g_wkh); cudaGetSymbolAddress((void**)&wkl, g_wkl);
    cudaGetSymbolAddress((void**)&wvh, g_wvh); cudaGetSymbolAddress((void**)&wvl, g_wvl);
    cudaGetSymbolAddress((void**)&woh, g_woh); cudaGetSymbolAddress((void**)&wol, g_wol);
    cudaGetSymbolAddress((void**)&ah, g_ah);   cudaGetSymbolAddress((void**)&al, g_al);
    cudaGetSymbolAddress((void**)&qh, g_qh);   cudaGetSymbolAddress((void**)&ql, g_ql);
    cudaGetSymbolAddress((void**)&kh, g_kh);   cudaGetSymbolAddress((void**)&kl, g_kl);
    cudaGetSymbolAddress((void**)&vh, g_vh);   cudaGetSymbolAddress((void**)&vl, g_vl);

    cudaFuncSetAttribute(gemm_tc2, cudaFuncAttributeMaxDynamicSharedMemorySize, SMEM_G);
    cudaFuncSetAttribute(flash_tc, cudaFuncAttributeMaxDynamicSharedMemorySize, SMEM_FLASH);

    dim3 gg(D_MODEL / 128, MROWS / 128);   // (16, 32)

    prep_kernel<<<8704 + 4 * 4096, 256>>>(x, Wq, Wk, Wv, Wo);                       // 0
    gemm_tc2<<<gg, 256, SMEM_G>>>(xh, xl, wqh, wql, nullptr, qh, ql, 2,
                                  D_MODEL, D_MODEL);                                // 1: Q+RoPE
    gemm_tc2<<<gg, 256, SMEM_G>>>(xh, xl, wkh, wkl, nullptr, kh, kl, 2,
                                  D_MODEL, D_MODEL);                                // 2: K+RoPE
    gemm_tc2<<<gg, 256, SMEM_G>>>(xh, xl, wvh, wvl, nullptr, vh, vl, 1,
                                  D_MODEL, D_MODEL);                                // 3: V
    flash_tc<<<dim3(SEQ / 64, NHEADS, BATCH), 128, SMEM_FLASH>>>();                 // 4
    gemm_tc2<<<gg, 256, SMEM_G>>>(ah, al, woh, wol, out, nullptr, nullptr, 0,
                                  D_MODEL, D_MODEL);                                // 5 <- profiled
}

// round 16
// speedup vs baseline: 3.7694x; 1.0711x over previous
#include <cuda_runtime.h>
#include <cuda_bf16.h>
#include <cstdint>
#include <math.h>

#define D_MODEL 2048
#define SEQ     2048
#define BATCH   2
#define NHEADS  16
#define DK      128
#define MROWS   (BATCH*SEQ)   /* 4096 */

// ---------------- scratch ----------------
__device__ float g_cos[SEQ * (DK / 2)];
__device__ float g_sin[SEQ * (DK / 2)];

__device__ __nv_bfloat16 g_xh[(size_t)MROWS * D_MODEL];
__device__ __nv_bfloat16 g_xl[(size_t)MROWS * D_MODEL];
__device__ __nv_bfloat16 g_wqh[(size_t)D_MODEL * D_MODEL];
__device__ __nv_bfloat16 g_wql[(size_t)D_MODEL * D_MODEL];
__device__ __nv_bfloat16 g_wkh[(size_t)D_MODEL * D_MODEL];
__device__ __nv_bfloat16 g_wkl[(size_t)D_MODEL * D_MODEL];
__device__ __nv_bfloat16 g_wvh[(size_t)D_MODEL * D_MODEL];
__device__ __nv_bfloat16 g_wvl[(size_t)D_MODEL * D_MODEL];
__device__ __nv_bfloat16 g_woh[(size_t)D_MODEL * D_MODEL];
__device__ __nv_bfloat16 g_wol[(size_t)D_MODEL * D_MODEL];
__device__ __nv_bfloat16 g_ah[(size_t)MROWS * D_MODEL];
__device__ __nv_bfloat16 g_al[(size_t)MROWS * D_MODEL];

__device__ __nv_bfloat16 g_qh[(size_t)MROWS * D_MODEL];
__device__ __nv_bfloat16 g_ql[(size_t)MROWS * D_MODEL];
__device__ __nv_bfloat16 g_kh[(size_t)MROWS * D_MODEL];
__device__ __nv_bfloat16 g_kl[(size_t)MROWS * D_MODEL];
__device__ __nv_bfloat16 g_vh[(size_t)MROWS * D_MODEL];
__device__ __nv_bfloat16 g_vl[(size_t)MROWS * D_MODEL];

// ---------------- PTX helpers ----------------
__device__ __forceinline__ void cpa16(uint32_t dst, const void* src) {
    asm volatile("cp.async.cg.shared.global [%0], [%1], 16;" :: "r"(dst), "l"(src));
}
#define CPA_COMMIT() asm volatile("cp.async.commit_group;" ::: "memory")
#define CPA_WAIT0()  asm volatile("cp.async.wait_group 0;" ::: "memory")
#define CPA_WAIT1()  asm volatile("cp.async.wait_group 1;" ::: "memory")

__device__ __forceinline__ uint32_t su32(const void* p) {
    uint32_t a;
    asm("{ .reg .u64 t; cvta.to.shared.u64 t, %1; cvt.u32.u64 %0, t; }" : "=r"(a) : "l"(p));
    return a;
}

#define LDSM4(r0, r1, r2, r3, a) \
    asm volatile("ldmatrix.sync.aligned.m8n8.x4.shared.b16 {%0,%1,%2,%3}, [%4];" \
                 : "=r"(r0), "=r"(r1), "=r"(r2), "=r"(r3) : "r"(a))
#define LDSM4T(r0, r1, r2, r3, a) \
    asm volatile("ldmatrix.sync.aligned.m8n8.x4.trans.shared.b16 {%0,%1,%2,%3}, [%4];" \
                 : "=r"(r0), "=r"(r1), "=r"(r2), "=r"(r3) : "r"(a))
#define MMA16816(d, a0, a1, a2, a3, b0, b1) \
    asm volatile("mma.sync.aligned.m16n8k16.row.col.f32.bf16.bf16.f32 " \
                 "{%0,%1,%2,%3}, {%4,%5,%6,%7}, {%8,%9}, {%0,%1,%2,%3};" \
                 : "+f"((d)[0]), "+f"((d)[1]), "+f"((d)[2]), "+f"((d)[3]) \
                 : "r"(a0), "r"(a1), "r"(a2), "r"(a3), "r"(b0), "r"(b1))

__device__ __forceinline__ uint32_t packbf(float lo, float hi) {
    uint32_t u;
    asm("cvt.rn.bf16x2.f32 %0, %1, %2;" : "=r"(u) : "f"(hi), "f"(lo));
    return u;
}
__device__ __forceinline__ float bfres(float x) {
    return x - __bfloat162float(__float2bfloat16(x));
}

// fast exp2 on FMA pipe (arg <= 0)
__device__ __forceinline__ float exp2ff(float x) {
    x = fmaxf(x, -126.0f);
    float fl = floorf(x);
    float f = x - fl;
    float p = 1.54035304e-4f;
    p = fmaf(p, f, 1.33335581e-3f);
    p = fmaf(p, f, 9.61812910e-3f);
    p = fmaf(p, f, 5.55041086e-2f);
    p = fmaf(p, f, 2.40226512e-1f);
    p = fmaf(p, f, 6.93147182e-1f);
    p = fmaf(p, f, 1.0f);
    return __uint_as_float((uint32_t)((int)fl + 127) << 23) * p;
}

// ---------------- split helper ----------------
__device__ __forceinline__ void split4(const float* __restrict__ src,
                                       __nv_bfloat16* __restrict__ hi,
                                       __nv_bfloat16* __restrict__ lo, int i) {
    float4 v = ((const float4*)src)[i];
    __nv_bfloat16 h0 = __float2bfloat16(v.x);
    __nv_bfloat16 h1 = __float2bfloat16(v.y);
    __nv_bfloat16 h2 = __float2bfloat16(v.z);
    __nv_bfloat16 h3 = __float2bfloat16(v.w);
    __nv_bfloat16 l0 = __float2bfloat16(v.x - __bfloat162float(h0));
    __nv_bfloat16 l1 = __float2bfloat16(v.y - __bfloat162float(h1));
    __nv_bfloat16 l2 = __float2bfloat16(v.z - __bfloat162float(h2));
    __nv_bfloat16 l3 = __float2bfloat16(v.w - __bfloat162float(h3));
    uint2 hp, lp;
    hp.x = (uint32_t)__bfloat16_as_ushort(h0) | ((uint32_t)__bfloat16_as_ushort(h1) << 16);
    hp.y = (uint32_t)__bfloat16_as_ushort(h2) | ((uint32_t)__bfloat16_as_ushort(h3) << 16);
    lp.x = (uint32_t)__bfloat16_as_ushort(l0) | ((uint32_t)__bfloat16_as_ushort(l1) << 16);
    lp.y = (uint32_t)__bfloat16_as_ushort(l2) | ((uint32_t)__bfloat16_as_ushort(l3) << 16);
    ((uint2*)hi)[i] = hp;
    ((uint2*)lo)[i] = lp;
}

// ---------------- fused prep: rope tables + input/weight splits --------------
__global__ void prep_kernel(const float* __restrict__ x,
                            const float* __restrict__ Wq, const float* __restrict__ Wk,
                            const float* __restrict__ Wv, const float* __restrict__ Wo) {
    int bid = blockIdx.x;
    int t = threadIdx.x;
    if (bid < 512) {
        int idx = bid * 256 + t;
        int s = idx >> 6;
        int i = idx & 63;
        float th = powf(10000.0f, (float)i * (1.0f / 64.0f));
        float ph = (float)s / th;          // fp32 rounding matches reference
        double phd = (double)ph;
        g_cos[idx] = (float)cos(phd);
        g_sin[idx] = (float)sin(phd);
    } else if (bid < 8704) {
        split4(x, g_xh, g_xl, (bid - 512) * 256 + t);
    } else {
        int r = bid - 8704;
        int which = r >> 12;
        int i = (r & 4095) * 256 + t;
        if (which == 0)      split4(Wq, g_wqh, g_wql, i);
        else if (which == 1) split4(Wk, g_wkh, g_wkl, i);
        else if (which == 2) split4(Wv, g_wvh, g_wvl, i);
        else                 split4(Wo, g_woh, g_wol, i);
    }
}

// ============================================================================
// bf16 GEMM core: C[M,N] = A[M,K]*B[N,K]^T, 3-term split precision.
// CTA 128x128, 8 warps (64x32 each), Kc=32, 3-stage cp.async, XOR swizzle.
// Per-term inner loops: consecutive MMAs to one accumulator are 4 issues apart.
// mode 0: fp32 C; mode 1: bf16 hi/lo; mode 2: RoPE then bf16 hi/lo.
// ============================================================================
#define GKC    32
#define GMAT   8192                 /* 128 rows x 64B per matrix */
#define GSTG   (4 * GMAT)           /* 32768 per stage */
#define SMEM_G (3 * GSTG)           /* 98304 */

__device__ __forceinline__ void g_load(
    uint32_t sdst, const __nv_bfloat16* __restrict__ Ah, const __nv_bfloat16* __restrict__ Al,
    const __nv_bfloat16* __restrict__ Bh, const __nv_bfloat16* __restrict__ Bl,
    int m0, int n0, int k0, int K, int tid) {
    const __nv_bfloat16* srcs[4] = {Ah, Al, Bh, Bl};
#pragma unroll
    for (int t = 0; t < 8; ++t) {
        int u = t * 256 + tid;            // 0..2047: 4 mats x 128 rows x 4 chunks
        int mtx = u >> 9;
        int rem = u & 511;
        int row = rem >> 2;
        int c16 = (rem & 3) << 4;
        int gr = (mtx < 2 ? m0 : n0) + row;
        cpa16(sdst + mtx * GMAT + row * 64 + (c16 ^ ((row & 6) << 3)),
              srcs[mtx] + (size_t)gr * K + k0 + (c16 >> 1));
    }
}

__device__ __forceinline__ void gemm_core(
    const __nv_bfloat16* __restrict__ Ah, const __nv_bfloat16* __restrict__ Al,
    const __nv_bfloat16* __restrict__ Bh, const __nv_bfloat16* __restrict__ Bl,
    float* __restrict__ C, __nv_bfloat16* __restrict__ Ch, __nv_bfloat16* __restrict__ Cl,
    int mode, int N, int K, char* smem) {
    const uint32_t sbase = su32(smem);
    const int tid  = threadIdx.x;
    const int wid  = tid >> 5;
    const int lane = tid & 31;
    const int m0 = blockIdx.y * 128;
    const int n0 = blockIdx.x * 128;
    const int wm = (wid & 1) * 64;        // 2x4 grid of 64x32 warp tiles
    const int wn = (wid >> 1) * 32;
    const int nchunk = K / GKC;           // 64

    float acc[4][4][4];
#pragma unroll
    for (int mi = 0; mi < 4; ++mi)
#pragma unroll
        for (int n8 = 0; n8 < 4; ++n8) {
            acc[mi][n8][0] = 0.f; acc[mi][n8][1] = 0.f;
            acc[mi][n8][2] = 0.f; acc[mi][n8][3] = 0.f;
        }

    g_load(sbase, Ah, Al, Bh, Bl, m0, n0, 0, K, tid);
    CPA_COMMIT();
    g_load(sbase + GSTG, Ah, Al, Bh, Bl, m0, n0, GKC, K, tid);
    CPA_COMMIT();

    const int r15 = lane & 15;
    const uint32_t xv = (uint32_t)((r15 & 6) << 3);
    const uint32_t chalf = (uint32_t)((lane >> 4) << 4);

#pragma unroll 1
    for (int c = 0; c < nchunk; ++c) {
        CPA_WAIT1();
        __syncthreads();
        if (c + 2 < nchunk) {
            g_load(sbase + ((c + 2) % 3) * GSTG, Ah, Al, Bh, Bl,
                   m0, n0, (c + 2) * GKC, K, tid);
            CPA_COMMIT();
        }
        const uint32_t sa = sbase + (c % 3) * GSTG;
#pragma unroll
        for (int ks = 0; ks < 2; ++ks) {
            const uint32_t cc = (uint32_t)(ks * 32) + chalf;
            uint32_t fb[2][4], fbl[2][4];
#pragma unroll
            for (int ni = 0; ni < 2; ++ni) {
                uint32_t row = (uint32_t)(wn + ni * 16 + r15);
                uint32_t bd = sa + 2 * GMAT + row * 64 + (cc ^ xv);
                LDSM4(fb[ni][0], fb[ni][1], fb[ni][2], fb[ni][3], bd);
                LDSM4(fbl[ni][0], fbl[ni][1], fbl[ni][2], fbl[ni][3], bd + GMAT);
            }
#pragma unroll
            for (int mi = 0; mi < 4; ++mi) {
                uint32_t row = (uint32_t)(wm + mi * 16 + r15);
                uint32_t ad = sa + row * 64 + (cc ^ xv);
                uint32_t fa0, fa1, fa2, fa3, fl0, fl1, fl2, fl3;
                LDSM4(fa0, fa1, fa2, fa3, ad);
                LDSM4(fl0, fl1, fl2, fl3, ad + GMAT);
                // term 1: Ah*Bh over all n8 (acc reuse distance = 4)
#pragma unroll
                for (int n8 = 0; n8 < 4; ++n8)
                    MMA16816(acc[mi][n8], fa0, fa1, fa2, fa3,
                             fb[n8 >> 1][n8 & 1], fb[n8 >> 1][(n8 & 1) + 2]);
                // term 2: Ah*Bl
#pragma unroll
                for (int n8 = 0; n8 < 4; ++n8)
                    MMA16816(acc[mi][n8], fa0, fa1, fa2, fa3,
                             fbl[n8 >> 1][n8 & 1], fbl[n8 >> 1][(n8 & 1) + 2]);
                // term 3: Al*Bh
#pragma unroll
                for (int n8 = 0; n8 < 4; ++n8)
                    MMA16816(acc[mi][n8], fl0, fl1, fl2, fl3,
                             fb[n8 >> 1][n8 & 1], fb[n8 >> 1][(n8 & 1) + 2]);
            }
        }
    }

    // ---- epilogue ----
    const int group = lane >> 2;
    const int tig = lane & 3;
#pragma unroll
    for (int mi = 0; mi < 4; ++mi)
#pragma unroll
        for (int n8 = 0; n8 < 4; ++n8) {
            int grow = m0 + wm + mi * 16 + group;
            size_t row0 = (size_t)grow * N;
            size_t row1 = row0 + (size_t)8 * N;
            int col = n0 + wn + n8 * 8 + tig * 2;
            float d0 = acc[mi][n8][0], d1 = acc[mi][n8][1];
            float d2 = acc[mi][n8][2], d3 = acc[mi][n8][3];
            if (mode == 0) {
                *(float2*)(C + row0 + col) = make_float2(d0, d1);
                *(float2*)(C + row1 + col) = make_float2(d2, d3);
            } else {
                if (mode == 2) {   // RoPE on the interleaved pair
                    int i = ((wn + n8 * 8) >> 1) + tig;      // pair index in head
                    int s0 = grow & (SEQ - 1);
                    float c0 = g_cos[s0 * 64 + i], sn0 = g_sin[s0 * 64 + i];
                    float c1 = g_cos[(s0 + 8) * 64 + i], sn1 = g_sin[(s0 + 8) * 64 + i];
                    float t0 = d0 * c0 - d1 * sn0, t1 = d0 * sn0 + d1 * c0;
                    float t2 = d2 * c1 - d3 * sn1, t3 = d2 * sn1 + d3 * c1;
                    d0 = t0; d1 = t1; d2 = t2; d3 = t3;
                }
                __nv_bfloat16 h0 = __float2bfloat16(d0), h1 = __float2bfloat16(d1);
                __nv_bfloat16 h2 = __float2bfloat16(d2), h3 = __float2bfloat16(d3);
                *(__nv_bfloat162*)(Ch + row0 + col) = __halves2bfloat162(h0, h1);
                *(__nv_bfloat162*)(Ch + row1 + col) = __halves2bfloat162(h2, h3);
                *(__nv_bfloat162*)(Cl + row0 + col) = __halves2bfloat162(
                    __float2bfloat16(d0 - __bfloat162float(h0)),
                    __float2bfloat16(d1 - __bfloat162float(h1)));
                *(__nv_bfloat162*)(Cl + row1 + col) = __halves2bfloat162(
                    __float2bfloat16(d2 - __bfloat162float(h2)),
                    __float2bfloat16(d3 - __bfloat162float(h3)));
            }
        }
}

// fused Q/K/V projection: blockIdx.z selects weights/outputs/mode
__global__ void __launch_bounds__(256, 2) gemm_qkv() {
    extern __shared__ char smem[];
    const int z = blockIdx.z;
    const __nv_bfloat16* Bh = (z == 0) ? g_wqh : (z == 1) ? g_wkh : g_wvh;
    const __nv_bfloat16* Bl = (z == 0) ? g_wql : (z == 1) ? g_wkl : g_wvl;
    __nv_bfloat16* Ch = (z == 0) ? g_qh : (z == 1) ? g_kh : g_vh;
    __nv_bfloat16* Cl = (z == 0) ? g_ql : (z == 1) ? g_kl : g_vl;
    const int mode = (z < 2) ? 2 : 1;
    gemm_core(g_xh, g_xl, Bh, Bl, nullptr, Ch, Cl, mode, D_MODEL, D_MODEL, smem);
}

// out projection
__global__ void __launch_bounds__(256, 2) gemm_out(float* __restrict__ C) {
    extern __shared__ char smem[];
    gemm_core(g_ah, g_al, g_woh, g_wol, C, nullptr, nullptr, 0,
              D_MODEL, D_MODEL, smem);
}

// ============================================================================
// Flash attention (unchanged; epilogue writes ah/al bf16 hi/lo)
// ============================================================================
#define FPITCH 272
#define FKT    (64 * FPITCH)
#define QOFF   0
#define KOFF   (2 * FKT)
#define VOFF   (4 * FKT)
#define SMEM_FLASH (6 * FKT)       /* 104448 */

__device__ __forceinline__ void ld_pair(uint32_t sdst, const __nv_bfloat16* __restrict__ h,
                                        const __nv_bfloat16* __restrict__ l,
                                        int brow0, int hcol, int tid) {
#pragma unroll
    for (int t = 0; t < 16; ++t) {
        int u = t * 128 + tid;
        int mtx = u >> 10;
        int rem = u & 1023;
        int row = rem >> 4;
        int c16 = rem & 15;
        const __nv_bfloat16* src = mtx ? l : h;
        cpa16(sdst + mtx * FKT + row * FPITCH + c16 * 16,
              src + (size_t)(brow0 + row) * D_MODEL + hcol + c16 * 8);
    }
}

__global__ void __launch_bounds__(128) flash_tc() {
    extern __shared__ char smem[];
    const uint32_t sbase = su32(smem);
    const int tid  = threadIdx.x;
    const int wid  = tid >> 5;
    const int lane = tid & 31;
    const int qb   = (int)gridDim.x - 1 - (int)blockIdx.x;
    const int h    = blockIdx.y;
    const int b    = blockIdx.z;
    const int hcol = h * DK;
    const int brow0q = b * SEQ + qb * 64;
    const int group = lane >> 2;
    const int tig   = lane & 3;
    const int qg0   = qb * 64 + wid * 16 + group;

    const float SCL2 = 0.08838834764831845f * 1.4426950408889634f;

    ld_pair(sbase + QOFF, g_qh, g_ql, brow0q, hcol, tid);
    ld_pair(sbase + KOFF, g_kh, g_kl, b * SEQ, hcol, tid);
    CPA_COMMIT();
    ld_pair(sbase + VOFF, g_vh, g_vl, b * SEQ, hcol, tid);
    CPA_COMMIT();

    float oacc[16][4];
#pragma unroll
    for (int f = 0; f < 16; ++f) {
        oacc[f][0] = 0.f; oacc[f][1] = 0.f; oacc[f][2] = 0.f; oacc[f][3] = 0.f;
    }
    float m2[2] = {-1e30f, -1e30f};
    float lsum[2] = {0.f, 0.f};

    const int nt = qb + 1;
    const uint32_t qrow_base = sbase + QOFF + (wid * 16 + (lane & 15)) * FPITCH
                             + (lane >> 4) * 16;
    const uint32_t krow = sbase + KOFF + (lane & 15) * FPITCH + (lane >> 4) * 16;
    const uint32_t vrow = sbase + VOFF
                        + ((lane & 7) + ((lane >> 3) & 1) * 8) * FPITCH
                        + ((lane >> 4) & 1) * 16;

    for (int t = 0; t < nt; ++t) {
        CPA_WAIT1();
        __syncthreads();

        float sacc[8][4];
#pragma unroll
        for (int f = 0; f < 8; ++f) {
            sacc[f][0] = 0.f; sacc[f][1] = 0.f; sacc[f][2] = 0.f; sacc[f][3] = 0.f;
        }
#pragma unroll
        for (int kc = 0; kc < 8; ++kc) {
            uint32_t qa0, qa1, qa2, qa3, ql0, ql1, ql2, ql3;
            LDSM4(qa0, qa1, qa2, qa3, qrow_base + kc * 32);
            LDSM4(ql0, ql1, ql2, ql3, qrow_base + FKT + kc * 32);
#pragma unroll
            for (int nf2 = 0; nf2 < 4; ++nf2) {
                uint32_t kh0, kh1, kh2, kh3, kl0, kl1, kl2, kl3;
                uint32_t ka = krow + nf2 * (16 * FPITCH) + kc * 32;
                LDSM4(kh0, kh1, kh2, kh3, ka);
                LDSM4(kl0, kl1, kl2, kl3, ka + FKT);
                MMA16816(sacc[2 * nf2],     qa0, qa1, qa2, qa3, kh0, kh2);
                MMA16816(sacc[2 * nf2 + 1], qa0, qa1, qa2, qa3, kh1, kh3);
                MMA16816(sacc[2 * nf2],     qa0, qa1, qa2, qa3, kl0, kl2);
                MMA16816(sacc[2 * nf2 + 1], qa0, qa1, qa2, qa3, kl1, kl3);
                MMA16816(sacc[2 * nf2],     ql0, ql1, ql2, ql3, kh0, kh2);
                MMA16816(sacc[2 * nf2 + 1], ql0, ql1, ql2, ql3, kh1, kh3);
            }
        }
        __syncthreads();
        if (t + 1 < nt) {
            ld_pair(sbase + KOFF, g_kh, g_kl, b * SEQ + (t + 1) * 64, hcol, tid);
            CPA_COMMIT();
        }

        if (t == qb) {
            const int j0 = t * 64;
#pragma unroll
            for (int f = 0; f < 8; ++f) {
                int col = j0 + f * 8 + tig * 2;
                if (col > qg0)          sacc[f][0] = -1e30f;
                if (col + 1 > qg0)      sacc[f][1] = -1e30f;
                if (col > qg0 + 8)      sacc[f][2] = -1e30f;
                if (col + 1 > qg0 + 8)  sacc[f][3] = -1e30f;
            }
        }

        float mn0 = -1e30f, mn1 = -1e30f;
#pragma unroll
        for (int f = 0; f < 8; ++f) {
            mn0 = fmaxf(mn0, fmaxf(sacc[f][0], sacc[f][1]));
            mn1 = fmaxf(mn1, fmaxf(sacc[f][2], sacc[f][3]));
        }
        mn0 = fmaxf(mn0, __shfl_xor_sync(0xffffffffu, mn0, 1));
        mn0 = fmaxf(mn0, __shfl_xor_sync(0xffffffffu, mn0, 2));
        mn1 = fmaxf(mn1, __shfl_xor_sync(0xffffffffu, mn1, 1));
        mn1 = fmaxf(mn1, __shfl_xor_sync(0xffffffffu, mn1, 2));
        float mN0 = fmaxf(m2[0], mn0), mN1 = fmaxf(m2[1], mn1);
        float corr0 = exp2ff(SCL2 * (m2[0] - mN0));
        float corr1 = exp2ff(SCL2 * (m2[1] - mN1));
        m2[0] = mN0; m2[1] = mN1;
        const float b0 = mN0 * SCL2, b1 = mN1 * SCL2;

        float ls0 = 0.f, ls1 = 0.f;
#pragma unroll
        for (int f = 0; f < 8; ++f) {
            sacc[f][0] = exp2ff(fmaf(sacc[f][0], SCL2, -b0));
            sacc[f][1] = exp2ff(fmaf(sacc[f][1], SCL2, -b0));
            sacc[f][2] = exp2ff(fmaf(sacc[f][2], SCL2, -b1));
            sacc[f][3] = exp2ff(fmaf(sacc[f][3], SCL2, -b1));
            ls0 += sacc[f][0] + sacc[f][1];
            ls1 += sacc[f][2] + sacc[f][3];
        }
        ls0 += __shfl_xor_sync(0xffffffffu, ls0, 1);
        ls0 += __shfl_xor_sync(0xffffffffu, ls0, 2);
        ls1 += __shfl_xor_sync(0xffffffffu, ls1, 1);
        ls1 += __shfl_xor_sync(0xffffffffu, ls1, 2);
        lsum[0] = lsum[0] * corr0 + ls0;
        lsum[1] = lsum[1] * corr1 + ls1;

#pragma unroll
        for (int f = 0; f < 16; ++f) {
            oacc[f][0] *= corr0; oacc[f][1] *= corr0;
            oacc[f][2] *= corr1; oacc[f][3] *= corr1;
        }

        if (t + 1 < nt) CPA_WAIT1(); else CPA_WAIT0();
        __syncthreads();

#pragma unroll
        for (int kc = 0; kc < 4; ++kc) {
            const int f0 = 2 * kc, f1 = 2 * kc + 1;
            uint32_t ph0 = packbf(sacc[f0][0], sacc[f0][1]);
            uint32_t ph1 = packbf(sacc[f0][2], sacc[f0][3]);
            uint32_t ph2 = packbf(sacc[f1][0], sacc[f1][1]);
            uint32_t ph3 = packbf(sacc[f1][2], sacc[f1][3]);
            uint32_t pl0 = packbf(bfres(sacc[f0][0]), bfres(sacc[f0][1]));
            uint32_t pl1 = packbf(bfres(sacc[f0][2]), bfres(sacc[f0][3]));
            uint32_t pl2 = packbf(bfres(sacc[f1][0]), bfres(sacc[f1][1]));
            uint32_t pl3 = packbf(bfres(sacc[f1][2]), bfres(sacc[f1][3]));
#pragma unroll
            for (int nf2 = 0; nf2 < 8; ++nf2) {
                uint32_t va = vrow + kc * (16 * FPITCH) + nf2 * 32;
                uint32_t v0, v1, v2, v3, u0, u1, u2, u3;
                LDSM4T(v0, v1, v2, v3, va);
                LDSM4T(u0, u1, u2, u3, va + FKT);
                MMA16816(oacc[2 * nf2],     ph0, ph1, ph2, ph3, v0, v1);
                MMA16816(oacc[2 * nf2 + 1], ph0, ph1, ph2, ph3, v2, v3);
                MMA16816(oacc[2 * nf2],     ph0, ph1, ph2, ph3, u0, u1);
                MMA16816(oacc[2 * nf2 + 1], ph0, ph1, ph2, ph3, u2, u3);
                MMA16816(oacc[2 * nf2],     pl0, pl1, pl2, pl3, v0, v1);
                MMA16816(oacc[2 * nf2 + 1], pl0, pl1, pl2, pl3, v2, v3);
            }
        }
        __syncthreads();
        if (t + 1 < nt) {
            ld_pair(sbase + VOFF, g_vh, g_vl, b * SEQ + (t + 1) * 64, hcol, tid);
            CPA_COMMIT();
        }
    }

    const float inv0 = 1.0f / lsum[0];
    const float inv1 = 1.0f / lsum[1];
    size_t r0 = (size_t)(brow0q + wid * 16 + group) * D_MODEL + hcol;
    size_t r1 = r0 + (size_t)8 * D_MODEL;
#pragma unroll
    for (int f = 0; f < 16; ++f) {
        const int col = f * 8 + tig * 2;
        float o0 = oacc[f][0] * inv0, o1 = oacc[f][1] * inv0;
        float o2 = oacc[f][2] * inv1, o3 = oacc[f][3] * inv1;
        __nv_bfloat16 h0 = __float2bfloat16(o0), h1 = __float2bfloat16(o1);
        __nv_bfloat16 h2 = __float2bfloat16(o2), h3 = __float2bfloat16(o3);
        *(__nv_bfloat162*)(g_ah + r0 + col) = __halves2bfloat162(h0, h1);
        *(__nv_bfloat162*)(g_ah + r1 + col) = __halves2bfloat162(h2, h3);
        *(__nv_bfloat162*)(g_al + r0 + col) = __halves2bfloat162(
            __float2bfloat16(o0 - __bfloat162float(h0)),
            __float2bfloat16(o1 - __bfloat162float(h1)));
        *(__nv_bfloat162*)(g_al + r1 + col) = __halves2bfloat162(
            __float2bfloat16(o2 - __bfloat162float(h2)),
            __float2bfloat16(o3 - __bfloat162float(h3)));
    }
}

// ---------------- launch ----------------
extern "C" void kernel_launch(void* const* d_in, const int* in_sizes, int n_in,
                              void* d_out, int out_size) {
    const float* x  = (const float*)d_in[0];
    const float* Wq = (const float*)d_in[2];
    const float* Wk = (const float*)d_in[3];
    const float* Wv = (const float*)d_in[4];
    const float* Wo = (const float*)d_in[5];
    float* out = (float*)d_out;

    cudaFuncSetAttribute(gemm_qkv, cudaFuncAttributeMaxDynamicSharedMemorySize, SMEM_G);
    cudaFuncSetAttribute(gemm_out, cudaFuncAttributeMaxDynamicSharedMemorySize, SMEM_G);
    cudaFuncSetAttribute(flash_tc, cudaFuncAttributeMaxDynamicSharedMemorySize, SMEM_FLASH);

    prep_kernel<<<8704 + 4 * 4096, 256>>>(x, Wq, Wk, Wv, Wo);                       // 0
    gemm_qkv<<<dim3(D_MODEL / 128, MROWS / 128, 3), 256, SMEM_G>>>();               // 1
    flash_tc<<<dim3(SEQ / 64, NHEADS, BATCH), 128, SMEM_FLASH>>>();                 // 2
    gemm_out<<<dim3(D_MODEL / 128, MROWS / 128), 256, SMEM_G>>>(out);               // 3
}